// round 5
// baseline (speedup 1.0000x reference)
#include <cuda_runtime.h>
#include <cuda_bf16.h>
#include <cstdint>

#define B_ 4
#define T_ 2048
#define D_ 1024
#define H_ 16
#define HD_ 64
#define K_ 1024
#define M_ (B_*T_)        // 8192
#define NQKV (3*D_)       // 3072

// ---------------------------------------------------------------------------
// Scratch (device globals — allocation-free rule)
// ---------------------------------------------------------------------------
__device__ __nv_bfloat16 g_q_hi[(size_t)B_ * H_ * T_ * HD_];
__device__ __nv_bfloat16 g_q_lo[(size_t)B_ * H_ * T_ * HD_];
__device__ __nv_bfloat16 g_k_hi[(size_t)B_ * H_ * T_ * HD_];
__device__ __nv_bfloat16 g_k_lo[(size_t)B_ * H_ * T_ * HD_];
__device__ __nv_bfloat16 g_v_hi[(size_t)B_ * H_ * HD_ * T_];   // transposed [b,h,hd,t]
__device__ __nv_bfloat16 g_v_lo[(size_t)B_ * H_ * HD_ * T_];
__device__ __nv_bfloat16 g_x_hi[(size_t)M_ * K_];
__device__ __nv_bfloat16 g_x_lo[(size_t)M_ * K_];
__device__ __nv_bfloat16 g_wqkvT_hi[(size_t)NQKV * K_];
__device__ __nv_bfloat16 g_wqkvT_lo[(size_t)NQKV * K_];
__device__ __nv_bfloat16 g_wprojT_hi[(size_t)D_ * K_];
__device__ __nv_bfloat16 g_wprojT_lo[(size_t)D_ * K_];
__device__ __nv_bfloat16 g_ao_hi[(size_t)M_ * D_];
__device__ __nv_bfloat16 g_ao_lo[(size_t)M_ * D_];

// ---------------------------------------------------------------------------
// Helpers
// ---------------------------------------------------------------------------
__device__ __forceinline__ uint32_t smem_u32(const void* p) {
    uint32_t a;
    asm("{ .reg .u64 t; cvta.to.shared.u64 t, %1; cvt.u32.u64 %0, t; }" : "=r"(a) : "l"(p));
    return a;
}
__device__ __forceinline__ void mma_bf16(float c[4], uint32_t a0, uint32_t a1,
                                         uint32_t a2, uint32_t a3,
                                         uint32_t b0, uint32_t b1) {
    asm volatile(
        "mma.sync.aligned.m16n8k16.row.col.f32.bf16.bf16.f32 "
        "{%0,%1,%2,%3},{%4,%5,%6,%7},{%8,%9},{%0,%1,%2,%3};"
        : "+f"(c[0]), "+f"(c[1]), "+f"(c[2]), "+f"(c[3])
        : "r"(a0), "r"(a1), "r"(a2), "r"(a3), "r"(b0), "r"(b1));
}
#define LDSM_X4(R, ADDR) \
    asm volatile("ldmatrix.sync.aligned.m8n8.x4.shared.b16 {%0,%1,%2,%3}, [%4];" \
        : "=r"((R)[0]), "=r"((R)[1]), "=r"((R)[2]), "=r"((R)[3]) : "r"(ADDR))

// d = {hi_elem:f_hi | lo_elem:f_lo}
__device__ __forceinline__ uint32_t pack_bf16(float f_lo, float f_hi) {
    uint32_t d;
    asm("cvt.rn.bf16x2.f32 %0, %1, %2;" : "=r"(d) : "f"(f_hi), "f"(f_lo));
    return d;
}
// exp(s/8) = 2^(s*C); polynomial path (FMA pipe)
__device__ __forceinline__ float exp_scaled_poly(float s) {
    const float C = 0.18033688011112042f;
    const float MAGIC = 12582912.0f;   // 1.5 * 2^23
    float r = __fmaf_rn(s, C, MAGIC);
    float t = r - MAGIC;
    float f = __fmaf_rn(s, C, -t);     // f in [-0.5, 0.5]
    float p = 0.0013333558146428443f;
    p = __fmaf_rn(p, f, 0.009618129107628477f);
    p = __fmaf_rn(p, f, 0.05550410866482158f);
    p = __fmaf_rn(p, f, 0.2402265069591007f);
    p = __fmaf_rn(p, f, 0.6931471805599453f);
    p = __fmaf_rn(p, f, 1.0f);
    return __int_as_float(__float_as_int(p) + (__float_as_int(r) << 23));
}
// MUFU path
__device__ __forceinline__ float exp_scaled_mufu(float s) {
    float z = s * 0.18033688011112042f;
    float r;
    asm("ex2.approx.f32 %0, %1;" : "=f"(r) : "f"(z));
    return r;
}

// ---------------------------------------------------------------------------
// Splitters
// ---------------------------------------------------------------------------
__global__ void split_kernel(const float* __restrict__ src,
                             __nv_bfloat16* __restrict__ hi,
                             __nv_bfloat16* __restrict__ lo, int n)
{
    int i = (blockIdx.x * blockDim.x + threadIdx.x) * 4;
    if (i >= n) return;
    float4 v = *(const float4*)(src + i);
    __nv_bfloat16 h0 = __float2bfloat16(v.x);
    __nv_bfloat16 h1 = __float2bfloat16(v.y);
    __nv_bfloat16 h2 = __float2bfloat16(v.z);
    __nv_bfloat16 h3 = __float2bfloat16(v.w);
    __nv_bfloat16 l0 = __float2bfloat16(v.x - __bfloat162float(h0));
    __nv_bfloat16 l1 = __float2bfloat16(v.y - __bfloat162float(h1));
    __nv_bfloat16 l2 = __float2bfloat16(v.z - __bfloat162float(h2));
    __nv_bfloat16 l3 = __float2bfloat16(v.w - __bfloat162float(h3));
    *(__nv_bfloat162*)(hi + i)     = __nv_bfloat162(h0, h1);
    *(__nv_bfloat162*)(hi + i + 2) = __nv_bfloat162(h2, h3);
    *(__nv_bfloat162*)(lo + i)     = __nv_bfloat162(l0, l1);
    *(__nv_bfloat162*)(lo + i + 2) = __nv_bfloat162(l2, l3);
}

__global__ void transpose_split_kernel(const float* __restrict__ src,
                                       __nv_bfloat16* __restrict__ hi,
                                       __nv_bfloat16* __restrict__ lo,
                                       int K, int N)
{
    __shared__ float tile[32][33];
    int nb = blockIdx.x * 32, kb = blockIdx.y * 32;
    int tx = threadIdx.x, ty = threadIdx.y;  // 32 x 8
#pragma unroll
    for (int r = ty; r < 32; r += 8)
        tile[r][tx] = src[(size_t)(kb + r) * N + nb + tx];
    __syncthreads();
#pragma unroll
    for (int r = ty; r < 32; r += 8) {
        float v = tile[tx][r];
        __nv_bfloat16 h = __float2bfloat16(v);
        size_t o = (size_t)(nb + r) * K + kb + tx;
        hi[o] = h;
        lo[o] = __float2bfloat16(v - __bfloat162float(h));
    }
}

// ---------------------------------------------------------------------------
// bf16x3 GEMM, cp.async double-buffered, ldmatrix fragment loads.
// CTA 128x128, BK=32, 8 warps (4M x 2N), warp tile 32x64.
// ---------------------------------------------------------------------------
#define GTILE 10240           // 128 rows * 80B
#define GSTAGE (4*GTILE)      // 40960

__global__ __launch_bounds__(256) void gemm_bf16x3_kernel(
    const float* __restrict__ bias, float* __restrict__ out, int N, int mode)
{
    extern __shared__ char gs[];
    uint32_t gsb = smem_u32(gs);

    int tid = threadIdx.x;
    int wid = tid >> 5;
    int lane = tid & 31;
    int qr = lane >> 2;
    int qc = lane & 3;
    int wm = wid & 3;
    int wn = wid >> 2;
    int bm = blockIdx.y * 128;
    int bn = blockIdx.x * 128;

    // ldmatrix lane offsets
    int row_in = lane & 7;
    int tsel = lane >> 3;
    uint32_t laneA = (uint32_t)(((tsel & 1) * 8 + row_in) * 80 + (tsel >> 1) * 16);
    uint32_t laneB = (uint32_t)(((tsel >> 1) * 8 + row_in) * 80 + (tsel & 1) * 16);

    const __nv_bfloat16* Ahi = (mode == 0) ? g_x_hi : g_ao_hi;
    const __nv_bfloat16* Alo = (mode == 0) ? g_x_lo : g_ao_lo;
    const __nv_bfloat16* Bhi = (mode == 0) ? g_wqkvT_hi : g_wprojT_hi;
    const __nv_bfloat16* Blo = (mode == 0) ? g_wqkvT_lo : g_wprojT_lo;

    const __nv_bfloat16* srcp[4] = {
        Ahi + (size_t)bm * K_, Alo + (size_t)bm * K_,
        Bhi + (size_t)bn * K_, Blo + (size_t)bn * K_ };

    float acc[2][8][4];
#pragma unroll
    for (int i = 0; i < 2; i++)
#pragma unroll
        for (int j = 0; j < 8; j++)
#pragma unroll
            for (int c = 0; c < 4; c++) acc[i][j][c] = 0.0f;

    const int NC = K_ / 32;

#define GISSUE(CH, STG) do { int _k0 = (CH) * 32;                                   \
    _Pragma("unroll")                                                               \
    for (int t8 = 0; t8 < 8; ++t8) {                                                \
        int id = tid + t8 * 256; int tle = id >> 9; int rem = id & 511;             \
        int row = rem >> 2; int c = rem & 3;                                        \
        const __nv_bfloat16* sp = srcp[tle] + (size_t)row * K_ + _k0 + c * 8;       \
        uint32_t dp = gsb + (STG) * GSTAGE + tle * GTILE + row * 80 + c * 16;       \
        asm volatile("cp.async.cg.shared.global [%0], [%1], 16;" :: "r"(dp), "l"(sp)); \
    }                                                                               \
    asm volatile("cp.async.commit_group;"); } while (0)

    GISSUE(0, 0);

    for (int ch = 0; ch < NC; ++ch) {
        if (ch + 1 < NC) {
            GISSUE(ch + 1, (ch + 1) & 1);
            asm volatile("cp.async.wait_group 1;");
        } else {
            asm volatile("cp.async.wait_group 0;");
        }
        __syncthreads();

        uint32_t sA0 = gsb + (ch & 1) * GSTAGE;
        uint32_t sA1 = sA0 + GTILE;
        uint32_t sB0 = sA0 + 2 * GTILE;
        uint32_t sB1 = sA0 + 3 * GTILE;

#pragma unroll
        for (int k16 = 0; k16 < 2; ++k16) {
            uint32_t koff = k16 * 32;
            uint32_t ah[2][4], al[2][4];
#pragma unroll
            for (int i = 0; i < 2; ++i) {
                uint32_t aoff = (uint32_t)((wm * 32 + i * 16) * 80) + koff;
                LDSM_X4(ah[i], sA0 + aoff + laneA);
                LDSM_X4(al[i], sA1 + aoff + laneA);
            }
#pragma unroll
            for (int p = 0; p < 4; ++p) {
                uint32_t boff = (uint32_t)((wn * 64 + p * 16) * 80) + koff;
                uint32_t bh4[4], bl4[4];
                LDSM_X4(bh4, sB0 + boff + laneB);
                LDSM_X4(bl4, sB1 + boff + laneB);
#pragma unroll
                for (int half = 0; half < 2; ++half) {
                    int j = 2 * p + half;
                    uint32_t bh0 = bh4[half * 2], bh1 = bh4[half * 2 + 1];
                    uint32_t bl0 = bl4[half * 2], bl1 = bl4[half * 2 + 1];
#pragma unroll
                    for (int i = 0; i < 2; ++i) {
                        mma_bf16(acc[i][j], ah[i][0], ah[i][1], ah[i][2], ah[i][3], bh0, bh1);
                        mma_bf16(acc[i][j], ah[i][0], ah[i][1], ah[i][2], ah[i][3], bl0, bl1);
                        mma_bf16(acc[i][j], al[i][0], al[i][1], al[i][2], al[i][3], bh0, bh1);
                    }
                }
            }
        }
        __syncthreads();
    }

    // epilogue
#pragma unroll
    for (int i = 0; i < 2; ++i) {
#pragma unroll
        for (int j = 0; j < 8; ++j) {
            int n = bn + wn * 64 + j * 8 + qc * 2;
            float b0v = bias[n], b1v = bias[n + 1];
#pragma unroll
            for (int half = 0; half < 2; ++half) {
                int m = bm + wm * 32 + i * 16 + qr + half * 8;
                float v0 = acc[i][j][half * 2 + 0] + b0v;
                float v1 = acc[i][j][half * 2 + 1] + b1v;
                if (mode == 0) {
                    int bq = m >> 11;
                    int t = m & (T_ - 1);
                    int sel = n >> 10;
                    int dd = n & (D_ - 1);
                    int h = dd >> 6;
                    int hd = dd & (HD_ - 1);
                    __nv_bfloat16 h0 = __float2bfloat16(v0);
                    __nv_bfloat16 h1 = __float2bfloat16(v1);
                    __nv_bfloat16 l0 = __float2bfloat16(v0 - __bfloat162float(h0));
                    __nv_bfloat16 l1 = __float2bfloat16(v1 - __bfloat162float(h1));
                    if (sel == 2) {
                        size_t vb = ((size_t)(bq * H_ + h) * HD_);
                        g_v_hi[(vb + hd) * T_ + t] = h0;
                        g_v_hi[(vb + hd + 1) * T_ + t] = h1;
                        g_v_lo[(vb + hd) * T_ + t] = l0;
                        g_v_lo[(vb + hd + 1) * T_ + t] = l1;
                    } else {
                        size_t o = ((size_t)(bq * H_ + h) * T_ + t) * HD_ + hd;
                        __nv_bfloat16* dh = (sel == 0) ? g_q_hi : g_k_hi;
                        __nv_bfloat16* dl = (sel == 0) ? g_q_lo : g_k_lo;
                        *(__nv_bfloat162*)(dh + o) = __nv_bfloat162(h0, h1);
                        *(__nv_bfloat162*)(dl + o) = __nv_bfloat162(l0, l1);
                    }
                } else {
                    *(float2*)(out + (size_t)m * N + n) = make_float2(v0, v1);
                }
            }
        }
    }
}

// ---------------------------------------------------------------------------
// Attention: bf16x3 mma + ldmatrix, no-max softmax, poly/MUFU exp.
// CTA: 128 q-rows, one (b,h). 8 warps (4M x 2N). KV tiles of 128.
// ---------------------------------------------------------------------------
#define A_QHI 0
#define A_QLO 18432
#define A_KHI 36864
#define A_KLO 55296
#define A_VHI 73728
#define A_VLO 91136
#define A_OA  36864          // union (post-loop)
#define A_OB  70656
#define A_LP  104448
#define A_LI  105472
#define A_SMEM 108544

__global__ __launch_bounds__(256) void attn_mma_kernel()
{
    extern __shared__ char as_[];
    uint32_t asb = smem_u32(as_);

    int tid = threadIdx.x;
    int wid = tid >> 5;
    int lane = tid & 31;
    int qr = lane >> 2;
    int qc = lane & 3;
    int wm = wid & 3;
    int wn = wid >> 2;
    int q0 = blockIdx.x * 128;
    int h = blockIdx.y;
    int b = blockIdx.z;

    int row_in = lane & 7;
    int tsel = lane >> 3;
    uint32_t laneAq = (uint32_t)(((tsel & 1) * 8 + row_in) * 144 + (tsel >> 1) * 16);
    uint32_t laneBk = (uint32_t)(((tsel >> 1) * 8 + row_in) * 144 + (tsel & 1) * 16);
    uint32_t laneBv = (uint32_t)(((tsel >> 1) * 8 + row_in) * 272 + (tsel & 1) * 16);

    const size_t bh = (size_t)(b * H_ + h);
    const __nv_bfloat16* gqh = g_q_hi + (bh * T_ + q0) * HD_;
    const __nv_bfloat16* gql = g_q_lo + (bh * T_ + q0) * HD_;
    const __nv_bfloat16* gkh = g_k_hi + bh * T_ * HD_;
    const __nv_bfloat16* gkl = g_k_lo + bh * T_ * HD_;
    const __nv_bfloat16* gvh = g_v_hi + bh * HD_ * T_;
    const __nv_bfloat16* gvl = g_v_lo + bh * HD_ * T_;

    // load Q tiles (hi/lo): 128 rows x 64 halves, stride 144B
#pragma unroll
    for (int r = 0; r < 4; ++r) {
        int id = tid + r * 256;
        int row = id >> 3;
        int c = id & 7;
        *(uint4*)(as_ + A_QHI + row * 144 + c * 16) = *(const uint4*)(gqh + (size_t)row * HD_ + c * 8);
        *(uint4*)(as_ + A_QLO + row * 144 + c * 16) = *(const uint4*)(gql + (size_t)row * HD_ + c * 8);
    }
    __syncthreads();

    // Q hi fragments in registers
    uint32_t qh[2][4][4];
#pragma unroll
    for (int i = 0; i < 2; ++i) {
#pragma unroll
        for (int t = 0; t < 4; ++t) {
            LDSM_X4(qh[i][t], asb + A_QHI + (uint32_t)((wm * 32 + i * 16) * 144 + t * 32) + laneAq);
        }
    }

    float oacc[2][8][4];
#pragma unroll
    for (int i = 0; i < 2; i++)
#pragma unroll
        for (int j = 0; j < 8; j++)
#pragma unroll
            for (int c = 0; c < 4; c++) oacc[i][j][c] = 0.0f;
    float lsum[2][2] = {{0.f, 0.f}, {0.f, 0.f}};

    for (int kt = 0; kt < T_ / 128; ++kt) {
        __syncthreads();
        // load K tile (hi/lo) and V^T tile (hi/lo)
        {
            const __nv_bfloat16* kh_p = gkh + (size_t)kt * 128 * HD_;
            const __nv_bfloat16* kl_p = gkl + (size_t)kt * 128 * HD_;
#pragma unroll
            for (int r = 0; r < 4; ++r) {
                int id = tid + r * 256;
                int row = id >> 3;
                int c = id & 7;
                *(uint4*)(as_ + A_KHI + row * 144 + c * 16) = *(const uint4*)(kh_p + (size_t)row * HD_ + c * 8);
                *(uint4*)(as_ + A_KLO + row * 144 + c * 16) = *(const uint4*)(kl_p + (size_t)row * HD_ + c * 8);
            }
#pragma unroll
            for (int r = 0; r < 4; ++r) {
                int id = tid + r * 256;
                int row = id >> 4;     // hd row 0..63
                int c = id & 15;
                *(uint4*)(as_ + A_VHI + row * 272 + c * 16) = *(const uint4*)(gvh + (size_t)row * T_ + kt * 128 + c * 8);
                *(uint4*)(as_ + A_VLO + row * 272 + c * 16) = *(const uint4*)(gvl + (size_t)row * T_ + kt * 128 + c * 8);
            }
        }
        __syncthreads();

        // ---- S = Q K^T (bf16x3) ----
        float sacc[2][8][4];
#pragma unroll
        for (int i = 0; i < 2; i++)
#pragma unroll
            for (int j = 0; j < 8; j++)
#pragma unroll
                for (int c = 0; c < 4; c++) sacc[i][j][c] = 0.0f;

#pragma unroll
        for (int t = 0; t < 4; ++t) {
            uint32_t koff = (uint32_t)(t * 32);
            uint32_t ql[2][4];
#pragma unroll
            for (int i = 0; i < 2; ++i) {
                LDSM_X4(ql[i], asb + A_QLO + (uint32_t)((wm * 32 + i * 16) * 144) + koff + laneAq);
            }
#pragma unroll
            for (int p = 0; p < 4; ++p) {
                uint32_t boff = (uint32_t)((wn * 64 + p * 16) * 144) + koff;
                uint32_t kh4[4], kl4[4];
                LDSM_X4(kh4, asb + A_KHI + boff + laneBk);
                LDSM_X4(kl4, asb + A_KLO + boff + laneBk);
#pragma unroll
                for (int half = 0; half < 2; ++half) {
                    int j = 2 * p + half;
                    uint32_t bh0 = kh4[half * 2], bh1 = kh4[half * 2 + 1];
                    uint32_t bl0 = kl4[half * 2], bl1 = kl4[half * 2 + 1];
#pragma unroll
                    for (int i = 0; i < 2; ++i) {
                        mma_bf16(sacc[i][j], qh[i][t][0], qh[i][t][1], qh[i][t][2], qh[i][t][3], bh0, bh1);
                        mma_bf16(sacc[i][j], qh[i][t][0], qh[i][t][1], qh[i][t][2], qh[i][t][3], bl0, bl1);
                        mma_bf16(sacc[i][j], ql[i][0], ql[i][1], ql[i][2], ql[i][3], bh0, bh1);
                    }
                }
            }
        }

        // ---- exp (no max subtraction) + pack P hi/lo ----
        uint32_t ph[2][8][2], pl[2][8][2];
#pragma unroll
        for (int i = 0; i < 2; ++i) {
#pragma unroll
            for (int j = 0; j < 8; ++j) {
                float p0, p1, p2, p3;
                if (j < 3) {
                    p0 = exp_scaled_mufu(sacc[i][j][0]);
                    p1 = exp_scaled_mufu(sacc[i][j][1]);
                    p2 = exp_scaled_mufu(sacc[i][j][2]);
                    p3 = exp_scaled_mufu(sacc[i][j][3]);
                } else {
                    p0 = exp_scaled_poly(sacc[i][j][0]);
                    p1 = exp_scaled_poly(sacc[i][j][1]);
                    p2 = exp_scaled_poly(sacc[i][j][2]);
                    p3 = exp_scaled_poly(sacc[i][j][3]);
                }
                lsum[i][0] += p0 + p1;
                lsum[i][1] += p2 + p3;
                uint32_t h01 = pack_bf16(p0, p1);
                uint32_t h23 = pack_bf16(p2, p3);
                float r0 = p0 - __int_as_float(h01 << 16);
                float r1 = p1 - __int_as_float(h01 & 0xFFFF0000u);
                float r2 = p2 - __int_as_float(h23 << 16);
                float r3 = p3 - __int_as_float(h23 & 0xFFFF0000u);
                ph[i][j][0] = h01;
                ph[i][j][1] = h23;
                pl[i][j][0] = pack_bf16(r0, r1);
                pl[i][j][1] = pack_bf16(r2, r3);
            }
        }

        // ---- O += P V (bf16x3); warp covers kv slice wn*64..+64 ----
#pragma unroll
        for (int t = 0; t < 4; ++t) {
            uint32_t koff = (uint32_t)(wn * 128 + t * 32);
#pragma unroll
            for (int p = 0; p < 4; ++p) {
                uint32_t boff = (uint32_t)(p * 16 * 272) + koff;
                uint32_t vh4[4], vl4[4];
                LDSM_X4(vh4, asb + A_VHI + boff + laneBv);
                LDSM_X4(vl4, asb + A_VLO + boff + laneBv);
#pragma unroll
                for (int half = 0; half < 2; ++half) {
                    int j = 2 * p + half;
                    uint32_t vh0 = vh4[half * 2], vh1 = vh4[half * 2 + 1];
                    uint32_t vl0 = vl4[half * 2], vl1 = vl4[half * 2 + 1];
#pragma unroll
                    for (int i = 0; i < 2; ++i) {
                        uint32_t a0 = ph[i][2 * t][0], a1 = ph[i][2 * t][1];
                        uint32_t a2 = ph[i][2 * t + 1][0], a3 = ph[i][2 * t + 1][1];
                        mma_bf16(oacc[i][j], a0, a1, a2, a3, vh0, vh1);
                        mma_bf16(oacc[i][j], a0, a1, a2, a3, vl0, vl1);
                        mma_bf16(oacc[i][j], pl[i][2 * t][0], pl[i][2 * t][1],
                                 pl[i][2 * t + 1][0], pl[i][2 * t + 1][1], vh0, vh1);
                    }
                }
            }
        }
    }

    __syncthreads();   // done with K/V smem; reuse for O reduction

    // store partial O (per wn) to smem
    {
        float* obuf = (float*)(as_ + (wn == 0 ? A_OA : A_OB));
#pragma unroll
        for (int i = 0; i < 2; ++i) {
#pragma unroll
            for (int j = 0; j < 8; ++j) {
                int row = wm * 32 + i * 16 + qr;
                int col = j * 8 + qc * 2;
                *(float2*)&obuf[row * 66 + col] = make_float2(oacc[i][j][0], oacc[i][j][1]);
                *(float2*)&obuf[(row + 8) * 66 + col] = make_float2(oacc[i][j][2], oacc[i][j][3]);
            }
        }
    }
    // reduce l over qc lanes, write partials
    {
        float* lp = (float*)(as_ + A_LP);
#pragma unroll
        for (int i = 0; i < 2; ++i) {
#pragma unroll
            for (int hf = 0; hf < 2; ++hf) {
                float v = lsum[i][hf];
                v += __shfl_xor_sync(0xffffffffu, v, 1);
                v += __shfl_xor_sync(0xffffffffu, v, 2);
                lsum[i][hf] = v;
            }
            if (qc == 0) {
                lp[wn * 128 + wm * 32 + i * 16 + qr] = lsum[i][0];
                lp[wn * 128 + wm * 32 + i * 16 + qr + 8] = lsum[i][1];
            }
        }
    }
    __syncthreads();
    {
        float* lp = (float*)(as_ + A_LP);
        float* li = (float*)(as_ + A_LI);
        if (tid < 128) li[tid] = 1.0f / (lp[tid] + lp[128 + tid]);
    }
    __syncthreads();

    // final: sum partials, normalize, split, write g_ao
    {
        const float* oA = (const float*)(as_ + A_OA);
        const float* oB = (const float*)(as_ + A_OB);
        const float* li = (const float*)(as_ + A_LI);
        int colp = (tid & 31) * 2;
        int rbase = tid >> 5;
#pragma unroll
        for (int pass = 0; pass < 16; ++pass) {
            int row = pass * 8 + rbase;
            float iv = li[row];
            float o0 = (oA[row * 66 + colp] + oB[row * 66 + colp]) * iv;
            float o1 = (oA[row * 66 + colp + 1] + oB[row * 66 + colp + 1]) * iv;
            uint32_t hp = pack_bf16(o0, o1);
            float r0 = o0 - __int_as_float(hp << 16);
            float r1 = o1 - __int_as_float(hp & 0xFFFF0000u);
            uint32_t lpk = pack_bf16(r0, r1);
            size_t go = ((size_t)(b * T_ + q0 + row)) * D_ + h * HD_ + colp;
            *(uint32_t*)(g_ao_hi + go) = hp;
            *(uint32_t*)(g_ao_lo + go) = lpk;
        }
    }
}

// ---------------------------------------------------------------------------
extern "C" void kernel_launch(void* const* d_in, const int* in_sizes, int n_in,
                              void* d_out, int out_size)
{
    const float* x = (const float*)d_in[0];
    const float* w_qkv = (const float*)d_in[1];
    const float* b_qkv = (const float*)d_in[2];
    const float* w_proj = (const float*)d_in[3];
    const float* b_proj = (const float*)d_in[4];
    float* out = (float*)d_out;

    __nv_bfloat16 *xhi, *xlo, *wqh, *wql, *wph, *wpl;
    cudaGetSymbolAddress((void**)&xhi, g_x_hi);
    cudaGetSymbolAddress((void**)&xlo, g_x_lo);
    cudaGetSymbolAddress((void**)&wqh, g_wqkvT_hi);
    cudaGetSymbolAddress((void**)&wql, g_wqkvT_lo);
    cudaGetSymbolAddress((void**)&wph, g_wprojT_hi);
    cudaGetSymbolAddress((void**)&wpl, g_wprojT_lo);

    cudaFuncSetAttribute(gemm_bf16x3_kernel, cudaFuncAttributeMaxDynamicSharedMemorySize, 2 * GSTAGE);
    cudaFuncSetAttribute(attn_mma_kernel, cudaFuncAttributeMaxDynamicSharedMemorySize, A_SMEM);

    // split x -> bf16 hi/lo
    {
        int n = M_ * K_;
        split_kernel<<<(n / 4 + 255) / 256, 256>>>(x, xhi, xlo, n);
    }
    transpose_split_kernel<<<dim3(NQKV / 32, K_ / 32), dim3(32, 8)>>>(w_qkv, wqh, wql, K_, NQKV);
    transpose_split_kernel<<<dim3(D_ / 32, K_ / 32), dim3(32, 8)>>>(w_proj, wph, wpl, K_, D_);

    // QKV GEMM -> split q/k/v
    gemm_bf16x3_kernel<<<dim3(NQKV / 128, M_ / 128), 256, 2 * GSTAGE>>>(b_qkv, nullptr, NQKV, 0);

    // Attention (tensor cores + fast exp) -> g_ao hi/lo
    attn_mma_kernel<<<dim3(T_ / 128, H_, B_), 256, A_SMEM>>>();

    // Output projection -> out
    gemm_bf16x3_kernel<<<dim3(D_ / 128, M_ / 128), 256, 2 * GSTAGE>>>(b_proj, out, D_, 1);
}

// round 7
// speedup vs baseline: 1.1029x; 1.1029x over previous
#include <cuda_runtime.h>
#include <cuda_bf16.h>
#include <cstdint>

#define B_ 4
#define T_ 2048
#define D_ 1024
#define H_ 16
#define HD_ 64
#define K_ 1024
#define M_ (B_*T_)        // 8192
#define NQKV (3*D_)       // 3072

// ---------------------------------------------------------------------------
// Scratch (device globals — allocation-free rule)
// ---------------------------------------------------------------------------
__device__ __nv_bfloat16 g_q_hi[(size_t)B_ * H_ * T_ * HD_];
__device__ __nv_bfloat16 g_q_lo[(size_t)B_ * H_ * T_ * HD_];
__device__ __nv_bfloat16 g_k_hi[(size_t)B_ * H_ * T_ * HD_];
__device__ __nv_bfloat16 g_k_lo[(size_t)B_ * H_ * T_ * HD_];
__device__ __nv_bfloat16 g_v_hi[(size_t)B_ * H_ * HD_ * T_];   // transposed [b,h,hd,t]
__device__ __nv_bfloat16 g_v_lo[(size_t)B_ * H_ * HD_ * T_];
__device__ __nv_bfloat16 g_x_hi[(size_t)M_ * K_];
__device__ __nv_bfloat16 g_x_lo[(size_t)M_ * K_];
__device__ __nv_bfloat16 g_wqkvT_hi[(size_t)NQKV * K_];
__device__ __nv_bfloat16 g_wqkvT_lo[(size_t)NQKV * K_];
__device__ __nv_bfloat16 g_wprojT_hi[(size_t)D_ * K_];
__device__ __nv_bfloat16 g_wprojT_lo[(size_t)D_ * K_];
__device__ __nv_bfloat16 g_ao_hi[(size_t)M_ * D_];
__device__ __nv_bfloat16 g_ao_lo[(size_t)M_ * D_];

// ---------------------------------------------------------------------------
// Helpers
// ---------------------------------------------------------------------------
__device__ __forceinline__ uint32_t smem_u32(const void* p) {
    uint32_t a;
    asm("{ .reg .u64 t; cvta.to.shared.u64 t, %1; cvt.u32.u64 %0, t; }" : "=r"(a) : "l"(p));
    return a;
}
__device__ __forceinline__ void mma_bf16(float c[4], uint32_t a0, uint32_t a1,
                                         uint32_t a2, uint32_t a3,
                                         uint32_t b0, uint32_t b1) {
    asm volatile(
        "mma.sync.aligned.m16n8k16.row.col.f32.bf16.bf16.f32 "
        "{%0,%1,%2,%3},{%4,%5,%6,%7},{%8,%9},{%0,%1,%2,%3};"
        : "+f"(c[0]), "+f"(c[1]), "+f"(c[2]), "+f"(c[3])
        : "r"(a0), "r"(a1), "r"(a2), "r"(a3), "r"(b0), "r"(b1));
}
#define LDSM_X4(R, ADDR) \
    asm volatile("ldmatrix.sync.aligned.m8n8.x4.shared.b16 {%0,%1,%2,%3}, [%4];" \
        : "=r"((R)[0]), "=r"((R)[1]), "=r"((R)[2]), "=r"((R)[3]) : "r"(ADDR))

// d = {hi_elem:f_hi | lo_elem:f_lo}
__device__ __forceinline__ uint32_t pack_bf16(float f_lo, float f_hi) {
    uint32_t d;
    asm("cvt.rn.bf16x2.f32 %0, %1, %2;" : "=r"(d) : "f"(f_hi), "f"(f_lo));
    return d;
}
// exp(s/8) = 2^(s*C); polynomial path (FMA pipe)
__device__ __forceinline__ float exp_scaled_poly(float s) {
    const float C = 0.18033688011112042f;
    const float MAGIC = 12582912.0f;   // 1.5 * 2^23
    float r = __fmaf_rn(s, C, MAGIC);
    float t = r - MAGIC;
    float f = __fmaf_rn(s, C, -t);     // f in [-0.5, 0.5]
    float p = 0.0013333558146428443f;
    p = __fmaf_rn(p, f, 0.009618129107628477f);
    p = __fmaf_rn(p, f, 0.05550410866482158f);
    p = __fmaf_rn(p, f, 0.2402265069591007f);
    p = __fmaf_rn(p, f, 0.6931471805599453f);
    p = __fmaf_rn(p, f, 1.0f);
    return __int_as_float(__float_as_int(p) + (__float_as_int(r) << 23));
}
// MUFU path
__device__ __forceinline__ float exp_scaled_mufu(float s) {
    float z = s * 0.18033688011112042f;
    float r;
    asm("ex2.approx.f32 %0, %1;" : "=f"(r) : "f"(z));
    return r;
}

// ---------------------------------------------------------------------------
// Splitters
// ---------------------------------------------------------------------------
__global__ void split_kernel(const float* __restrict__ src,
                             __nv_bfloat16* __restrict__ hi,
                             __nv_bfloat16* __restrict__ lo, int n)
{
    int i = (blockIdx.x * blockDim.x + threadIdx.x) * 4;
    if (i >= n) return;
    float4 v = *(const float4*)(src + i);
    __nv_bfloat16 h0 = __float2bfloat16(v.x);
    __nv_bfloat16 h1 = __float2bfloat16(v.y);
    __nv_bfloat16 h2 = __float2bfloat16(v.z);
    __nv_bfloat16 h3 = __float2bfloat16(v.w);
    __nv_bfloat16 l0 = __float2bfloat16(v.x - __bfloat162float(h0));
    __nv_bfloat16 l1 = __float2bfloat16(v.y - __bfloat162float(h1));
    __nv_bfloat16 l2 = __float2bfloat16(v.z - __bfloat162float(h2));
    __nv_bfloat16 l3 = __float2bfloat16(v.w - __bfloat162float(h3));
    *(__nv_bfloat162*)(hi + i)     = __nv_bfloat162(h0, h1);
    *(__nv_bfloat162*)(hi + i + 2) = __nv_bfloat162(h2, h3);
    *(__nv_bfloat162*)(lo + i)     = __nv_bfloat162(l0, l1);
    *(__nv_bfloat162*)(lo + i + 2) = __nv_bfloat162(l2, l3);
}

__global__ void transpose_split_kernel(const float* __restrict__ src,
                                       __nv_bfloat16* __restrict__ hi,
                                       __nv_bfloat16* __restrict__ lo,
                                       int K, int N)
{
    __shared__ float tile[32][33];
    int nb = blockIdx.x * 32, kb = blockIdx.y * 32;
    int tx = threadIdx.x, ty = threadIdx.y;  // 32 x 8
#pragma unroll
    for (int r = ty; r < 32; r += 8)
        tile[r][tx] = src[(size_t)(kb + r) * N + nb + tx];
    __syncthreads();
#pragma unroll
    for (int r = ty; r < 32; r += 8) {
        float v = tile[tx][r];
        __nv_bfloat16 h = __float2bfloat16(v);
        size_t o = (size_t)(nb + r) * K + kb + tx;
        hi[o] = h;
        lo[o] = __float2bfloat16(v - __bfloat162float(h));
    }
}

// ---------------------------------------------------------------------------
// bf16x3 GEMM, cp.async double-buffered, ldmatrix fragment loads.
// CTA 128x128, BK=32, 8 warps (4M x 2N), warp tile 32x64.
// __launch_bounds__(256, 2): cap regs at 128 so 2 CTAs/SM fit (64K regfile).
// ---------------------------------------------------------------------------
#define GTILE 10240           // 128 rows * 80B
#define GSTAGE (4*GTILE)      // 40960

__global__ __launch_bounds__(256, 2) void gemm_bf16x3_kernel(
    const float* __restrict__ bias, float* __restrict__ out, int N, int mode)
{
    extern __shared__ char gs[];
    uint32_t gsb = smem_u32(gs);

    int tid = threadIdx.x;
    int wid = tid >> 5;
    int lane = tid & 31;
    int qr = lane >> 2;
    int qc = lane & 3;
    int wm = wid & 3;
    int wn = wid >> 2;
    int bm = blockIdx.y * 128;
    int bn = blockIdx.x * 128;

    // ldmatrix lane offsets
    int row_in = lane & 7;
    int tsel = lane >> 3;
    uint32_t laneA = (uint32_t)(((tsel & 1) * 8 + row_in) * 80 + (tsel >> 1) * 16);
    uint32_t laneB = (uint32_t)(((tsel >> 1) * 8 + row_in) * 80 + (tsel & 1) * 16);

    const __nv_bfloat16* Ahi = (mode == 0) ? g_x_hi : g_ao_hi;
    const __nv_bfloat16* Alo = (mode == 0) ? g_x_lo : g_ao_lo;
    const __nv_bfloat16* Bhi = (mode == 0) ? g_wqkvT_hi : g_wprojT_hi;
    const __nv_bfloat16* Blo = (mode == 0) ? g_wqkvT_lo : g_wprojT_lo;

    const __nv_bfloat16* srcp[4] = {
        Ahi + (size_t)bm * K_, Alo + (size_t)bm * K_,
        Bhi + (size_t)bn * K_, Blo + (size_t)bn * K_ };

    float acc[2][8][4];
#pragma unroll
    for (int i = 0; i < 2; i++)
#pragma unroll
        for (int j = 0; j < 8; j++)
#pragma unroll
            for (int c = 0; c < 4; c++) acc[i][j][c] = 0.0f;

    const int NC = K_ / 32;

#define GISSUE(CH, STG) do { int _k0 = (CH) * 32;                                   \
    _Pragma("unroll")                                                               \
    for (int t8 = 0; t8 < 8; ++t8) {                                                \
        int id = tid + t8 * 256; int tle = id >> 9; int rem = id & 511;             \
        int row = rem >> 2; int c = rem & 3;                                        \
        const __nv_bfloat16* sp = srcp[tle] + (size_t)row * K_ + _k0 + c * 8;       \
        uint32_t dp = gsb + (STG) * GSTAGE + tle * GTILE + row * 80 + c * 16;       \
        asm volatile("cp.async.cg.shared.global [%0], [%1], 16;" :: "r"(dp), "l"(sp)); \
    }                                                                               \
    asm volatile("cp.async.commit_group;"); } while (0)

    GISSUE(0, 0);

    for (int ch = 0; ch < NC; ++ch) {
        if (ch + 1 < NC) {
            GISSUE(ch + 1, (ch + 1) & 1);
            asm volatile("cp.async.wait_group 1;");
        } else {
            asm volatile("cp.async.wait_group 0;");
        }
        __syncthreads();

        uint32_t sA0 = gsb + (ch & 1) * GSTAGE;
        uint32_t sA1 = sA0 + GTILE;
        uint32_t sB0 = sA0 + 2 * GTILE;
        uint32_t sB1 = sA0 + 3 * GTILE;

#pragma unroll
        for (int k16 = 0; k16 < 2; ++k16) {
            uint32_t koff = k16 * 32;
            uint32_t ah[2][4], al[2][4];
#pragma unroll
            for (int i = 0; i < 2; ++i) {
                uint32_t aoff = (uint32_t)((wm * 32 + i * 16) * 80) + koff;
                LDSM_X4(ah[i], sA0 + aoff + laneA);
                LDSM_X4(al[i], sA1 + aoff + laneA);
            }
#pragma unroll
            for (int p = 0; p < 4; ++p) {
                uint32_t boff = (uint32_t)((wn * 64 + p * 16) * 80) + koff;
                uint32_t bh4[4], bl4[4];
                LDSM_X4(bh4, sB0 + boff + laneB);
                LDSM_X4(bl4, sB1 + boff + laneB);
#pragma unroll
                for (int half = 0; half < 2; ++half) {
                    int j = 2 * p + half;
                    uint32_t bh0 = bh4[half * 2], bh1 = bh4[half * 2 + 1];
                    uint32_t bl0 = bl4[half * 2], bl1 = bl4[half * 2 + 1];
#pragma unroll
                    for (int i = 0; i < 2; ++i) {
                        mma_bf16(acc[i][j], ah[i][0], ah[i][1], ah[i][2], ah[i][3], bh0, bh1);
                        mma_bf16(acc[i][j], ah[i][0], ah[i][1], ah[i][2], ah[i][3], bl0, bl1);
                        mma_bf16(acc[i][j], al[i][0], al[i][1], al[i][2], al[i][3], bh0, bh1);
                    }
                }
            }
        }
        __syncthreads();
    }

    // epilogue
#pragma unroll
    for (int i = 0; i < 2; ++i) {
#pragma unroll
        for (int j = 0; j < 8; ++j) {
            int n = bn + wn * 64 + j * 8 + qc * 2;
            float b0v = bias[n], b1v = bias[n + 1];
#pragma unroll
            for (int half = 0; half < 2; ++half) {
                int m = bm + wm * 32 + i * 16 + qr + half * 8;
                float v0 = acc[i][j][half * 2 + 0] + b0v;
                float v1 = acc[i][j][half * 2 + 1] + b1v;
                if (mode == 0) {
                    int bq = m >> 11;
                    int t = m & (T_ - 1);
                    int sel = n >> 10;
                    int dd = n & (D_ - 1);
                    int h = dd >> 6;
                    int hd = dd & (HD_ - 1);
                    __nv_bfloat16 h0 = __float2bfloat16(v0);
                    __nv_bfloat16 h1 = __float2bfloat16(v1);
                    __nv_bfloat16 l0 = __float2bfloat16(v0 - __bfloat162float(h0));
                    __nv_bfloat16 l1 = __float2bfloat16(v1 - __bfloat162float(h1));
                    if (sel == 2) {
                        size_t vb = ((size_t)(bq * H_ + h) * HD_);
                        g_v_hi[(vb + hd) * T_ + t] = h0;
                        g_v_hi[(vb + hd + 1) * T_ + t] = h1;
                        g_v_lo[(vb + hd) * T_ + t] = l0;
                        g_v_lo[(vb + hd + 1) * T_ + t] = l1;
                    } else {
                        size_t o = ((size_t)(bq * H_ + h) * T_ + t) * HD_ + hd;
                        __nv_bfloat16* dh = (sel == 0) ? g_q_hi : g_k_hi;
                        __nv_bfloat16* dl = (sel == 0) ? g_q_lo : g_k_lo;
                        *(__nv_bfloat162*)(dh + o) = __nv_bfloat162(h0, h1);
                        *(__nv_bfloat162*)(dl + o) = __nv_bfloat162(l0, l1);
                    }
                } else {
                    *(float2*)(out + (size_t)m * N + n) = make_float2(v0, v1);
                }
            }
        }
    }
}

// ---------------------------------------------------------------------------
// Attention: bf16x3 mma + ldmatrix, no-max softmax, poly/MUFU exp.
// CTA: 128 q-rows, one (b,h). 8 warps (4M x 2N). KV tiles of 128.
// (unchanged: exp/issue-bound, not occupancy-recoverable w/o spills)
// ---------------------------------------------------------------------------
#define A_QHI 0
#define A_QLO 18432
#define A_KHI 36864
#define A_KLO 55296
#define A_VHI 73728
#define A_VLO 91136
#define A_OA  36864          // union (post-loop)
#define A_OB  70656
#define A_LP  104448
#define A_LI  105472
#define A_SMEM 108544

__global__ __launch_bounds__(256) void attn_mma_kernel()
{
    extern __shared__ char as_[];
    uint32_t asb = smem_u32(as_);

    int tid = threadIdx.x;
    int wid = tid >> 5;
    int lane = tid & 31;
    int qr = lane >> 2;
    int qc = lane & 3;
    int wm = wid & 3;
    int wn = wid >> 2;
    int q0 = blockIdx.x * 128;
    int h = blockIdx.y;
    int b = blockIdx.z;

    int row_in = lane & 7;
    int tsel = lane >> 3;
    uint32_t laneAq = (uint32_t)(((tsel & 1) * 8 + row_in) * 144 + (tsel >> 1) * 16);
    uint32_t laneBk = (uint32_t)(((tsel >> 1) * 8 + row_in) * 144 + (tsel & 1) * 16);
    uint32_t laneBv = (uint32_t)(((tsel >> 1) * 8 + row_in) * 272 + (tsel & 1) * 16);

    const size_t bh = (size_t)(b * H_ + h);
    const __nv_bfloat16* gqh = g_q_hi + (bh * T_ + q0) * HD_;
    const __nv_bfloat16* gql = g_q_lo + (bh * T_ + q0) * HD_;
    const __nv_bfloat16* gkh = g_k_hi + bh * T_ * HD_;
    const __nv_bfloat16* gkl = g_k_lo + bh * T_ * HD_;
    const __nv_bfloat16* gvh = g_v_hi + bh * HD_ * T_;
    const __nv_bfloat16* gvl = g_v_lo + bh * HD_ * T_;

    // load Q tiles (hi/lo): 128 rows x 64 halves, stride 144B
#pragma unroll
    for (int r = 0; r < 4; ++r) {
        int id = tid + r * 256;
        int row = id >> 3;
        int c = id & 7;
        *(uint4*)(as_ + A_QHI + row * 144 + c * 16) = *(const uint4*)(gqh + (size_t)row * HD_ + c * 8);
        *(uint4*)(as_ + A_QLO + row * 144 + c * 16) = *(const uint4*)(gql + (size_t)row * HD_ + c * 8);
    }
    __syncthreads();

    // Q hi fragments in registers
    uint32_t qh[2][4][4];
#pragma unroll
    for (int i = 0; i < 2; ++i) {
#pragma unroll
        for (int t = 0; t < 4; ++t) {
            LDSM_X4(qh[i][t], asb + A_QHI + (uint32_t)((wm * 32 + i * 16) * 144 + t * 32) + laneAq);
        }
    }

    float oacc[2][8][4];
#pragma unroll
    for (int i = 0; i < 2; i++)
#pragma unroll
        for (int j = 0; j < 8; j++)
#pragma unroll
            for (int c = 0; c < 4; c++) oacc[i][j][c] = 0.0f;
    float lsum[2][2] = {{0.f, 0.f}, {0.f, 0.f}};

    for (int kt = 0; kt < T_ / 128; ++kt) {
        __syncthreads();
        // load K tile (hi/lo) and V^T tile (hi/lo)
        {
            const __nv_bfloat16* kh_p = gkh + (size_t)kt * 128 * HD_;
            const __nv_bfloat16* kl_p = gkl + (size_t)kt * 128 * HD_;
#pragma unroll
            for (int r = 0; r < 4; ++r) {
                int id = tid + r * 256;
                int row = id >> 3;
                int c = id & 7;
                *(uint4*)(as_ + A_KHI + row * 144 + c * 16) = *(const uint4*)(kh_p + (size_t)row * HD_ + c * 8);
                *(uint4*)(as_ + A_KLO + row * 144 + c * 16) = *(const uint4*)(kl_p + (size_t)row * HD_ + c * 8);
            }
#pragma unroll
            for (int r = 0; r < 4; ++r) {
                int id = tid + r * 256;
                int row = id >> 4;     // hd row 0..63
                int c = id & 15;
                *(uint4*)(as_ + A_VHI + row * 272 + c * 16) = *(const uint4*)(gvh + (size_t)row * T_ + kt * 128 + c * 8);
                *(uint4*)(as_ + A_VLO + row * 272 + c * 16) = *(const uint4*)(gvl + (size_t)row * T_ + kt * 128 + c * 8);
            }
        }
        __syncthreads();

        // ---- S = Q K^T (bf16x3) ----
        float sacc[2][8][4];
#pragma unroll
        for (int i = 0; i < 2; i++)
#pragma unroll
            for (int j = 0; j < 8; j++)
#pragma unroll
                for (int c = 0; c < 4; c++) sacc[i][j][c] = 0.0f;

#pragma unroll
        for (int t = 0; t < 4; ++t) {
            uint32_t koff = (uint32_t)(t * 32);
            uint32_t ql[2][4];
#pragma unroll
            for (int i = 0; i < 2; ++i) {
                LDSM_X4(ql[i], asb + A_QLO + (uint32_t)((wm * 32 + i * 16) * 144) + koff + laneAq);
            }
#pragma unroll
            for (int p = 0; p < 4; ++p) {
                uint32_t boff = (uint32_t)((wn * 64 + p * 16) * 144) + koff;
                uint32_t kh4[4], kl4[4];
                LDSM_X4(kh4, asb + A_KHI + boff + laneBk);
                LDSM_X4(kl4, asb + A_KLO + boff + laneBk);
#pragma unroll
                for (int half = 0; half < 2; ++half) {
                    int j = 2 * p + half;
                    uint32_t bh0 = kh4[half * 2], bh1 = kh4[half * 2 + 1];
                    uint32_t bl0 = kl4[half * 2], bl1 = kl4[half * 2 + 1];
#pragma unroll
                    for (int i = 0; i < 2; ++i) {
                        mma_bf16(sacc[i][j], qh[i][t][0], qh[i][t][1], qh[i][t][2], qh[i][t][3], bh0, bh1);
                        mma_bf16(sacc[i][j], qh[i][t][0], qh[i][t][1], qh[i][t][2], qh[i][t][3], bl0, bl1);
                        mma_bf16(sacc[i][j], ql[i][0], ql[i][1], ql[i][2], ql[i][3], bh0, bh1);
                    }
                }
            }
        }

        // ---- exp (no max subtraction) + pack P hi/lo ----
        uint32_t ph[2][8][2], pl[2][8][2];
#pragma unroll
        for (int i = 0; i < 2; ++i) {
#pragma unroll
            for (int j = 0; j < 8; ++j) {
                float p0, p1, p2, p3;
                if (j < 3) {
                    p0 = exp_scaled_mufu(sacc[i][j][0]);
                    p1 = exp_scaled_mufu(sacc[i][j][1]);
                    p2 = exp_scaled_mufu(sacc[i][j][2]);
                    p3 = exp_scaled_mufu(sacc[i][j][3]);
                } else {
                    p0 = exp_scaled_poly(sacc[i][j][0]);
                    p1 = exp_scaled_poly(sacc[i][j][1]);
                    p2 = exp_scaled_poly(sacc[i][j][2]);
                    p3 = exp_scaled_poly(sacc[i][j][3]);
                }
                lsum[i][0] += p0 + p1;
                lsum[i][1] += p2 + p3;
                uint32_t h01 = pack_bf16(p0, p1);
                uint32_t h23 = pack_bf16(p2, p3);
                float r0 = p0 - __int_as_float(h01 << 16);
                float r1 = p1 - __int_as_float(h01 & 0xFFFF0000u);
                float r2 = p2 - __int_as_float(h23 << 16);
                float r3 = p3 - __int_as_float(h23 & 0xFFFF0000u);
                ph[i][j][0] = h01;
                ph[i][j][1] = h23;
                pl[i][j][0] = pack_bf16(r0, r1);
                pl[i][j][1] = pack_bf16(r2, r3);
            }
        }

        // ---- O += P V (bf16x3); warp covers kv slice wn*64..+64 ----
#pragma unroll
        for (int t = 0; t < 4; ++t) {
            uint32_t koff = (uint32_t)(wn * 128 + t * 32);
#pragma unroll
            for (int p = 0; p < 4; ++p) {
                uint32_t boff = (uint32_t)(p * 16 * 272) + koff;
                uint32_t vh4[4], vl4[4];
                LDSM_X4(vh4, asb + A_VHI + boff + laneBv);
                LDSM_X4(vl4, asb + A_VLO + boff + laneBv);
#pragma unroll
                for (int half = 0; half < 2; ++half) {
                    int j = 2 * p + half;
                    uint32_t vh0 = vh4[half * 2], vh1 = vh4[half * 2 + 1];
                    uint32_t vl0 = vl4[half * 2], vl1 = vl4[half * 2 + 1];
#pragma unroll
                    for (int i = 0; i < 2; ++i) {
                        uint32_t a0 = ph[i][2 * t][0], a1 = ph[i][2 * t][1];
                        uint32_t a2 = ph[i][2 * t + 1][0], a3 = ph[i][2 * t + 1][1];
                        mma_bf16(oacc[i][j], a0, a1, a2, a3, vh0, vh1);
                        mma_bf16(oacc[i][j], a0, a1, a2, a3, vl0, vl1);
                        mma_bf16(oacc[i][j], pl[i][2 * t][0], pl[i][2 * t][1],
                                 pl[i][2 * t + 1][0], pl[i][2 * t + 1][1], vh0, vh1);
                    }
                }
            }
        }
    }

    __syncthreads();   // done with K/V smem; reuse for O reduction

    // store partial O (per wn) to smem
    {
        float* obuf = (float*)(as_ + (wn == 0 ? A_OA : A_OB));
#pragma unroll
        for (int i = 0; i < 2; ++i) {
#pragma unroll
            for (int j = 0; j < 8; ++j) {
                int row = wm * 32 + i * 16 + qr;
                int col = j * 8 + qc * 2;
                *(float2*)&obuf[row * 66 + col] = make_float2(oacc[i][j][0], oacc[i][j][1]);
                *(float2*)&obuf[(row + 8) * 66 + col] = make_float2(oacc[i][j][2], oacc[i][j][3]);
            }
        }
    }
    // reduce l over qc lanes, write partials
    {
        float* lp = (float*)(as_ + A_LP);
#pragma unroll
        for (int i = 0; i < 2; ++i) {
#pragma unroll
            for (int hf = 0; hf < 2; ++hf) {
                float v = lsum[i][hf];
                v += __shfl_xor_sync(0xffffffffu, v, 1);
                v += __shfl_xor_sync(0xffffffffu, v, 2);
                lsum[i][hf] = v;
            }
            if (qc == 0) {
                lp[wn * 128 + wm * 32 + i * 16 + qr] = lsum[i][0];
                lp[wn * 128 + wm * 32 + i * 16 + qr + 8] = lsum[i][1];
            }
        }
    }
    __syncthreads();
    {
        float* lp = (float*)(as_ + A_LP);
        float* li = (float*)(as_ + A_LI);
        if (tid < 128) li[tid] = 1.0f / (lp[tid] + lp[128 + tid]);
    }
    __syncthreads();

    // final: sum partials, normalize, split, write g_ao
    {
        const float* oA = (const float*)(as_ + A_OA);
        const float* oB = (const float*)(as_ + A_OB);
        const float* li = (const float*)(as_ + A_LI);
        int colp = (tid & 31) * 2;
        int rbase = tid >> 5;
#pragma unroll
        for (int pass = 0; pass < 16; ++pass) {
            int row = pass * 8 + rbase;
            float iv = li[row];
            float o0 = (oA[row * 66 + colp] + oB[row * 66 + colp]) * iv;
            float o1 = (oA[row * 66 + colp + 1] + oB[row * 66 + colp + 1]) * iv;
            uint32_t hp = pack_bf16(o0, o1);
            float r0 = o0 - __int_as_float(hp << 16);
            float r1 = o1 - __int_as_float(hp & 0xFFFF0000u);
            uint32_t lpk = pack_bf16(r0, r1);
            size_t go = ((size_t)(b * T_ + q0 + row)) * D_ + h * HD_ + colp;
            *(uint32_t*)(g_ao_hi + go) = hp;
            *(uint32_t*)(g_ao_lo + go) = lpk;
        }
    }
}

// ---------------------------------------------------------------------------
extern "C" void kernel_launch(void* const* d_in, const int* in_sizes, int n_in,
                              void* d_out, int out_size)
{
    const float* x = (const float*)d_in[0];
    const float* w_qkv = (const float*)d_in[1];
    const float* b_qkv = (const float*)d_in[2];
    const float* w_proj = (const float*)d_in[3];
    const float* b_proj = (const float*)d_in[4];
    float* out = (float*)d_out;

    __nv_bfloat16 *xhi, *xlo, *wqh, *wql, *wph, *wpl;
    cudaGetSymbolAddress((void**)&xhi, g_x_hi);
    cudaGetSymbolAddress((void**)&xlo, g_x_lo);
    cudaGetSymbolAddress((void**)&wqh, g_wqkvT_hi);
    cudaGetSymbolAddress((void**)&wql, g_wqkvT_lo);
    cudaGetSymbolAddress((void**)&wph, g_wprojT_hi);
    cudaGetSymbolAddress((void**)&wpl, g_wprojT_lo);

    cudaFuncSetAttribute(gemm_bf16x3_kernel, cudaFuncAttributeMaxDynamicSharedMemorySize, 2 * GSTAGE);
    cudaFuncSetAttribute(attn_mma_kernel, cudaFuncAttributeMaxDynamicSharedMemorySize, A_SMEM);

    // split x -> bf16 hi/lo
    {
        int n = M_ * K_;
        split_kernel<<<(n / 4 + 255) / 256, 256>>>(x, xhi, xlo, n);
    }
    transpose_split_kernel<<<dim3(NQKV / 32, K_ / 32), dim3(32, 8)>>>(w_qkv, wqh, wql, K_, NQKV);
    transpose_split_kernel<<<dim3(D_ / 32, K_ / 32), dim3(32, 8)>>>(w_proj, wph, wpl, K_, D_);

    // QKV GEMM -> split q/k/v
    gemm_bf16x3_kernel<<<dim3(NQKV / 128, M_ / 128), 256, 2 * GSTAGE>>>(b_qkv, nullptr, NQKV, 0);

    // Attention (tensor cores + fast exp) -> g_ao hi/lo
    attn_mma_kernel<<<dim3(T_ / 128, H_, B_), 256, A_SMEM>>>();

    // Output projection -> out
    gemm_bf16x3_kernel<<<dim3(D_ / 128, M_ / 128), 256, 2 * GSTAGE>>>(b_proj, out, D_, 1);
}

// round 8
// speedup vs baseline: 1.1621x; 1.0537x over previous
#include <cuda_runtime.h>
#include <cuda_bf16.h>
#include <cstdint>

#define B_ 4
#define T_ 2048
#define D_ 1024
#define H_ 16
#define HD_ 64
#define K_ 1024
#define M_ (B_*T_)        // 8192
#define NQKV (3*D_)       // 3072

// ---------------------------------------------------------------------------
// Scratch (device globals — allocation-free rule)
// ---------------------------------------------------------------------------
__device__ __nv_bfloat16 g_q_hi[(size_t)B_ * H_ * T_ * HD_];
__device__ __nv_bfloat16 g_q_lo[(size_t)B_ * H_ * T_ * HD_];
__device__ __nv_bfloat16 g_k_hi[(size_t)B_ * H_ * T_ * HD_];
__device__ __nv_bfloat16 g_k_lo[(size_t)B_ * H_ * T_ * HD_];
__device__ __nv_bfloat16 g_v_hi[(size_t)B_ * H_ * HD_ * T_];   // transposed [b,h,hd,t]
__device__ __nv_bfloat16 g_v_lo[(size_t)B_ * H_ * HD_ * T_];
__device__ __nv_bfloat16 g_x_hi[(size_t)M_ * K_];
__device__ __nv_bfloat16 g_x_lo[(size_t)M_ * K_];
__device__ __nv_bfloat16 g_wqkvT_hi[(size_t)NQKV * K_];
__device__ __nv_bfloat16 g_wqkvT_lo[(size_t)NQKV * K_];
__device__ __nv_bfloat16 g_wprojT_hi[(size_t)D_ * K_];
__device__ __nv_bfloat16 g_wprojT_lo[(size_t)D_ * K_];
__device__ __nv_bfloat16 g_ao_hi[(size_t)M_ * D_];
__device__ __nv_bfloat16 g_ao_lo[(size_t)M_ * D_];

// ---------------------------------------------------------------------------
// Helpers
// ---------------------------------------------------------------------------
__device__ __forceinline__ uint32_t smem_u32(const void* p) {
    uint32_t a;
    asm("{ .reg .u64 t; cvta.to.shared.u64 t, %1; cvt.u32.u64 %0, t; }" : "=r"(a) : "l"(p));
    return a;
}
__device__ __forceinline__ void mma_bf16(float c[4], uint32_t a0, uint32_t a1,
                                         uint32_t a2, uint32_t a3,
                                         uint32_t b0, uint32_t b1) {
    asm volatile(
        "mma.sync.aligned.m16n8k16.row.col.f32.bf16.bf16.f32 "
        "{%0,%1,%2,%3},{%4,%5,%6,%7},{%8,%9},{%0,%1,%2,%3};"
        : "+f"(c[0]), "+f"(c[1]), "+f"(c[2]), "+f"(c[3])
        : "r"(a0), "r"(a1), "r"(a2), "r"(a3), "r"(b0), "r"(b1));
}
#define LDSM_X4(R, ADDR) \
    asm volatile("ldmatrix.sync.aligned.m8n8.x4.shared.b16 {%0,%1,%2,%3}, [%4];" \
        : "=r"((R)[0]), "=r"((R)[1]), "=r"((R)[2]), "=r"((R)[3]) : "r"(ADDR))

#define CP_ASYNC16(DST, SRC) \
    asm volatile("cp.async.cg.shared.global [%0], [%1], 16;" :: "r"(DST), "l"(SRC))

// d = {hi_elem:f_hi | lo_elem:f_lo}
__device__ __forceinline__ uint32_t pack_bf16(float f_lo, float f_hi) {
    uint32_t d;
    asm("cvt.rn.bf16x2.f32 %0, %1, %2;" : "=r"(d) : "f"(f_hi), "f"(f_lo));
    return d;
}
// exp(s/8) = 2^(s*C); polynomial path (FMA pipe)
__device__ __forceinline__ float exp_scaled_poly(float s) {
    const float C = 0.18033688011112042f;
    const float MAGIC = 12582912.0f;   // 1.5 * 2^23
    float r = __fmaf_rn(s, C, MAGIC);
    float t = r - MAGIC;
    float f = __fmaf_rn(s, C, -t);     // f in [-0.5, 0.5]
    float p = 0.0013333558146428443f;
    p = __fmaf_rn(p, f, 0.009618129107628477f);
    p = __fmaf_rn(p, f, 0.05550410866482158f);
    p = __fmaf_rn(p, f, 0.2402265069591007f);
    p = __fmaf_rn(p, f, 0.6931471805599453f);
    p = __fmaf_rn(p, f, 1.0f);
    return __int_as_float(__float_as_int(p) + (__float_as_int(r) << 23));
}
// MUFU path
__device__ __forceinline__ float exp_scaled_mufu(float s) {
    float z = s * 0.18033688011112042f;
    float r;
    asm("ex2.approx.f32 %0, %1;" : "=f"(r) : "f"(z));
    return r;
}

// ---------------------------------------------------------------------------
// Splitters
// ---------------------------------------------------------------------------
__global__ void split_kernel(const float* __restrict__ src,
                             __nv_bfloat16* __restrict__ hi,
                             __nv_bfloat16* __restrict__ lo, int n)
{
    int i = (blockIdx.x * blockDim.x + threadIdx.x) * 4;
    if (i >= n) return;
    float4 v = *(const float4*)(src + i);
    __nv_bfloat16 h0 = __float2bfloat16(v.x);
    __nv_bfloat16 h1 = __float2bfloat16(v.y);
    __nv_bfloat16 h2 = __float2bfloat16(v.z);
    __nv_bfloat16 h3 = __float2bfloat16(v.w);
    __nv_bfloat16 l0 = __float2bfloat16(v.x - __bfloat162float(h0));
    __nv_bfloat16 l1 = __float2bfloat16(v.y - __bfloat162float(h1));
    __nv_bfloat16 l2 = __float2bfloat16(v.z - __bfloat162float(h2));
    __nv_bfloat16 l3 = __float2bfloat16(v.w - __bfloat162float(h3));
    *(__nv_bfloat162*)(hi + i)     = __nv_bfloat162(h0, h1);
    *(__nv_bfloat162*)(hi + i + 2) = __nv_bfloat162(h2, h3);
    *(__nv_bfloat162*)(lo + i)     = __nv_bfloat162(l0, l1);
    *(__nv_bfloat162*)(lo + i + 2) = __nv_bfloat162(l2, l3);
}

__global__ void transpose_split_kernel(const float* __restrict__ src,
                                       __nv_bfloat16* __restrict__ hi,
                                       __nv_bfloat16* __restrict__ lo,
                                       int K, int N)
{
    __shared__ float tile[32][33];
    int nb = blockIdx.x * 32, kb = blockIdx.y * 32;
    int tx = threadIdx.x, ty = threadIdx.y;  // 32 x 8
#pragma unroll
    for (int r = ty; r < 32; r += 8)
        tile[r][tx] = src[(size_t)(kb + r) * N + nb + tx];
    __syncthreads();
#pragma unroll
    for (int r = ty; r < 32; r += 8) {
        float v = tile[tx][r];
        __nv_bfloat16 h = __float2bfloat16(v);
        size_t o = (size_t)(nb + r) * K + kb + tx;
        hi[o] = h;
        lo[o] = __float2bfloat16(v - __bfloat162float(h));
    }
}

// ---------------------------------------------------------------------------
// bf16x3 GEMM, cp.async double-buffered, ldmatrix fragment loads.
// CTA 128x128, BK=32, 8 warps (4M x 2N), warp tile 32x64.
// __launch_bounds__(256, 2): cap regs at 128 so 2 CTAs/SM fit.
// ---------------------------------------------------------------------------
#define GTILE 10240           // 128 rows * 80B
#define GSTAGE (4*GTILE)      // 40960

__global__ __launch_bounds__(256, 2) void gemm_bf16x3_kernel(
    const float* __restrict__ bias, float* __restrict__ out, int N, int mode)
{
    extern __shared__ char gs[];
    uint32_t gsb = smem_u32(gs);

    int tid = threadIdx.x;
    int wid = tid >> 5;
    int lane = tid & 31;
    int qr = lane >> 2;
    int qc = lane & 3;
    int wm = wid & 3;
    int wn = wid >> 2;
    int bm = blockIdx.y * 128;
    int bn = blockIdx.x * 128;

    // ldmatrix lane offsets
    int row_in = lane & 7;
    int tsel = lane >> 3;
    uint32_t laneA = (uint32_t)(((tsel & 1) * 8 + row_in) * 80 + (tsel >> 1) * 16);
    uint32_t laneB = (uint32_t)(((tsel >> 1) * 8 + row_in) * 80 + (tsel & 1) * 16);

    const __nv_bfloat16* Ahi = (mode == 0) ? g_x_hi : g_ao_hi;
    const __nv_bfloat16* Alo = (mode == 0) ? g_x_lo : g_ao_lo;
    const __nv_bfloat16* Bhi = (mode == 0) ? g_wqkvT_hi : g_wprojT_hi;
    const __nv_bfloat16* Blo = (mode == 0) ? g_wqkvT_lo : g_wprojT_lo;

    const __nv_bfloat16* srcp[4] = {
        Ahi + (size_t)bm * K_, Alo + (size_t)bm * K_,
        Bhi + (size_t)bn * K_, Blo + (size_t)bn * K_ };

    float acc[2][8][4];
#pragma unroll
    for (int i = 0; i < 2; i++)
#pragma unroll
        for (int j = 0; j < 8; j++)
#pragma unroll
            for (int c = 0; c < 4; c++) acc[i][j][c] = 0.0f;

    const int NC = K_ / 32;

#define GISSUE(CH, STG) do { int _k0 = (CH) * 32;                                   \
    _Pragma("unroll")                                                               \
    for (int t8 = 0; t8 < 8; ++t8) {                                                \
        int id = tid + t8 * 256; int tle = id >> 9; int rem = id & 511;             \
        int row = rem >> 2; int c = rem & 3;                                        \
        const __nv_bfloat16* sp = srcp[tle] + (size_t)row * K_ + _k0 + c * 8;       \
        uint32_t dp = gsb + (STG) * GSTAGE + tle * GTILE + row * 80 + c * 16;       \
        CP_ASYNC16(dp, sp);                                                         \
    }                                                                               \
    asm volatile("cp.async.commit_group;"); } while (0)

    GISSUE(0, 0);

    for (int ch = 0; ch < NC; ++ch) {
        if (ch + 1 < NC) {
            GISSUE(ch + 1, (ch + 1) & 1);
            asm volatile("cp.async.wait_group 1;");
        } else {
            asm volatile("cp.async.wait_group 0;");
        }
        __syncthreads();

        uint32_t sA0 = gsb + (ch & 1) * GSTAGE;
        uint32_t sA1 = sA0 + GTILE;
        uint32_t sB0 = sA0 + 2 * GTILE;
        uint32_t sB1 = sA0 + 3 * GTILE;

#pragma unroll
        for (int k16 = 0; k16 < 2; ++k16) {
            uint32_t koff = k16 * 32;
            uint32_t ah[2][4], al[2][4];
#pragma unroll
            for (int i = 0; i < 2; ++i) {
                uint32_t aoff = (uint32_t)((wm * 32 + i * 16) * 80) + koff;
                LDSM_X4(ah[i], sA0 + aoff + laneA);
                LDSM_X4(al[i], sA1 + aoff + laneA);
            }
#pragma unroll
            for (int p = 0; p < 4; ++p) {
                uint32_t boff = (uint32_t)((wn * 64 + p * 16) * 80) + koff;
                uint32_t bh4[4], bl4[4];
                LDSM_X4(bh4, sB0 + boff + laneB);
                LDSM_X4(bl4, sB1 + boff + laneB);
#pragma unroll
                for (int half = 0; half < 2; ++half) {
                    int j = 2 * p + half;
                    uint32_t bh0 = bh4[half * 2], bh1 = bh4[half * 2 + 1];
                    uint32_t bl0 = bl4[half * 2], bl1 = bl4[half * 2 + 1];
#pragma unroll
                    for (int i = 0; i < 2; ++i) {
                        mma_bf16(acc[i][j], ah[i][0], ah[i][1], ah[i][2], ah[i][3], bh0, bh1);
                        mma_bf16(acc[i][j], ah[i][0], ah[i][1], ah[i][2], ah[i][3], bl0, bl1);
                        mma_bf16(acc[i][j], al[i][0], al[i][1], al[i][2], al[i][3], bh0, bh1);
                    }
                }
            }
        }
        __syncthreads();
    }

    // epilogue
#pragma unroll
    for (int i = 0; i < 2; ++i) {
#pragma unroll
        for (int j = 0; j < 8; ++j) {
            int n = bn + wn * 64 + j * 8 + qc * 2;
            float b0v = bias[n], b1v = bias[n + 1];
#pragma unroll
            for (int half = 0; half < 2; ++half) {
                int m = bm + wm * 32 + i * 16 + qr + half * 8;
                float v0 = acc[i][j][half * 2 + 0] + b0v;
                float v1 = acc[i][j][half * 2 + 1] + b1v;
                if (mode == 0) {
                    int bq = m >> 11;
                    int t = m & (T_ - 1);
                    int sel = n >> 10;
                    int dd = n & (D_ - 1);
                    int h = dd >> 6;
                    int hd = dd & (HD_ - 1);
                    __nv_bfloat16 h0 = __float2bfloat16(v0);
                    __nv_bfloat16 h1 = __float2bfloat16(v1);
                    __nv_bfloat16 l0 = __float2bfloat16(v0 - __bfloat162float(h0));
                    __nv_bfloat16 l1 = __float2bfloat16(v1 - __bfloat162float(h1));
                    if (sel == 2) {
                        size_t vb = ((size_t)(bq * H_ + h) * HD_);
                        g_v_hi[(vb + hd) * T_ + t] = h0;
                        g_v_hi[(vb + hd + 1) * T_ + t] = h1;
                        g_v_lo[(vb + hd) * T_ + t] = l0;
                        g_v_lo[(vb + hd + 1) * T_ + t] = l1;
                    } else {
                        size_t o = ((size_t)(bq * H_ + h) * T_ + t) * HD_ + hd;
                        __nv_bfloat16* dh = (sel == 0) ? g_q_hi : g_k_hi;
                        __nv_bfloat16* dl = (sel == 0) ? g_q_lo : g_k_lo;
                        *(__nv_bfloat162*)(dh + o) = __nv_bfloat162(h0, h1);
                        *(__nv_bfloat162*)(dl + o) = __nv_bfloat162(l0, l1);
                    }
                } else {
                    *(float2*)(out + (size_t)m * N + n) = make_float2(v0, v1);
                }
            }
        }
    }
}

// ---------------------------------------------------------------------------
// Attention: bf16x3 mma + ldmatrix, no-max softmax, poly/MUFU exp.
// KV tiles double-buffered via cp.async (hides 71.7KB/iter load exposure).
// CTA: 128 q-rows, one (b,h). 8 warps (4M x 2N). KV tiles of 128.
// ---------------------------------------------------------------------------
#define A_QHI 0
#define A_QLO 18432
#define KV_STAGE 71680        // KHI 18432 + KLO 18432 + VHI 17408 + VLO 17408
#define A_ST(s) (36864 + (s) * KV_STAGE)
#define KO_KHI 0
#define KO_KLO 18432
#define KO_VHI 36864
#define KO_VLO 54272
// post-loop reduction areas reuse the stage region
#define A_OA  36864
#define A_OB  70656
#define A_LP  104448
#define A_LI  105472
#define A_SMEM 180224         // 36864 + 2*71680

__global__ __launch_bounds__(256) void attn_mma_kernel()
{
    extern __shared__ char as_[];
    uint32_t asb = smem_u32(as_);

    int tid = threadIdx.x;
    int wid = tid >> 5;
    int lane = tid & 31;
    int qr = lane >> 2;
    int qc = lane & 3;
    int wm = wid & 3;
    int wn = wid >> 2;
    int q0 = blockIdx.x * 128;
    int h = blockIdx.y;
    int b = blockIdx.z;

    int row_in = lane & 7;
    int tsel = lane >> 3;
    uint32_t laneAq = (uint32_t)(((tsel & 1) * 8 + row_in) * 144 + (tsel >> 1) * 16);
    uint32_t laneBk = (uint32_t)(((tsel >> 1) * 8 + row_in) * 144 + (tsel & 1) * 16);
    uint32_t laneBv = (uint32_t)(((tsel >> 1) * 8 + row_in) * 272 + (tsel & 1) * 16);

    const size_t bh = (size_t)(b * H_ + h);
    const __nv_bfloat16* gqh = g_q_hi + (bh * T_ + q0) * HD_;
    const __nv_bfloat16* gql = g_q_lo + (bh * T_ + q0) * HD_;
    const __nv_bfloat16* gkh = g_k_hi + bh * T_ * HD_;
    const __nv_bfloat16* gkl = g_k_lo + bh * T_ * HD_;
    const __nv_bfloat16* gvh = g_v_hi + bh * HD_ * T_;
    const __nv_bfloat16* gvl = g_v_lo + bh * HD_ * T_;

#define KV_ISSUE(KT, STG) do {                                                        \
    const __nv_bfloat16* _khp = gkh + (size_t)(KT) * 128 * HD_;                       \
    const __nv_bfloat16* _klp = gkl + (size_t)(KT) * 128 * HD_;                       \
    const __nv_bfloat16* _vhp = gvh + (KT) * 128;                                     \
    const __nv_bfloat16* _vlp = gvl + (KT) * 128;                                     \
    uint32_t _sb = asb + A_ST(STG);                                                   \
    _Pragma("unroll")                                                                 \
    for (int r = 0; r < 4; ++r) {                                                     \
        int id = tid + r * 256;                                                       \
        int row = id >> 3; int c = id & 7;                                            \
        CP_ASYNC16(_sb + KO_KHI + row * 144 + c * 16, _khp + (size_t)row * HD_ + c * 8); \
        CP_ASYNC16(_sb + KO_KLO + row * 144 + c * 16, _klp + (size_t)row * HD_ + c * 8); \
    }                                                                                 \
    _Pragma("unroll")                                                                 \
    for (int r = 0; r < 4; ++r) {                                                     \
        int id = tid + r * 256;                                                       \
        int row = id >> 4; int c = id & 15;                                           \
        CP_ASYNC16(_sb + KO_VHI + row * 272 + c * 16, _vhp + (size_t)row * T_ + c * 8);  \
        CP_ASYNC16(_sb + KO_VLO + row * 272 + c * 16, _vlp + (size_t)row * T_ + c * 8);  \
    }                                                                                 \
    asm volatile("cp.async.commit_group;"); } while (0)

    // prefetch KV tile 0 (async, overlaps Q load below)
    KV_ISSUE(0, 0);

    // load Q tiles (hi/lo): 128 rows x 64 halves, stride 144B
#pragma unroll
    for (int r = 0; r < 4; ++r) {
        int id = tid + r * 256;
        int row = id >> 3;
        int c = id & 7;
        *(uint4*)(as_ + A_QHI + row * 144 + c * 16) = *(const uint4*)(gqh + (size_t)row * HD_ + c * 8);
        *(uint4*)(as_ + A_QLO + row * 144 + c * 16) = *(const uint4*)(gql + (size_t)row * HD_ + c * 8);
    }
    __syncthreads();

    // Q hi fragments in registers
    uint32_t qh[2][4][4];
#pragma unroll
    for (int i = 0; i < 2; ++i) {
#pragma unroll
        for (int t = 0; t < 4; ++t) {
            LDSM_X4(qh[i][t], asb + A_QHI + (uint32_t)((wm * 32 + i * 16) * 144 + t * 32) + laneAq);
        }
    }

    float oacc[2][8][4];
#pragma unroll
    for (int i = 0; i < 2; i++)
#pragma unroll
        for (int j = 0; j < 8; j++)
#pragma unroll
            for (int c = 0; c < 4; c++) oacc[i][j][c] = 0.0f;
    float lsum[2][2] = {{0.f, 0.f}, {0.f, 0.f}};

    const int NT = T_ / 128;
    for (int kt = 0; kt < NT; ++kt) {
        if (kt + 1 < NT) {
            KV_ISSUE(kt + 1, (kt + 1) & 1);
            asm volatile("cp.async.wait_group 1;");
        } else {
            asm volatile("cp.async.wait_group 0;");
        }
        __syncthreads();

        uint32_t stg = asb + A_ST(kt & 1);

        // ---- S = Q K^T (bf16x3) ----
        float sacc[2][8][4];
#pragma unroll
        for (int i = 0; i < 2; i++)
#pragma unroll
            for (int j = 0; j < 8; j++)
#pragma unroll
                for (int c = 0; c < 4; c++) sacc[i][j][c] = 0.0f;

#pragma unroll
        for (int t = 0; t < 4; ++t) {
            uint32_t koff = (uint32_t)(t * 32);
            uint32_t ql[2][4];
#pragma unroll
            for (int i = 0; i < 2; ++i) {
                LDSM_X4(ql[i], asb + A_QLO + (uint32_t)((wm * 32 + i * 16) * 144) + koff + laneAq);
            }
#pragma unroll
            for (int p = 0; p < 4; ++p) {
                uint32_t boff = (uint32_t)((wn * 64 + p * 16) * 144) + koff;
                uint32_t kh4[4], kl4[4];
                LDSM_X4(kh4, stg + KO_KHI + boff + laneBk);
                LDSM_X4(kl4, stg + KO_KLO + boff + laneBk);
#pragma unroll
                for (int half = 0; half < 2; ++half) {
                    int j = 2 * p + half;
                    uint32_t bh0 = kh4[half * 2], bh1 = kh4[half * 2 + 1];
                    uint32_t bl0 = kl4[half * 2], bl1 = kl4[half * 2 + 1];
#pragma unroll
                    for (int i = 0; i < 2; ++i) {
                        mma_bf16(sacc[i][j], qh[i][t][0], qh[i][t][1], qh[i][t][2], qh[i][t][3], bh0, bh1);
                        mma_bf16(sacc[i][j], qh[i][t][0], qh[i][t][1], qh[i][t][2], qh[i][t][3], bl0, bl1);
                        mma_bf16(sacc[i][j], ql[i][0], ql[i][1], ql[i][2], ql[i][3], bh0, bh1);
                    }
                }
            }
        }

        // ---- exp (no max subtraction) + pack P hi/lo ----
        uint32_t ph[2][8][2], pl[2][8][2];
#pragma unroll
        for (int i = 0; i < 2; ++i) {
#pragma unroll
            for (int j = 0; j < 8; ++j) {
                float p0, p1, p2, p3;
                if (j < 3) {
                    p0 = exp_scaled_mufu(sacc[i][j][0]);
                    p1 = exp_scaled_mufu(sacc[i][j][1]);
                    p2 = exp_scaled_mufu(sacc[i][j][2]);
                    p3 = exp_scaled_mufu(sacc[i][j][3]);
                } else {
                    p0 = exp_scaled_poly(sacc[i][j][0]);
                    p1 = exp_scaled_poly(sacc[i][j][1]);
                    p2 = exp_scaled_poly(sacc[i][j][2]);
                    p3 = exp_scaled_poly(sacc[i][j][3]);
                }
                lsum[i][0] += p0 + p1;
                lsum[i][1] += p2 + p3;
                uint32_t h01 = pack_bf16(p0, p1);
                uint32_t h23 = pack_bf16(p2, p3);
                float r0 = p0 - __int_as_float(h01 << 16);
                float r1 = p1 - __int_as_float(h01 & 0xFFFF0000u);
                float r2 = p2 - __int_as_float(h23 << 16);
                float r3 = p3 - __int_as_float(h23 & 0xFFFF0000u);
                ph[i][j][0] = h01;
                ph[i][j][1] = h23;
                pl[i][j][0] = pack_bf16(r0, r1);
                pl[i][j][1] = pack_bf16(r2, r3);
            }
        }

        // ---- O += P V (bf16x3); warp covers kv slice wn*64..+64 ----
#pragma unroll
        for (int t = 0; t < 4; ++t) {
            uint32_t koff = (uint32_t)(wn * 128 + t * 32);
#pragma unroll
            for (int p = 0; p < 4; ++p) {
                uint32_t boff = (uint32_t)(p * 16 * 272) + koff;
                uint32_t vh4[4], vl4[4];
                LDSM_X4(vh4, stg + KO_VHI + boff + laneBv);
                LDSM_X4(vl4, stg + KO_VLO + boff + laneBv);
#pragma unroll
                for (int half = 0; half < 2; ++half) {
                    int j = 2 * p + half;
                    uint32_t vh0 = vh4[half * 2], vh1 = vh4[half * 2 + 1];
                    uint32_t vl0 = vl4[half * 2], vl1 = vl4[half * 2 + 1];
#pragma unroll
                    for (int i = 0; i < 2; ++i) {
                        uint32_t a0 = ph[i][2 * t][0], a1 = ph[i][2 * t][1];
                        uint32_t a2 = ph[i][2 * t + 1][0], a3 = ph[i][2 * t + 1][1];
                        mma_bf16(oacc[i][j], a0, a1, a2, a3, vh0, vh1);
                        mma_bf16(oacc[i][j], a0, a1, a2, a3, vl0, vl1);
                        mma_bf16(oacc[i][j], pl[i][2 * t][0], pl[i][2 * t][1],
                                 pl[i][2 * t + 1][0], pl[i][2 * t + 1][1], vh0, vh1);
                    }
                }
            }
        }
        __syncthreads();   // all warps done with stage (kt&1) before it's re-filled
    }

    // store partial O (per wn) to smem (stage region reused; loop's trailing bar protects)
    {
        float* obuf = (float*)(as_ + (wn == 0 ? A_OA : A_OB));
#pragma unroll
        for (int i = 0; i < 2; ++i) {
#pragma unroll
            for (int j = 0; j < 8; ++j) {
                int row = wm * 32 + i * 16 + qr;
                int col = j * 8 + qc * 2;
                *(float2*)&obuf[row * 66 + col] = make_float2(oacc[i][j][0], oacc[i][j][1]);
                *(float2*)&obuf[(row + 8) * 66 + col] = make_float2(oacc[i][j][2], oacc[i][j][3]);
            }
        }
    }
    // reduce l over qc lanes, write partials
    {
        float* lp = (float*)(as_ + A_LP);
#pragma unroll
        for (int i = 0; i < 2; ++i) {
#pragma unroll
            for (int hf = 0; hf < 2; ++hf) {
                float v = lsum[i][hf];
                v += __shfl_xor_sync(0xffffffffu, v, 1);
                v += __shfl_xor_sync(0xffffffffu, v, 2);
                lsum[i][hf] = v;
            }
            if (qc == 0) {
                lp[wn * 128 + wm * 32 + i * 16 + qr] = lsum[i][0];
                lp[wn * 128 + wm * 32 + i * 16 + qr + 8] = lsum[i][1];
            }
        }
    }
    __syncthreads();
    {
        float* lp = (float*)(as_ + A_LP);
        float* li = (float*)(as_ + A_LI);
        if (tid < 128) li[tid] = 1.0f / (lp[tid] + lp[128 + tid]);
    }
    __syncthreads();

    // final: sum partials, normalize, split, write g_ao
    {
        const float* oA = (const float*)(as_ + A_OA);
        const float* oB = (const float*)(as_ + A_OB);
        const float* li = (const float*)(as_ + A_LI);
        int colp = (tid & 31) * 2;
        int rbase = tid >> 5;
#pragma unroll
        for (int pass = 0; pass < 16; ++pass) {
            int row = pass * 8 + rbase;
            float iv = li[row];
            float o0 = (oA[row * 66 + colp] + oB[row * 66 + colp]) * iv;
            float o1 = (oA[row * 66 + colp + 1] + oB[row * 66 + colp + 1]) * iv;
            uint32_t hp = pack_bf16(o0, o1);
            float r0 = o0 - __int_as_float(hp << 16);
            float r1 = o1 - __int_as_float(hp & 0xFFFF0000u);
            uint32_t lpk = pack_bf16(r0, r1);
            size_t go = ((size_t)(b * T_ + q0 + row)) * D_ + h * HD_ + colp;
            *(uint32_t*)(g_ao_hi + go) = hp;
            *(uint32_t*)(g_ao_lo + go) = lpk;
        }
    }
}

// ---------------------------------------------------------------------------
extern "C" void kernel_launch(void* const* d_in, const int* in_sizes, int n_in,
                              void* d_out, int out_size)
{
    const float* x = (const float*)d_in[0];
    const float* w_qkv = (const float*)d_in[1];
    const float* b_qkv = (const float*)d_in[2];
    const float* w_proj = (const float*)d_in[3];
    const float* b_proj = (const float*)d_in[4];
    float* out = (float*)d_out;

    __nv_bfloat16 *xhi, *xlo, *wqh, *wql, *wph, *wpl;
    cudaGetSymbolAddress((void**)&xhi, g_x_hi);
    cudaGetSymbolAddress((void**)&xlo, g_x_lo);
    cudaGetSymbolAddress((void**)&wqh, g_wqkvT_hi);
    cudaGetSymbolAddress((void**)&wql, g_wqkvT_lo);
    cudaGetSymbolAddress((void**)&wph, g_wprojT_hi);
    cudaGetSymbolAddress((void**)&wpl, g_wprojT_lo);

    cudaFuncSetAttribute(gemm_bf16x3_kernel, cudaFuncAttributeMaxDynamicSharedMemorySize, 2 * GSTAGE);
    cudaFuncSetAttribute(attn_mma_kernel, cudaFuncAttributeMaxDynamicSharedMemorySize, A_SMEM);

    // split x -> bf16 hi/lo
    {
        int n = M_ * K_;
        split_kernel<<<(n / 4 + 255) / 256, 256>>>(x, xhi, xlo, n);
    }
    transpose_split_kernel<<<dim3(NQKV / 32, K_ / 32), dim3(32, 8)>>>(w_qkv, wqh, wql, K_, NQKV);
    transpose_split_kernel<<<dim3(D_ / 32, K_ / 32), dim3(32, 8)>>>(w_proj, wph, wpl, K_, D_);

    // QKV GEMM -> split q/k/v
    gemm_bf16x3_kernel<<<dim3(NQKV / 128, M_ / 128), 256, 2 * GSTAGE>>>(b_qkv, nullptr, NQKV, 0);

    // Attention (tensor cores + fast exp, cp.async KV pipeline) -> g_ao hi/lo
    attn_mma_kernel<<<dim3(T_ / 128, H_, B_), 256, A_SMEM>>>();

    // Output projection -> out
    gemm_bf16x3_kernel<<<dim3(D_ / 128, M_ / 128), 256, 2 * GSTAGE>>>(b_proj, out, D_, 1);
}

// round 10
// speedup vs baseline: 1.1855x; 1.0202x over previous
#include <cuda_runtime.h>
#include <cuda_bf16.h>
#include <cstdint>

#define B_ 4
#define T_ 2048
#define D_ 1024
#define H_ 16
#define HD_ 64
#define K_ 1024
#define M_ (B_*T_)        // 8192
#define NQKV (3*D_)       // 3072

// ---------------------------------------------------------------------------
// Scratch (device globals — allocation-free rule)
// ---------------------------------------------------------------------------
__device__ __nv_bfloat16 g_q_hi[(size_t)B_ * H_ * T_ * HD_];
__device__ __nv_bfloat16 g_q_lo[(size_t)B_ * H_ * T_ * HD_];
__device__ __nv_bfloat16 g_k_hi[(size_t)B_ * H_ * T_ * HD_];
__device__ __nv_bfloat16 g_k_lo[(size_t)B_ * H_ * T_ * HD_];
__device__ __nv_bfloat16 g_v_hi[(size_t)B_ * H_ * HD_ * T_];   // transposed [b,h,hd,t]
__device__ __nv_bfloat16 g_v_lo[(size_t)B_ * H_ * HD_ * T_];
__device__ __nv_bfloat16 g_x_hi[(size_t)M_ * K_];
__device__ __nv_bfloat16 g_x_lo[(size_t)M_ * K_];
__device__ __nv_bfloat16 g_wqkvT_hi[(size_t)NQKV * K_];
__device__ __nv_bfloat16 g_wqkvT_lo[(size_t)NQKV * K_];
__device__ __nv_bfloat16 g_wprojT_hi[(size_t)D_ * K_];
__device__ __nv_bfloat16 g_wprojT_lo[(size_t)D_ * K_];
__device__ __nv_bfloat16 g_ao_hi[(size_t)M_ * D_];
__device__ __nv_bfloat16 g_ao_lo[(size_t)M_ * D_];

// ---------------------------------------------------------------------------
// Helpers
// ---------------------------------------------------------------------------
__device__ __forceinline__ uint32_t smem_u32(const void* p) {
    uint32_t a;
    asm("{ .reg .u64 t; cvta.to.shared.u64 t, %1; cvt.u32.u64 %0, t; }" : "=r"(a) : "l"(p));
    return a;
}
__device__ __forceinline__ void mma_bf16(float c[4], uint32_t a0, uint32_t a1,
                                         uint32_t a2, uint32_t a3,
                                         uint32_t b0, uint32_t b1) {
    asm volatile(
        "mma.sync.aligned.m16n8k16.row.col.f32.bf16.bf16.f32 "
        "{%0,%1,%2,%3},{%4,%5,%6,%7},{%8,%9},{%0,%1,%2,%3};"
        : "+f"(c[0]), "+f"(c[1]), "+f"(c[2]), "+f"(c[3])
        : "r"(a0), "r"(a1), "r"(a2), "r"(a3), "r"(b0), "r"(b1));
}
#define LDSM_X4(R, ADDR) \
    asm volatile("ldmatrix.sync.aligned.m8n8.x4.shared.b16 {%0,%1,%2,%3}, [%4];" \
        : "=r"((R)[0]), "=r"((R)[1]), "=r"((R)[2]), "=r"((R)[3]) : "r"(ADDR))

#define CP_ASYNC16(DST, SRC) \
    asm volatile("cp.async.cg.shared.global [%0], [%1], 16;" :: "r"(DST), "l"(SRC))

// d = {hi_elem:f_hi | lo_elem:f_lo}
__device__ __forceinline__ uint32_t pack_bf16(float f_lo, float f_hi) {
    uint32_t d;
    asm("cvt.rn.bf16x2.f32 %0, %1, %2;" : "=r"(d) : "f"(f_hi), "f"(f_lo));
    return d;
}
// exp(s/8) = 2^(s*C) via MUFU (all exp on the MUFU pipe; fma pipe stays free)
__device__ __forceinline__ float exp_scaled_mufu(float s) {
    float z = s * 0.18033688011112042f;
    float r;
    asm("ex2.approx.f32 %0, %1;" : "=f"(r) : "f"(z));
    return r;
}

// ---------------------------------------------------------------------------
// Splitters
// ---------------------------------------------------------------------------
__global__ void split_kernel(const float* __restrict__ src,
                             __nv_bfloat16* __restrict__ hi,
                             __nv_bfloat16* __restrict__ lo, int n)
{
    int i = (blockIdx.x * blockDim.x + threadIdx.x) * 4;
    if (i >= n) return;
    float4 v = *(const float4*)(src + i);
    __nv_bfloat16 h0 = __float2bfloat16(v.x);
    __nv_bfloat16 h1 = __float2bfloat16(v.y);
    __nv_bfloat16 h2 = __float2bfloat16(v.z);
    __nv_bfloat16 h3 = __float2bfloat16(v.w);
    __nv_bfloat16 l0 = __float2bfloat16(v.x - __bfloat162float(h0));
    __nv_bfloat16 l1 = __float2bfloat16(v.y - __bfloat162float(h1));
    __nv_bfloat16 l2 = __float2bfloat16(v.z - __bfloat162float(h2));
    __nv_bfloat16 l3 = __float2bfloat16(v.w - __bfloat162float(h3));
    *(__nv_bfloat162*)(hi + i)     = __nv_bfloat162(h0, h1);
    *(__nv_bfloat162*)(hi + i + 2) = __nv_bfloat162(h2, h3);
    *(__nv_bfloat162*)(lo + i)     = __nv_bfloat162(l0, l1);
    *(__nv_bfloat162*)(lo + i + 2) = __nv_bfloat162(l2, l3);
}

__global__ void transpose_split_kernel(const float* __restrict__ src,
                                       __nv_bfloat16* __restrict__ hi,
                                       __nv_bfloat16* __restrict__ lo,
                                       int K, int N)
{
    __shared__ float tile[32][33];
    int nb = blockIdx.x * 32, kb = blockIdx.y * 32;
    int tx = threadIdx.x, ty = threadIdx.y;  // 32 x 8
#pragma unroll
    for (int r = ty; r < 32; r += 8)
        tile[r][tx] = src[(size_t)(kb + r) * N + nb + tx];
    __syncthreads();
#pragma unroll
    for (int r = ty; r < 32; r += 8) {
        float v = tile[tx][r];
        __nv_bfloat16 h = __float2bfloat16(v);
        size_t o = (size_t)(nb + r) * K + kb + tx;
        hi[o] = h;
        lo[o] = __float2bfloat16(v - __bfloat162float(h));
    }
}

// ---------------------------------------------------------------------------
// bf16x3 GEMM, cp.async double-buffered, ldmatrix fragment loads.
// CTA 128x128, BK=32, 8 warps (4M x 2N), warp tile 32x64.
// __launch_bounds__(256, 2): cap regs at 128 so 2 CTAs/SM fit.
// ---------------------------------------------------------------------------
#define GTILE 10240           // 128 rows * 80B
#define GSTAGE (4*GTILE)      // 40960

__global__ __launch_bounds__(256, 2) void gemm_bf16x3_kernel(
    const float* __restrict__ bias, float* __restrict__ out, int N, int mode)
{
    extern __shared__ char gs[];
    uint32_t gsb = smem_u32(gs);

    int tid = threadIdx.x;
    int wid = tid >> 5;
    int lane = tid & 31;
    int qr = lane >> 2;
    int qc = lane & 3;
    int wm = wid & 3;
    int wn = wid >> 2;
    int bm = blockIdx.y * 128;
    int bn = blockIdx.x * 128;

    // ldmatrix lane offsets
    int row_in = lane & 7;
    int tsel = lane >> 3;
    uint32_t laneA = (uint32_t)(((tsel & 1) * 8 + row_in) * 80 + (tsel >> 1) * 16);
    uint32_t laneB = (uint32_t)(((tsel >> 1) * 8 + row_in) * 80 + (tsel & 1) * 16);

    const __nv_bfloat16* Ahi = (mode == 0) ? g_x_hi : g_ao_hi;
    const __nv_bfloat16* Alo = (mode == 0) ? g_x_lo : g_ao_lo;
    const __nv_bfloat16* Bhi = (mode == 0) ? g_wqkvT_hi : g_wprojT_hi;
    const __nv_bfloat16* Blo = (mode == 0) ? g_wqkvT_lo : g_wprojT_lo;

    const __nv_bfloat16* srcp[4] = {
        Ahi + (size_t)bm * K_, Alo + (size_t)bm * K_,
        Bhi + (size_t)bn * K_, Blo + (size_t)bn * K_ };

    float acc[2][8][4];
#pragma unroll
    for (int i = 0; i < 2; i++)
#pragma unroll
        for (int j = 0; j < 8; j++)
#pragma unroll
            for (int c = 0; c < 4; c++) acc[i][j][c] = 0.0f;

    const int NC = K_ / 32;

#define GISSUE(CH, STG) do { int _k0 = (CH) * 32;                                   \
    _Pragma("unroll")                                                               \
    for (int t8 = 0; t8 < 8; ++t8) {                                                \
        int id = tid + t8 * 256; int tle = id >> 9; int rem = id & 511;             \
        int row = rem >> 2; int c = rem & 3;                                        \
        const __nv_bfloat16* sp = srcp[tle] + (size_t)row * K_ + _k0 + c * 8;       \
        uint32_t dp = gsb + (STG) * GSTAGE + tle * GTILE + row * 80 + c * 16;       \
        CP_ASYNC16(dp, sp);                                                         \
    }                                                                               \
    asm volatile("cp.async.commit_group;"); } while (0)

    GISSUE(0, 0);

    for (int ch = 0; ch < NC; ++ch) {
        if (ch + 1 < NC) {
            GISSUE(ch + 1, (ch + 1) & 1);
            asm volatile("cp.async.wait_group 1;");
        } else {
            asm volatile("cp.async.wait_group 0;");
        }
        __syncthreads();

        uint32_t sA0 = gsb + (ch & 1) * GSTAGE;
        uint32_t sA1 = sA0 + GTILE;
        uint32_t sB0 = sA0 + 2 * GTILE;
        uint32_t sB1 = sA0 + 3 * GTILE;

#pragma unroll
        for (int k16 = 0; k16 < 2; ++k16) {
            uint32_t koff = k16 * 32;
            uint32_t ah[2][4], al[2][4];
#pragma unroll
            for (int i = 0; i < 2; ++i) {
                uint32_t aoff = (uint32_t)((wm * 32 + i * 16) * 80) + koff;
                LDSM_X4(ah[i], sA0 + aoff + laneA);
                LDSM_X4(al[i], sA1 + aoff + laneA);
            }
#pragma unroll
            for (int p = 0; p < 4; ++p) {
                uint32_t boff = (uint32_t)((wn * 64 + p * 16) * 80) + koff;
                uint32_t bh4[4], bl4[4];
                LDSM_X4(bh4, sB0 + boff + laneB);
                LDSM_X4(bl4, sB1 + boff + laneB);
#pragma unroll
                for (int half = 0; half < 2; ++half) {
                    int j = 2 * p + half;
                    uint32_t bh0 = bh4[half * 2], bh1 = bh4[half * 2 + 1];
                    uint32_t bl0 = bl4[half * 2], bl1 = bl4[half * 2 + 1];
#pragma unroll
                    for (int i = 0; i < 2; ++i) {
                        mma_bf16(acc[i][j], ah[i][0], ah[i][1], ah[i][2], ah[i][3], bh0, bh1);
                        mma_bf16(acc[i][j], ah[i][0], ah[i][1], ah[i][2], ah[i][3], bl0, bl1);
                        mma_bf16(acc[i][j], al[i][0], al[i][1], al[i][2], al[i][3], bh0, bh1);
                    }
                }
            }
        }
        __syncthreads();
    }

    // epilogue
#pragma unroll
    for (int i = 0; i < 2; ++i) {
#pragma unroll
        for (int j = 0; j < 8; ++j) {
            int n = bn + wn * 64 + j * 8 + qc * 2;
            float b0v = bias[n], b1v = bias[n + 1];
#pragma unroll
            for (int half = 0; half < 2; ++half) {
                int m = bm + wm * 32 + i * 16 + qr + half * 8;
                float v0 = acc[i][j][half * 2 + 0] + b0v;
                float v1 = acc[i][j][half * 2 + 1] + b1v;
                if (mode == 0) {
                    int bq = m >> 11;
                    int t = m & (T_ - 1);
                    int sel = n >> 10;
                    int dd = n & (D_ - 1);
                    int h = dd >> 6;
                    int hd = dd & (HD_ - 1);
                    __nv_bfloat16 h0 = __float2bfloat16(v0);
                    __nv_bfloat16 h1 = __float2bfloat16(v1);
                    __nv_bfloat16 l0 = __float2bfloat16(v0 - __bfloat162float(h0));
                    __nv_bfloat16 l1 = __float2bfloat16(v1 - __bfloat162float(h1));
                    if (sel == 2) {
                        size_t vb = ((size_t)(bq * H_ + h) * HD_);
                        g_v_hi[(vb + hd) * T_ + t] = h0;
                        g_v_hi[(vb + hd + 1) * T_ + t] = h1;
                        g_v_lo[(vb + hd) * T_ + t] = l0;
                        g_v_lo[(vb + hd + 1) * T_ + t] = l1;
                    } else {
                        size_t o = ((size_t)(bq * H_ + h) * T_ + t) * HD_ + hd;
                        __nv_bfloat16* dh = (sel == 0) ? g_q_hi : g_k_hi;
                        __nv_bfloat16* dl = (sel == 0) ? g_q_lo : g_k_lo;
                        *(__nv_bfloat162*)(dh + o) = __nv_bfloat162(h0, h1);
                        *(__nv_bfloat162*)(dl + o) = __nv_bfloat162(l0, l1);
                    }
                } else {
                    *(float2*)(out + (size_t)m * N + n) = make_float2(v0, v1);
                }
            }
        }
    }
}

// ---------------------------------------------------------------------------
// Attention: bf16x3 S and PV, all-MUFU exp, cp.async KV pipeline.
// CTA: 128 q-rows, one (b,h). 8 warps (4M x 2N). KV tiles of 128.
// ---------------------------------------------------------------------------
#define A_QHI 0
#define A_QLO 18432
#define KV_STAGE 71680        // KHI 18432 + KLO 18432 + VHI 17408 + VLO 17408
#define A_ST(s) (36864 + (s) * KV_STAGE)
#define KO_KHI 0
#define KO_KLO 18432
#define KO_VHI 36864
#define KO_VLO 54272
// post-loop reduction areas reuse the stage region
#define A_OA  36864
#define A_OB  70656
#define A_LP  104448
#define A_LI  105472
#define A_SMEM 180224         // 36864 + 2*71680

__global__ __launch_bounds__(256) void attn_mma_kernel()
{
    extern __shared__ char as_[];
    uint32_t asb = smem_u32(as_);

    int tid = threadIdx.x;
    int wid = tid >> 5;
    int lane = tid & 31;
    int qr = lane >> 2;
    int qc = lane & 3;
    int wm = wid & 3;
    int wn = wid >> 2;
    int q0 = blockIdx.x * 128;
    int h = blockIdx.y;
    int b = blockIdx.z;

    int row_in = lane & 7;
    int tsel = lane >> 3;
    uint32_t laneAq = (uint32_t)(((tsel & 1) * 8 + row_in) * 144 + (tsel >> 1) * 16);
    uint32_t laneBk = (uint32_t)(((tsel >> 1) * 8 + row_in) * 144 + (tsel & 1) * 16);
    uint32_t laneBv = (uint32_t)(((tsel >> 1) * 8 + row_in) * 272 + (tsel & 1) * 16);

    const size_t bh = (size_t)(b * H_ + h);
    const __nv_bfloat16* gqh = g_q_hi + (bh * T_ + q0) * HD_;
    const __nv_bfloat16* gql = g_q_lo + (bh * T_ + q0) * HD_;
    const __nv_bfloat16* gkh = g_k_hi + bh * T_ * HD_;
    const __nv_bfloat16* gkl = g_k_lo + bh * T_ * HD_;
    const __nv_bfloat16* gvh = g_v_hi + bh * HD_ * T_;
    const __nv_bfloat16* gvl = g_v_lo + bh * HD_ * T_;

#define KV_ISSUE(KT, STG) do {                                                        \
    const __nv_bfloat16* _khp = gkh + (size_t)(KT) * 128 * HD_;                       \
    const __nv_bfloat16* _klp = gkl + (size_t)(KT) * 128 * HD_;                       \
    const __nv_bfloat16* _vhp = gvh + (KT) * 128;                                     \
    const __nv_bfloat16* _vlp = gvl + (KT) * 128;                                     \
    uint32_t _sb = asb + A_ST(STG);                                                   \
    _Pragma("unroll")                                                                 \
    for (int r = 0; r < 4; ++r) {                                                     \
        int id = tid + r * 256;                                                       \
        int row = id >> 3; int c = id & 7;                                            \
        CP_ASYNC16(_sb + KO_KHI + row * 144 + c * 16, _khp + (size_t)row * HD_ + c * 8); \
        CP_ASYNC16(_sb + KO_KLO + row * 144 + c * 16, _klp + (size_t)row * HD_ + c * 8); \
    }                                                                                 \
    _Pragma("unroll")                                                                 \
    for (int r = 0; r < 4; ++r) {                                                     \
        int id = tid + r * 256;                                                       \
        int row = id >> 4; int c = id & 15;                                           \
        CP_ASYNC16(_sb + KO_VHI + row * 272 + c * 16, _vhp + (size_t)row * T_ + c * 8);  \
        CP_ASYNC16(_sb + KO_VLO + row * 272 + c * 16, _vlp + (size_t)row * T_ + c * 8);  \
    }                                                                                 \
    asm volatile("cp.async.commit_group;"); } while (0)

    // prefetch KV tile 0 (async, overlaps Q load below)
    KV_ISSUE(0, 0);

    // load Q tiles (hi/lo): 128 rows x 64 halves, stride 144B
#pragma unroll
    for (int r = 0; r < 4; ++r) {
        int id = tid + r * 256;
        int row = id >> 3;
        int c = id & 7;
        *(uint4*)(as_ + A_QHI + row * 144 + c * 16) = *(const uint4*)(gqh + (size_t)row * HD_ + c * 8);
        *(uint4*)(as_ + A_QLO + row * 144 + c * 16) = *(const uint4*)(gql + (size_t)row * HD_ + c * 8);
    }
    __syncthreads();

    // Q hi fragments in registers
    uint32_t qh[2][4][4];
#pragma unroll
    for (int i = 0; i < 2; ++i) {
#pragma unroll
        for (int t = 0; t < 4; ++t) {
            LDSM_X4(qh[i][t], asb + A_QHI + (uint32_t)((wm * 32 + i * 16) * 144 + t * 32) + laneAq);
        }
    }

    float oacc[2][8][4];
#pragma unroll
    for (int i = 0; i < 2; i++)
#pragma unroll
        for (int j = 0; j < 8; j++)
#pragma unroll
            for (int c = 0; c < 4; c++) oacc[i][j][c] = 0.0f;
    float lsum[2][2] = {{0.f, 0.f}, {0.f, 0.f}};

    const int NT = T_ / 128;
    for (int kt = 0; kt < NT; ++kt) {
        if (kt + 1 < NT) {
            KV_ISSUE(kt + 1, (kt + 1) & 1);
            asm volatile("cp.async.wait_group 1;");
        } else {
            asm volatile("cp.async.wait_group 0;");
        }
        __syncthreads();

        uint32_t stg = asb + A_ST(kt & 1);

        // ---- S = Q K^T (bf16x3) ----
        float sacc[2][8][4];
#pragma unroll
        for (int i = 0; i < 2; i++)
#pragma unroll
            for (int j = 0; j < 8; j++)
#pragma unroll
                for (int c = 0; c < 4; c++) sacc[i][j][c] = 0.0f;

#pragma unroll
        for (int t = 0; t < 4; ++t) {
            uint32_t koff = (uint32_t)(t * 32);
            uint32_t ql[2][4];
#pragma unroll
            for (int i = 0; i < 2; ++i) {
                LDSM_X4(ql[i], asb + A_QLO + (uint32_t)((wm * 32 + i * 16) * 144) + koff + laneAq);
            }
#pragma unroll
            for (int p = 0; p < 4; ++p) {
                uint32_t boff = (uint32_t)((wn * 64 + p * 16) * 144) + koff;
                uint32_t kh4[4], kl4[4];
                LDSM_X4(kh4, stg + KO_KHI + boff + laneBk);
                LDSM_X4(kl4, stg + KO_KLO + boff + laneBk);
#pragma unroll
                for (int half = 0; half < 2; ++half) {
                    int j = 2 * p + half;
                    uint32_t bh0 = kh4[half * 2], bh1 = kh4[half * 2 + 1];
                    uint32_t bl0 = kl4[half * 2], bl1 = kl4[half * 2 + 1];
#pragma unroll
                    for (int i = 0; i < 2; ++i) {
                        mma_bf16(sacc[i][j], qh[i][t][0], qh[i][t][1], qh[i][t][2], qh[i][t][3], bh0, bh1);
                        mma_bf16(sacc[i][j], qh[i][t][0], qh[i][t][1], qh[i][t][2], qh[i][t][3], bl0, bl1);
                        mma_bf16(sacc[i][j], ql[i][0], ql[i][1], ql[i][2], ql[i][3], bh0, bh1);
                    }
                }
            }
        }

        // ---- exp (no max subtraction, all-MUFU) + pack P hi/lo ----
        uint32_t ph[2][8][2], pl[2][8][2];
#pragma unroll
        for (int i = 0; i < 2; ++i) {
#pragma unroll
            for (int j = 0; j < 8; ++j) {
                float p0 = exp_scaled_mufu(sacc[i][j][0]);
                float p1 = exp_scaled_mufu(sacc[i][j][1]);
                float p2 = exp_scaled_mufu(sacc[i][j][2]);
                float p3 = exp_scaled_mufu(sacc[i][j][3]);
                lsum[i][0] += p0 + p1;
                lsum[i][1] += p2 + p3;
                uint32_t h01 = pack_bf16(p0, p1);
                uint32_t h23 = pack_bf16(p2, p3);
                float r0 = p0 - __int_as_float(h01 << 16);
                float r1 = p1 - __int_as_float(h01 & 0xFFFF0000u);
                float r2 = p2 - __int_as_float(h23 << 16);
                float r3 = p3 - __int_as_float(h23 & 0xFFFF0000u);
                ph[i][j][0] = h01;
                ph[i][j][1] = h23;
                pl[i][j][0] = pack_bf16(r0, r1);
                pl[i][j][1] = pack_bf16(r2, r3);
            }
        }

        // ---- O += P V (bf16x3); warp covers kv slice wn*64..+64 ----
#pragma unroll
        for (int t = 0; t < 4; ++t) {
            uint32_t koff = (uint32_t)(wn * 128 + t * 32);
#pragma unroll
            for (int p = 0; p < 4; ++p) {
                uint32_t boff = (uint32_t)(p * 16 * 272) + koff;
                uint32_t vh4[4], vl4[4];
                LDSM_X4(vh4, stg + KO_VHI + boff + laneBv);
                LDSM_X4(vl4, stg + KO_VLO + boff + laneBv);
#pragma unroll
                for (int half = 0; half < 2; ++half) {
                    int j = 2 * p + half;
                    uint32_t vh0 = vh4[half * 2], vh1 = vh4[half * 2 + 1];
                    uint32_t vl0 = vl4[half * 2], vl1 = vl4[half * 2 + 1];
#pragma unroll
                    for (int i = 0; i < 2; ++i) {
                        uint32_t a0 = ph[i][2 * t][0], a1 = ph[i][2 * t][1];
                        uint32_t a2 = ph[i][2 * t + 1][0], a3 = ph[i][2 * t + 1][1];
                        mma_bf16(oacc[i][j], a0, a1, a2, a3, vh0, vh1);
                        mma_bf16(oacc[i][j], a0, a1, a2, a3, vl0, vl1);
                        mma_bf16(oacc[i][j], pl[i][2 * t][0], pl[i][2 * t][1],
                                 pl[i][2 * t + 1][0], pl[i][2 * t + 1][1], vh0, vh1);
                    }
                }
            }
        }
        __syncthreads();   // all warps done with stage (kt&1) before it's re-filled
    }

    // store partial O (per wn) to smem (stage region reused; loop's trailing bar protects)
    {
        float* obuf = (float*)(as_ + (wn == 0 ? A_OA : A_OB));
#pragma unroll
        for (int i = 0; i < 2; ++i) {
#pragma unroll
            for (int j = 0; j < 8; ++j) {
                int row = wm * 32 + i * 16 + qr;
                int col = j * 8 + qc * 2;
                *(float2*)&obuf[row * 66 + col] = make_float2(oacc[i][j][0], oacc[i][j][1]);
                *(float2*)&obuf[(row + 8) * 66 + col] = make_float2(oacc[i][j][2], oacc[i][j][3]);
            }
        }
    }
    // reduce l over qc lanes, write partials
    {
        float* lp = (float*)(as_ + A_LP);
#pragma unroll
        for (int i = 0; i < 2; ++i) {
#pragma unroll
            for (int hf = 0; hf < 2; ++hf) {
                float v = lsum[i][hf];
                v += __shfl_xor_sync(0xffffffffu, v, 1);
                v += __shfl_xor_sync(0xffffffffu, v, 2);
                lsum[i][hf] = v;
            }
            if (qc == 0) {
                lp[wn * 128 + wm * 32 + i * 16 + qr] = lsum[i][0];
                lp[wn * 128 + wm * 32 + i * 16 + qr + 8] = lsum[i][1];
            }
        }
    }
    __syncthreads();
    {
        float* lp = (float*)(as_ + A_LP);
        float* li = (float*)(as_ + A_LI);
        if (tid < 128) li[tid] = 1.0f / (lp[tid] + lp[128 + tid]);
    }
    __syncthreads();

    // final: sum partials, normalize, split, write g_ao
    {
        const float* oA = (const float*)(as_ + A_OA);
        const float* oB = (const float*)(as_ + A_OB);
        const float* li = (const float*)(as_ + A_LI);
        int colp = (tid & 31) * 2;
        int rbase = tid >> 5;
#pragma unroll
        for (int pass = 0; pass < 16; ++pass) {
            int row = pass * 8 + rbase;
            float iv = li[row];
            float o0 = (oA[row * 66 + colp] + oB[row * 66 + colp]) * iv;
            float o1 = (oA[row * 66 + colp + 1] + oB[row * 66 + colp + 1]) * iv;
            uint32_t hp = pack_bf16(o0, o1);
            float r0 = o0 - __int_as_float(hp << 16);
            float r1 = o1 - __int_as_float(hp & 0xFFFF0000u);
            uint32_t lpk = pack_bf16(r0, r1);
            size_t go = ((size_t)(b * T_ + q0 + row)) * D_ + h * HD_ + colp;
            *(uint32_t*)(g_ao_hi + go) = hp;
            *(uint32_t*)(g_ao_lo + go) = lpk;
        }
    }
}

// ---------------------------------------------------------------------------
extern "C" void kernel_launch(void* const* d_in, const int* in_sizes, int n_in,
                              void* d_out, int out_size)
{
    const float* x = (const float*)d_in[0];
    const float* w_qkv = (const float*)d_in[1];
    const float* b_qkv = (const float*)d_in[2];
    const float* w_proj = (const float*)d_in[3];
    const float* b_proj = (const float*)d_in[4];
    float* out = (float*)d_out;

    __nv_bfloat16 *xhi, *xlo, *wqh, *wql, *wph, *wpl;
    cudaGetSymbolAddress((void**)&xhi, g_x_hi);
    cudaGetSymbolAddress((void**)&xlo, g_x_lo);
    cudaGetSymbolAddress((void**)&wqh, g_wqkvT_hi);
    cudaGetSymbolAddress((void**)&wql, g_wqkvT_lo);
    cudaGetSymbolAddress((void**)&wph, g_wprojT_hi);
    cudaGetSymbolAddress((void**)&wpl, g_wprojT_lo);

    cudaFuncSetAttribute(gemm_bf16x3_kernel, cudaFuncAttributeMaxDynamicSharedMemorySize, 2 * GSTAGE);
    cudaFuncSetAttribute(attn_mma_kernel, cudaFuncAttributeMaxDynamicSharedMemorySize, A_SMEM);

    // split x -> bf16 hi/lo
    {
        int n = M_ * K_;
        split_kernel<<<(n / 4 + 255) / 256, 256>>>(x, xhi, xlo, n);
    }
    transpose_split_kernel<<<dim3(NQKV / 32, K_ / 32), dim3(32, 8)>>>(w_qkv, wqh, wql, K_, NQKV);
    transpose_split_kernel<<<dim3(D_ / 32, K_ / 32), dim3(32, 8)>>>(w_proj, wph, wpl, K_, D_);

    // QKV GEMM -> split q/k/v
    gemm_bf16x3_kernel<<<dim3(NQKV / 128, M_ / 128), 256, 2 * GSTAGE>>>(b_qkv, nullptr, NQKV, 0);

    // Attention (tensor cores + MUFU exp, cp.async KV pipeline) -> g_ao hi/lo
    attn_mma_kernel<<<dim3(T_ / 128, H_, B_), 256, A_SMEM>>>();

    // Output projection -> out
    gemm_bf16x3_kernel<<<dim3(D_ / 128, M_ / 128), 256, 2 * GSTAGE>>>(b_proj, out, D_, 1);
}

// round 11
// speedup vs baseline: 1.3048x; 1.1006x over previous
#include <cuda_runtime.h>
#include <cuda_bf16.h>
#include <cstdint>

#define B_ 4
#define T_ 2048
#define D_ 1024
#define H_ 16
#define HD_ 64
#define K_ 1024
#define M_ (B_*T_)        // 8192
#define NQKV (3*D_)       // 3072

// ---------------------------------------------------------------------------
// Scratch (device globals — allocation-free rule)
// ---------------------------------------------------------------------------
__device__ __nv_bfloat16 g_q_hi[(size_t)B_ * H_ * T_ * HD_];
__device__ __nv_bfloat16 g_q_lo[(size_t)B_ * H_ * T_ * HD_];
__device__ __nv_bfloat16 g_k_hi[(size_t)B_ * H_ * T_ * HD_];
__device__ __nv_bfloat16 g_k_lo[(size_t)B_ * H_ * T_ * HD_];
__device__ __nv_bfloat16 g_v_hi[(size_t)B_ * H_ * HD_ * T_];   // transposed [b,h,hd,t]
__device__ __nv_bfloat16 g_v_lo[(size_t)B_ * H_ * HD_ * T_];
__device__ __nv_bfloat16 g_x_hi[(size_t)M_ * K_];
__device__ __nv_bfloat16 g_x_lo[(size_t)M_ * K_];
__device__ __nv_bfloat16 g_wqkvT_hi[(size_t)NQKV * K_];
__device__ __nv_bfloat16 g_wqkvT_lo[(size_t)NQKV * K_];
__device__ __nv_bfloat16 g_wprojT_hi[(size_t)D_ * K_];
__device__ __nv_bfloat16 g_wprojT_lo[(size_t)D_ * K_];
__device__ __nv_bfloat16 g_ao_hi[(size_t)M_ * D_];
__device__ __nv_bfloat16 g_ao_lo[(size_t)M_ * D_];

// ---------------------------------------------------------------------------
// Helpers
// ---------------------------------------------------------------------------
__device__ __forceinline__ uint32_t smem_u32(const void* p) {
    uint32_t a;
    asm("{ .reg .u64 t; cvta.to.shared.u64 t, %1; cvt.u32.u64 %0, t; }" : "=r"(a) : "l"(p));
    return a;
}
__device__ __forceinline__ void mma_bf16(float c[4], uint32_t a0, uint32_t a1,
                                         uint32_t a2, uint32_t a3,
                                         uint32_t b0, uint32_t b1) {
    asm volatile(
        "mma.sync.aligned.m16n8k16.row.col.f32.bf16.bf16.f32 "
        "{%0,%1,%2,%3},{%4,%5,%6,%7},{%8,%9},{%0,%1,%2,%3};"
        : "+f"(c[0]), "+f"(c[1]), "+f"(c[2]), "+f"(c[3])
        : "r"(a0), "r"(a1), "r"(a2), "r"(a3), "r"(b0), "r"(b1));
}
#define LDSM_X4(R, ADDR) \
    asm volatile("ldmatrix.sync.aligned.m8n8.x4.shared.b16 {%0,%1,%2,%3}, [%4];" \
        : "=r"((R)[0]), "=r"((R)[1]), "=r"((R)[2]), "=r"((R)[3]) : "r"(ADDR))

#define CP_ASYNC16(DST, SRC) \
    asm volatile("cp.async.cg.shared.global [%0], [%1], 16;" :: "r"(DST), "l"(SRC))

// d = {hi_elem:f_hi | lo_elem:f_lo}
__device__ __forceinline__ uint32_t pack_bf16(float f_lo, float f_hi) {
    uint32_t d;
    asm("cvt.rn.bf16x2.f32 %0, %1, %2;" : "=r"(d) : "f"(f_hi), "f"(f_lo));
    return d;
}
// exp(s/8) = 2^(s*C) via MUFU
__device__ __forceinline__ float exp_scaled_mufu(float s) {
    float z = s * 0.18033688011112042f;
    float r;
    asm("ex2.approx.f32 %0, %1;" : "=f"(r) : "f"(z));
    return r;
}

// ---------------------------------------------------------------------------
// Splitters
// ---------------------------------------------------------------------------
__global__ void split_kernel(const float* __restrict__ src,
                             __nv_bfloat16* __restrict__ hi,
                             __nv_bfloat16* __restrict__ lo, int n)
{
    int i = (blockIdx.x * blockDim.x + threadIdx.x) * 4;
    if (i >= n) return;
    float4 v = *(const float4*)(src + i);
    __nv_bfloat16 h0 = __float2bfloat16(v.x);
    __nv_bfloat16 h1 = __float2bfloat16(v.y);
    __nv_bfloat16 h2 = __float2bfloat16(v.z);
    __nv_bfloat16 h3 = __float2bfloat16(v.w);
    __nv_bfloat16 l0 = __float2bfloat16(v.x - __bfloat162float(h0));
    __nv_bfloat16 l1 = __float2bfloat16(v.y - __bfloat162float(h1));
    __nv_bfloat16 l2 = __float2bfloat16(v.z - __bfloat162float(h2));
    __nv_bfloat16 l3 = __float2bfloat16(v.w - __bfloat162float(h3));
    *(__nv_bfloat162*)(hi + i)     = __nv_bfloat162(h0, h1);
    *(__nv_bfloat162*)(hi + i + 2) = __nv_bfloat162(h2, h3);
    *(__nv_bfloat162*)(lo + i)     = __nv_bfloat162(l0, l1);
    *(__nv_bfloat162*)(lo + i + 2) = __nv_bfloat162(l2, l3);
}

__global__ void transpose_split_kernel(const float* __restrict__ src,
                                       __nv_bfloat16* __restrict__ hi,
                                       __nv_bfloat16* __restrict__ lo,
                                       int K, int N)
{
    __shared__ float tile[32][33];
    int nb = blockIdx.x * 32, kb = blockIdx.y * 32;
    int tx = threadIdx.x, ty = threadIdx.y;  // 32 x 8
#pragma unroll
    for (int r = ty; r < 32; r += 8)
        tile[r][tx] = src[(size_t)(kb + r) * N + nb + tx];
    __syncthreads();
#pragma unroll
    for (int r = ty; r < 32; r += 8) {
        float v = tile[tx][r];
        __nv_bfloat16 h = __float2bfloat16(v);
        size_t o = (size_t)(nb + r) * K + kb + tx;
        hi[o] = h;
        lo[o] = __float2bfloat16(v - __bfloat162float(h));
    }
}

// ---------------------------------------------------------------------------
// bf16x3 GEMM, 3-stage cp.async pipeline, SW64-swizzled smem (64B rows),
// ldmatrix fragment loads. CTA 128x128, BK=32, 8 warps (4M x 2N).
// One __syncthreads per chunk. __launch_bounds__(256,2): 2 CTAs/SM.
// smem: 3 stages x 32KB = 96KB/CTA -> 192KB/SM.
// ---------------------------------------------------------------------------
#define GTILE 8192            // 128 rows * 64B (swizzled, no padding)
#define GSTAGE (4*GTILE)      // 32768

__global__ __launch_bounds__(256, 2) void gemm_bf16x3_kernel(
    const float* __restrict__ bias, float* __restrict__ out, int N, int mode)
{
    extern __shared__ char gs[];
    uint32_t gsb = smem_u32(gs);

    int tid = threadIdx.x;
    int wid = tid >> 5;
    int lane = tid & 31;
    int qr = lane >> 2;
    int qc = lane & 3;
    int wm = wid & 3;
    int wn = wid >> 2;
    int bm = blockIdx.y * 128;
    int bn = blockIdx.x * 128;

    // ldmatrix lane offsets with SW64 swizzle: chunk ^= (row&6)<<3
    int row_in = lane & 7;
    int tsel = lane >> 3;
    uint32_t maskr = (uint32_t)((row_in & 6) << 3);
    uint32_t rowA = (uint32_t)((tsel & 1) * 8 + row_in);
    uint32_t colA = (uint32_t)((tsel >> 1) * 16);
    uint32_t laneA0 = rowA * 64 + ((colA + 0) ^ maskr);
    uint32_t laneA1 = rowA * 64 + ((colA + 32) ^ maskr);
    uint32_t rowB = (uint32_t)((tsel >> 1) * 8 + row_in);
    uint32_t colB = (uint32_t)((tsel & 1) * 16);
    uint32_t laneB0 = rowB * 64 + ((colB + 0) ^ maskr);
    uint32_t laneB1 = rowB * 64 + ((colB + 32) ^ maskr);

    const __nv_bfloat16* Ahi = (mode == 0) ? g_x_hi : g_ao_hi;
    const __nv_bfloat16* Alo = (mode == 0) ? g_x_lo : g_ao_lo;
    const __nv_bfloat16* Bhi = (mode == 0) ? g_wqkvT_hi : g_wprojT_hi;
    const __nv_bfloat16* Blo = (mode == 0) ? g_wqkvT_lo : g_wprojT_lo;

    const __nv_bfloat16* srcp[4] = {
        Ahi + (size_t)bm * K_, Alo + (size_t)bm * K_,
        Bhi + (size_t)bn * K_, Blo + (size_t)bn * K_ };

    float acc[2][8][4];
#pragma unroll
    for (int i = 0; i < 2; i++)
#pragma unroll
        for (int j = 0; j < 8; j++)
#pragma unroll
            for (int c = 0; c < 4; c++) acc[i][j][c] = 0.0f;

    const int NC = K_ / 32;

#define GISSUE(CH, STG) do { int _k0 = (CH) * 32;                                   \
    _Pragma("unroll")                                                               \
    for (int t8 = 0; t8 < 8; ++t8) {                                                \
        int id = tid + t8 * 256; int tle = id >> 9; int rem = id & 511;             \
        int row = rem >> 2; int c = rem & 3;                                        \
        const __nv_bfloat16* sp = srcp[tle] + (size_t)row * K_ + _k0 + c * 8;       \
        uint32_t sw = (uint32_t)(c * 16) ^ (uint32_t)((row & 6) << 3);              \
        uint32_t dp = gsb + (STG) * GSTAGE + tle * GTILE + row * 64 + sw;           \
        CP_ASYNC16(dp, sp);                                                         \
    }                                                                               \
    asm volatile("cp.async.commit_group;"); } while (0)

    GISSUE(0, 0);
    GISSUE(1, 1);

    int sget = 0;      // stage of chunk ch
    int sput = 2;      // stage for chunk ch+2
    for (int ch = 0; ch < NC; ++ch) {
        if (ch + 1 < NC) {
            asm volatile("cp.async.wait_group 1;");
        } else {
            asm volatile("cp.async.wait_group 0;");
        }
        __syncthreads();

        uint32_t sA0 = gsb + sget * GSTAGE;
        uint32_t sA1 = sA0 + GTILE;
        uint32_t sB0 = sA0 + 2 * GTILE;
        uint32_t sB1 = sA0 + 3 * GTILE;

#pragma unroll
        for (int k16 = 0; k16 < 2; ++k16) {
            uint32_t lA = k16 ? laneA1 : laneA0;
            uint32_t lB = k16 ? laneB1 : laneB0;
            uint32_t ah[2][4], al[2][4];
#pragma unroll
            for (int i = 0; i < 2; ++i) {
                uint32_t aoff = (uint32_t)((wm * 32 + i * 16) * 64);
                LDSM_X4(ah[i], sA0 + aoff + lA);
                LDSM_X4(al[i], sA1 + aoff + lA);
            }
#pragma unroll
            for (int p = 0; p < 4; ++p) {
                uint32_t boff = (uint32_t)((wn * 64 + p * 16) * 64);
                uint32_t bh4[4], bl4[4];
                LDSM_X4(bh4, sB0 + boff + lB);
                LDSM_X4(bl4, sB1 + boff + lB);
#pragma unroll
                for (int half = 0; half < 2; ++half) {
                    int j = 2 * p + half;
                    uint32_t bh0 = bh4[half * 2], bh1 = bh4[half * 2 + 1];
                    uint32_t bl0 = bl4[half * 2], bl1 = bl4[half * 2 + 1];
#pragma unroll
                    for (int i = 0; i < 2; ++i) {
                        mma_bf16(acc[i][j], ah[i][0], ah[i][1], ah[i][2], ah[i][3], bh0, bh1);
                        mma_bf16(acc[i][j], ah[i][0], ah[i][1], ah[i][2], ah[i][3], bl0, bl1);
                        mma_bf16(acc[i][j], al[i][0], al[i][1], al[i][2], al[i][3], bh0, bh1);
                    }
                }
            }
        }

        // issue chunk ch+2 into the stage freed by compute(ch-1) (fenced by bar above)
        if (ch + 2 < NC) {
            GISSUE(ch + 2, sput);
        }
        sget = (sget == 2) ? 0 : sget + 1;
        sput = (sput == 2) ? 0 : sput + 1;
    }

    // epilogue
#pragma unroll
    for (int i = 0; i < 2; ++i) {
#pragma unroll
        for (int j = 0; j < 8; ++j) {
            int n = bn + wn * 64 + j * 8 + qc * 2;
            float b0v = bias[n], b1v = bias[n + 1];
#pragma unroll
            for (int half = 0; half < 2; ++half) {
                int m = bm + wm * 32 + i * 16 + qr + half * 8;
                float v0 = acc[i][j][half * 2 + 0] + b0v;
                float v1 = acc[i][j][half * 2 + 1] + b1v;
                if (mode == 0) {
                    int bq = m >> 11;
                    int t = m & (T_ - 1);
                    int sel = n >> 10;
                    int dd = n & (D_ - 1);
                    int h = dd >> 6;
                    int hd = dd & (HD_ - 1);
                    __nv_bfloat16 h0 = __float2bfloat16(v0);
                    __nv_bfloat16 h1 = __float2bfloat16(v1);
                    __nv_bfloat16 l0 = __float2bfloat16(v0 - __bfloat162float(h0));
                    __nv_bfloat16 l1 = __float2bfloat16(v1 - __bfloat162float(h1));
                    if (sel == 2) {
                        size_t vb = ((size_t)(bq * H_ + h) * HD_);
                        g_v_hi[(vb + hd) * T_ + t] = h0;
                        g_v_hi[(vb + hd + 1) * T_ + t] = h1;
                        g_v_lo[(vb + hd) * T_ + t] = l0;
                        g_v_lo[(vb + hd + 1) * T_ + t] = l1;
                    } else {
                        size_t o = ((size_t)(bq * H_ + h) * T_ + t) * HD_ + hd;
                        __nv_bfloat16* dh = (sel == 0) ? g_q_hi : g_k_hi;
                        __nv_bfloat16* dl = (sel == 0) ? g_q_lo : g_k_lo;
                        *(__nv_bfloat162*)(dh + o) = __nv_bfloat162(h0, h1);
                        *(__nv_bfloat162*)(dl + o) = __nv_bfloat162(l0, l1);
                    }
                } else {
                    *(float2*)(out + (size_t)m * N + n) = make_float2(v0, v1);
                }
            }
        }
    }
}

// ---------------------------------------------------------------------------
// Attention: bf16x3 S and PV, all-MUFU exp, cp.async KV pipeline.
// (unchanged from R10 — 1122us config)
// ---------------------------------------------------------------------------
#define A_QHI 0
#define A_QLO 18432
#define KV_STAGE 71680        // KHI 18432 + KLO 18432 + VHI 17408 + VLO 17408
#define A_ST(s) (36864 + (s) * KV_STAGE)
#define KO_KHI 0
#define KO_KLO 18432
#define KO_VHI 36864
#define KO_VLO 54272
// post-loop reduction areas reuse the stage region
#define A_OA  36864
#define A_OB  70656
#define A_LP  104448
#define A_LI  105472
#define A_SMEM 180224         // 36864 + 2*71680

__global__ __launch_bounds__(256) void attn_mma_kernel()
{
    extern __shared__ char as_[];
    uint32_t asb = smem_u32(as_);

    int tid = threadIdx.x;
    int wid = tid >> 5;
    int lane = tid & 31;
    int qr = lane >> 2;
    int qc = lane & 3;
    int wm = wid & 3;
    int wn = wid >> 2;
    int q0 = blockIdx.x * 128;
    int h = blockIdx.y;
    int b = blockIdx.z;

    int row_in = lane & 7;
    int tsel = lane >> 3;
    uint32_t laneAq = (uint32_t)(((tsel & 1) * 8 + row_in) * 144 + (tsel >> 1) * 16);
    uint32_t laneBk = (uint32_t)(((tsel >> 1) * 8 + row_in) * 144 + (tsel & 1) * 16);
    uint32_t laneBv = (uint32_t)(((tsel >> 1) * 8 + row_in) * 272 + (tsel & 1) * 16);

    const size_t bh = (size_t)(b * H_ + h);
    const __nv_bfloat16* gqh = g_q_hi + (bh * T_ + q0) * HD_;
    const __nv_bfloat16* gql = g_q_lo + (bh * T_ + q0) * HD_;
    const __nv_bfloat16* gkh = g_k_hi + bh * T_ * HD_;
    const __nv_bfloat16* gkl = g_k_lo + bh * T_ * HD_;
    const __nv_bfloat16* gvh = g_v_hi + bh * HD_ * T_;
    const __nv_bfloat16* gvl = g_v_lo + bh * HD_ * T_;

#define KV_ISSUE(KT, STG) do {                                                        \
    const __nv_bfloat16* _khp = gkh + (size_t)(KT) * 128 * HD_;                       \
    const __nv_bfloat16* _klp = gkl + (size_t)(KT) * 128 * HD_;                       \
    const __nv_bfloat16* _vhp = gvh + (KT) * 128;                                     \
    const __nv_bfloat16* _vlp = gvl + (KT) * 128;                                     \
    uint32_t _sb = asb + A_ST(STG);                                                   \
    _Pragma("unroll")                                                                 \
    for (int r = 0; r < 4; ++r) {                                                     \
        int id = tid + r * 256;                                                       \
        int row = id >> 3; int c = id & 7;                                            \
        CP_ASYNC16(_sb + KO_KHI + row * 144 + c * 16, _khp + (size_t)row * HD_ + c * 8); \
        CP_ASYNC16(_sb + KO_KLO + row * 144 + c * 16, _klp + (size_t)row * HD_ + c * 8); \
    }                                                                                 \
    _Pragma("unroll")                                                                 \
    for (int r = 0; r < 4; ++r) {                                                     \
        int id = tid + r * 256;                                                       \
        int row = id >> 4; int c = id & 15;                                           \
        CP_ASYNC16(_sb + KO_VHI + row * 272 + c * 16, _vhp + (size_t)row * T_ + c * 8);  \
        CP_ASYNC16(_sb + KO_VLO + row * 272 + c * 16, _vlp + (size_t)row * T_ + c * 8);  \
    }                                                                                 \
    asm volatile("cp.async.commit_group;"); } while (0)

    // prefetch KV tile 0 (async, overlaps Q load below)
    KV_ISSUE(0, 0);

    // load Q tiles (hi/lo): 128 rows x 64 halves, stride 144B
#pragma unroll
    for (int r = 0; r < 4; ++r) {
        int id = tid + r * 256;
        int row = id >> 3;
        int c = id & 7;
        *(uint4*)(as_ + A_QHI + row * 144 + c * 16) = *(const uint4*)(gqh + (size_t)row * HD_ + c * 8);
        *(uint4*)(as_ + A_QLO + row * 144 + c * 16) = *(const uint4*)(gql + (size_t)row * HD_ + c * 8);
    }
    __syncthreads();

    // Q hi fragments in registers
    uint32_t qh[2][4][4];
#pragma unroll
    for (int i = 0; i < 2; ++i) {
#pragma unroll
        for (int t = 0; t < 4; ++t) {
            LDSM_X4(qh[i][t], asb + A_QHI + (uint32_t)((wm * 32 + i * 16) * 144 + t * 32) + laneAq);
        }
    }

    float oacc[2][8][4];
#pragma unroll
    for (int i = 0; i < 2; i++)
#pragma unroll
        for (int j = 0; j < 8; j++)
#pragma unroll
            for (int c = 0; c < 4; c++) oacc[i][j][c] = 0.0f;
    float lsum[2][2] = {{0.f, 0.f}, {0.f, 0.f}};

    const int NT = T_ / 128;
    for (int kt = 0; kt < NT; ++kt) {
        if (kt + 1 < NT) {
            KV_ISSUE(kt + 1, (kt + 1) & 1);
            asm volatile("cp.async.wait_group 1;");
        } else {
            asm volatile("cp.async.wait_group 0;");
        }
        __syncthreads();

        uint32_t stg = asb + A_ST(kt & 1);

        // ---- S = Q K^T (bf16x3) ----
        float sacc[2][8][4];
#pragma unroll
        for (int i = 0; i < 2; i++)
#pragma unroll
            for (int j = 0; j < 8; j++)
#pragma unroll
                for (int c = 0; c < 4; c++) sacc[i][j][c] = 0.0f;

#pragma unroll
        for (int t = 0; t < 4; ++t) {
            uint32_t koff = (uint32_t)(t * 32);
            uint32_t ql[2][4];
#pragma unroll
            for (int i = 0; i < 2; ++i) {
                LDSM_X4(ql[i], asb + A_QLO + (uint32_t)((wm * 32 + i * 16) * 144) + koff + laneAq);
            }
#pragma unroll
            for (int p = 0; p < 4; ++p) {
                uint32_t boff = (uint32_t)((wn * 64 + p * 16) * 144) + koff;
                uint32_t kh4[4], kl4[4];
                LDSM_X4(kh4, stg + KO_KHI + boff + laneBk);
                LDSM_X4(kl4, stg + KO_KLO + boff + laneBk);
#pragma unroll
                for (int half = 0; half < 2; ++half) {
                    int j = 2 * p + half;
                    uint32_t bh0 = kh4[half * 2], bh1 = kh4[half * 2 + 1];
                    uint32_t bl0 = kl4[half * 2], bl1 = kl4[half * 2 + 1];
#pragma unroll
                    for (int i = 0; i < 2; ++i) {
                        mma_bf16(sacc[i][j], qh[i][t][0], qh[i][t][1], qh[i][t][2], qh[i][t][3], bh0, bh1);
                        mma_bf16(sacc[i][j], qh[i][t][0], qh[i][t][1], qh[i][t][2], qh[i][t][3], bl0, bl1);
                        mma_bf16(sacc[i][j], ql[i][0], ql[i][1], ql[i][2], ql[i][3], bh0, bh1);
                    }
                }
            }
        }

        // ---- exp (no max subtraction, all-MUFU) + pack P hi/lo ----
        uint32_t ph[2][8][2], pl[2][8][2];
#pragma unroll
        for (int i = 0; i < 2; ++i) {
#pragma unroll
            for (int j = 0; j < 8; ++j) {
                float p0 = exp_scaled_mufu(sacc[i][j][0]);
                float p1 = exp_scaled_mufu(sacc[i][j][1]);
                float p2 = exp_scaled_mufu(sacc[i][j][2]);
                float p3 = exp_scaled_mufu(sacc[i][j][3]);
                lsum[i][0] += p0 + p1;
                lsum[i][1] += p2 + p3;
                uint32_t h01 = pack_bf16(p0, p1);
                uint32_t h23 = pack_bf16(p2, p3);
                float r0 = p0 - __int_as_float(h01 << 16);
                float r1 = p1 - __int_as_float(h01 & 0xFFFF0000u);
                float r2 = p2 - __int_as_float(h23 << 16);
                float r3 = p3 - __int_as_float(h23 & 0xFFFF0000u);
                ph[i][j][0] = h01;
                ph[i][j][1] = h23;
                pl[i][j][0] = pack_bf16(r0, r1);
                pl[i][j][1] = pack_bf16(r2, r3);
            }
        }

        // ---- O += P V (bf16x3); warp covers kv slice wn*64..+64 ----
#pragma unroll
        for (int t = 0; t < 4; ++t) {
            uint32_t koff = (uint32_t)(wn * 128 + t * 32);
#pragma unroll
            for (int p = 0; p < 4; ++p) {
                uint32_t boff = (uint32_t)(p * 16 * 272) + koff;
                uint32_t vh4[4], vl4[4];
                LDSM_X4(vh4, stg + KO_VHI + boff + laneBv);
                LDSM_X4(vl4, stg + KO_VLO + boff + laneBv);
#pragma unroll
                for (int half = 0; half < 2; ++half) {
                    int j = 2 * p + half;
                    uint32_t vh0 = vh4[half * 2], vh1 = vh4[half * 2 + 1];
                    uint32_t vl0 = vl4[half * 2], vl1 = vl4[half * 2 + 1];
#pragma unroll
                    for (int i = 0; i < 2; ++i) {
                        uint32_t a0 = ph[i][2 * t][0], a1 = ph[i][2 * t][1];
                        uint32_t a2 = ph[i][2 * t + 1][0], a3 = ph[i][2 * t + 1][1];
                        mma_bf16(oacc[i][j], a0, a1, a2, a3, vh0, vh1);
                        mma_bf16(oacc[i][j], a0, a1, a2, a3, vl0, vl1);
                        mma_bf16(oacc[i][j], pl[i][2 * t][0], pl[i][2 * t][1],
                                 pl[i][2 * t + 1][0], pl[i][2 * t + 1][1], vh0, vh1);
                    }
                }
            }
        }
        __syncthreads();   // all warps done with stage (kt&1) before it's re-filled
    }

    // store partial O (per wn) to smem (stage region reused; loop's trailing bar protects)
    {
        float* obuf = (float*)(as_ + (wn == 0 ? A_OA : A_OB));
#pragma unroll
        for (int i = 0; i < 2; ++i) {
#pragma unroll
            for (int j = 0; j < 8; ++j) {
                int row = wm * 32 + i * 16 + qr;
                int col = j * 8 + qc * 2;
                *(float2*)&obuf[row * 66 + col] = make_float2(oacc[i][j][0], oacc[i][j][1]);
                *(float2*)&obuf[(row + 8) * 66 + col] = make_float2(oacc[i][j][2], oacc[i][j][3]);
            }
        }
    }
    // reduce l over qc lanes, write partials
    {
        float* lp = (float*)(as_ + A_LP);
#pragma unroll
        for (int i = 0; i < 2; ++i) {
#pragma unroll
            for (int hf = 0; hf < 2; ++hf) {
                float v = lsum[i][hf];
                v += __shfl_xor_sync(0xffffffffu, v, 1);
                v += __shfl_xor_sync(0xffffffffu, v, 2);
                lsum[i][hf] = v;
            }
            if (qc == 0) {
                lp[wn * 128 + wm * 32 + i * 16 + qr] = lsum[i][0];
                lp[wn * 128 + wm * 32 + i * 16 + qr + 8] = lsum[i][1];
            }
        }
    }
    __syncthreads();
    {
        float* lp = (float*)(as_ + A_LP);
        float* li = (float*)(as_ + A_LI);
        if (tid < 128) li[tid] = 1.0f / (lp[tid] + lp[128 + tid]);
    }
    __syncthreads();

    // final: sum partials, normalize, split, write g_ao
    {
        const float* oA = (const float*)(as_ + A_OA);
        const float* oB = (const float*)(as_ + A_OB);
        const float* li = (const float*)(as_ + A_LI);
        int colp = (tid & 31) * 2;
        int rbase = tid >> 5;
#pragma unroll
        for (int pass = 0; pass < 16; ++pass) {
            int row = pass * 8 + rbase;
            float iv = li[row];
            float o0 = (oA[row * 66 + colp] + oB[row * 66 + colp]) * iv;
            float o1 = (oA[row * 66 + colp + 1] + oB[row * 66 + colp + 1]) * iv;
            uint32_t hp = pack_bf16(o0, o1);
            float r0 = o0 - __int_as_float(hp << 16);
            float r1 = o1 - __int_as_float(hp & 0xFFFF0000u);
            uint32_t lpk = pack_bf16(r0, r1);
            size_t go = ((size_t)(b * T_ + q0 + row)) * D_ + h * HD_ + colp;
            *(uint32_t*)(g_ao_hi + go) = hp;
            *(uint32_t*)(g_ao_lo + go) = lpk;
        }
    }
}

// ---------------------------------------------------------------------------
extern "C" void kernel_launch(void* const* d_in, const int* in_sizes, int n_in,
                              void* d_out, int out_size)
{
    const float* x = (const float*)d_in[0];
    const float* w_qkv = (const float*)d_in[1];
    const float* b_qkv = (const float*)d_in[2];
    const float* w_proj = (const float*)d_in[3];
    const float* b_proj = (const float*)d_in[4];
    float* out = (float*)d_out;

    __nv_bfloat16 *xhi, *xlo, *wqh, *wql, *wph, *wpl;
    cudaGetSymbolAddress((void**)&xhi, g_x_hi);
    cudaGetSymbolAddress((void**)&xlo, g_x_lo);
    cudaGetSymbolAddress((void**)&wqh, g_wqkvT_hi);
    cudaGetSymbolAddress((void**)&wql, g_wqkvT_lo);
    cudaGetSymbolAddress((void**)&wph, g_wprojT_hi);
    cudaGetSymbolAddress((void**)&wpl, g_wprojT_lo);

    cudaFuncSetAttribute(gemm_bf16x3_kernel, cudaFuncAttributeMaxDynamicSharedMemorySize, 3 * GSTAGE);
    cudaFuncSetAttribute(attn_mma_kernel, cudaFuncAttributeMaxDynamicSharedMemorySize, A_SMEM);

    // split x -> bf16 hi/lo
    {
        int n = M_ * K_;
        split_kernel<<<(n / 4 + 255) / 256, 256>>>(x, xhi, xlo, n);
    }
    transpose_split_kernel<<<dim3(NQKV / 32, K_ / 32), dim3(32, 8)>>>(w_qkv, wqh, wql, K_, NQKV);
    transpose_split_kernel<<<dim3(D_ / 32, K_ / 32), dim3(32, 8)>>>(w_proj, wph, wpl, K_, D_);

    // QKV GEMM -> split q/k/v
    gemm_bf16x3_kernel<<<dim3(NQKV / 128, M_ / 128), 256, 3 * GSTAGE>>>(b_qkv, nullptr, NQKV, 0);

    // Attention (tensor cores + MUFU exp, cp.async KV pipeline) -> g_ao hi/lo
    attn_mma_kernel<<<dim3(T_ / 128, H_, B_), 256, A_SMEM>>>();

    // Output projection -> out
    gemm_bf16x3_kernel<<<dim3(D_ / 128, M_ / 128), 256, 3 * GSTAGE>>>(b_proj, out, D_, 1);
}

// round 12
// speedup vs baseline: 1.3622x; 1.0440x over previous
#include <cuda_runtime.h>
#include <cuda_bf16.h>
#include <cstdint>

#define B_ 4
#define T_ 2048
#define D_ 1024
#define H_ 16
#define HD_ 64
#define K_ 1024
#define M_ (B_*T_)        // 8192
#define NQKV (3*D_)       // 3072

// ---------------------------------------------------------------------------
// Scratch (device globals — allocation-free rule)
// ---------------------------------------------------------------------------
__device__ __nv_bfloat16 g_q_hi[(size_t)B_ * H_ * T_ * HD_];
__device__ __nv_bfloat16 g_q_lo[(size_t)B_ * H_ * T_ * HD_];
__device__ __nv_bfloat16 g_k_hi[(size_t)B_ * H_ * T_ * HD_];
__device__ __nv_bfloat16 g_k_lo[(size_t)B_ * H_ * T_ * HD_];
__device__ __nv_bfloat16 g_v_hi[(size_t)B_ * H_ * HD_ * T_];   // transposed [b,h,hd,t]
__device__ __nv_bfloat16 g_v_lo[(size_t)B_ * H_ * HD_ * T_];
__device__ __nv_bfloat16 g_x_hi[(size_t)M_ * K_];
__device__ __nv_bfloat16 g_x_lo[(size_t)M_ * K_];
__device__ __nv_bfloat16 g_wqkvT_hi[(size_t)NQKV * K_];
__device__ __nv_bfloat16 g_wqkvT_lo[(size_t)NQKV * K_];
__device__ __nv_bfloat16 g_wprojT_hi[(size_t)D_ * K_];
__device__ __nv_bfloat16 g_wprojT_lo[(size_t)D_ * K_];
__device__ __nv_bfloat16 g_ao_hi[(size_t)M_ * D_];
__device__ __nv_bfloat16 g_ao_lo[(size_t)M_ * D_];

// ---------------------------------------------------------------------------
// Helpers
// ---------------------------------------------------------------------------
__device__ __forceinline__ uint32_t smem_u32(const void* p) {
    uint32_t a;
    asm("{ .reg .u64 t; cvta.to.shared.u64 t, %1; cvt.u32.u64 %0, t; }" : "=r"(a) : "l"(p));
    return a;
}
__device__ __forceinline__ void mma_bf16(float c[4], uint32_t a0, uint32_t a1,
                                         uint32_t a2, uint32_t a3,
                                         uint32_t b0, uint32_t b1) {
    asm volatile(
        "mma.sync.aligned.m16n8k16.row.col.f32.bf16.bf16.f32 "
        "{%0,%1,%2,%3},{%4,%5,%6,%7},{%8,%9},{%0,%1,%2,%3};"
        : "+f"(c[0]), "+f"(c[1]), "+f"(c[2]), "+f"(c[3])
        : "r"(a0), "r"(a1), "r"(a2), "r"(a3), "r"(b0), "r"(b1));
}
#define LDSM_X4(R, ADDR) \
    asm volatile("ldmatrix.sync.aligned.m8n8.x4.shared.b16 {%0,%1,%2,%3}, [%4];" \
        : "=r"((R)[0]), "=r"((R)[1]), "=r"((R)[2]), "=r"((R)[3]) : "r"(ADDR))

#define CP_ASYNC16(DST, SRC) \
    asm volatile("cp.async.cg.shared.global [%0], [%1], 16;" :: "r"(DST), "l"(SRC))

// d = {hi_elem:f_hi | lo_elem:f_lo}
__device__ __forceinline__ uint32_t pack_bf16(float f_lo, float f_hi) {
    uint32_t d;
    asm("cvt.rn.bf16x2.f32 %0, %1, %2;" : "=r"(d) : "f"(f_hi), "f"(f_lo));
    return d;
}
// exp(s/8) = 2^(s*C) via MUFU
__device__ __forceinline__ float exp_scaled_mufu(float s) {
    float z = s * 0.18033688011112042f;
    float r;
    asm("ex2.approx.f32 %0, %1;" : "=f"(r) : "f"(z));
    return r;
}

// ---------------------------------------------------------------------------
// Splitters
// ---------------------------------------------------------------------------
__global__ void split_kernel(const float* __restrict__ src,
                             __nv_bfloat16* __restrict__ hi,
                             __nv_bfloat16* __restrict__ lo, int n)
{
    int i = (blockIdx.x * blockDim.x + threadIdx.x) * 4;
    if (i >= n) return;
    float4 v = *(const float4*)(src + i);
    __nv_bfloat16 h0 = __float2bfloat16(v.x);
    __nv_bfloat16 h1 = __float2bfloat16(v.y);
    __nv_bfloat16 h2 = __float2bfloat16(v.z);
    __nv_bfloat16 h3 = __float2bfloat16(v.w);
    __nv_bfloat16 l0 = __float2bfloat16(v.x - __bfloat162float(h0));
    __nv_bfloat16 l1 = __float2bfloat16(v.y - __bfloat162float(h1));
    __nv_bfloat16 l2 = __float2bfloat16(v.z - __bfloat162float(h2));
    __nv_bfloat16 l3 = __float2bfloat16(v.w - __bfloat162float(h3));
    *(__nv_bfloat162*)(hi + i)     = __nv_bfloat162(h0, h1);
    *(__nv_bfloat162*)(hi + i + 2) = __nv_bfloat162(h2, h3);
    *(__nv_bfloat162*)(lo + i)     = __nv_bfloat162(l0, l1);
    *(__nv_bfloat162*)(lo + i + 2) = __nv_bfloat162(l2, l3);
}

__global__ void transpose_split_kernel(const float* __restrict__ src,
                                       __nv_bfloat16* __restrict__ hi,
                                       __nv_bfloat16* __restrict__ lo,
                                       int K, int N)
{
    __shared__ float tile[32][33];
    int nb = blockIdx.x * 32, kb = blockIdx.y * 32;
    int tx = threadIdx.x, ty = threadIdx.y;  // 32 x 8
#pragma unroll
    for (int r = ty; r < 32; r += 8)
        tile[r][tx] = src[(size_t)(kb + r) * N + nb + tx];
    __syncthreads();
#pragma unroll
    for (int r = ty; r < 32; r += 8) {
        float v = tile[tx][r];
        __nv_bfloat16 h = __float2bfloat16(v);
        size_t o = (size_t)(nb + r) * K + kb + tx;
        hi[o] = h;
        lo[o] = __float2bfloat16(v - __bfloat162float(h));
    }
}

// ---------------------------------------------------------------------------
// bf16x3 GEMM, 3-stage cp.async pipeline, SW64-swizzled smem (64B rows),
// ldmatrix fragment loads. (unchanged from R11 — 355us/121us config)
// ---------------------------------------------------------------------------
#define GTILE 8192            // 128 rows * 64B (swizzled, no padding)
#define GSTAGE (4*GTILE)      // 32768

__global__ __launch_bounds__(256, 2) void gemm_bf16x3_kernel(
    const float* __restrict__ bias, float* __restrict__ out, int N, int mode)
{
    extern __shared__ char gs[];
    uint32_t gsb = smem_u32(gs);

    int tid = threadIdx.x;
    int wid = tid >> 5;
    int lane = tid & 31;
    int qr = lane >> 2;
    int qc = lane & 3;
    int wm = wid & 3;
    int wn = wid >> 2;
    int bm = blockIdx.y * 128;
    int bn = blockIdx.x * 128;

    // ldmatrix lane offsets with SW64 swizzle: chunk ^= (row&6)<<3
    int row_in = lane & 7;
    int tsel = lane >> 3;
    uint32_t maskr = (uint32_t)((row_in & 6) << 3);
    uint32_t rowA = (uint32_t)((tsel & 1) * 8 + row_in);
    uint32_t colA = (uint32_t)((tsel >> 1) * 16);
    uint32_t laneA0 = rowA * 64 + ((colA + 0) ^ maskr);
    uint32_t laneA1 = rowA * 64 + ((colA + 32) ^ maskr);
    uint32_t rowB = (uint32_t)((tsel >> 1) * 8 + row_in);
    uint32_t colB = (uint32_t)((tsel & 1) * 16);
    uint32_t laneB0 = rowB * 64 + ((colB + 0) ^ maskr);
    uint32_t laneB1 = rowB * 64 + ((colB + 32) ^ maskr);

    const __nv_bfloat16* Ahi = (mode == 0) ? g_x_hi : g_ao_hi;
    const __nv_bfloat16* Alo = (mode == 0) ? g_x_lo : g_ao_lo;
    const __nv_bfloat16* Bhi = (mode == 0) ? g_wqkvT_hi : g_wprojT_hi;
    const __nv_bfloat16* Blo = (mode == 0) ? g_wqkvT_lo : g_wprojT_lo;

    const __nv_bfloat16* srcp[4] = {
        Ahi + (size_t)bm * K_, Alo + (size_t)bm * K_,
        Bhi + (size_t)bn * K_, Blo + (size_t)bn * K_ };

    float acc[2][8][4];
#pragma unroll
    for (int i = 0; i < 2; i++)
#pragma unroll
        for (int j = 0; j < 8; j++)
#pragma unroll
            for (int c = 0; c < 4; c++) acc[i][j][c] = 0.0f;

    const int NC = K_ / 32;

#define GISSUE(CH, STG) do { int _k0 = (CH) * 32;                                   \
    _Pragma("unroll")                                                               \
    for (int t8 = 0; t8 < 8; ++t8) {                                                \
        int id = tid + t8 * 256; int tle = id >> 9; int rem = id & 511;             \
        int row = rem >> 2; int c = rem & 3;                                        \
        const __nv_bfloat16* sp = srcp[tle] + (size_t)row * K_ + _k0 + c * 8;       \
        uint32_t sw = (uint32_t)(c * 16) ^ (uint32_t)((row & 6) << 3);              \
        uint32_t dp = gsb + (STG) * GSTAGE + tle * GTILE + row * 64 + sw;           \
        CP_ASYNC16(dp, sp);                                                         \
    }                                                                               \
    asm volatile("cp.async.commit_group;"); } while (0)

    GISSUE(0, 0);
    GISSUE(1, 1);

    int sget = 0;
    int sput = 2;
    for (int ch = 0; ch < NC; ++ch) {
        if (ch + 1 < NC) {
            asm volatile("cp.async.wait_group 1;");
        } else {
            asm volatile("cp.async.wait_group 0;");
        }
        __syncthreads();

        uint32_t sA0 = gsb + sget * GSTAGE;
        uint32_t sA1 = sA0 + GTILE;
        uint32_t sB0 = sA0 + 2 * GTILE;
        uint32_t sB1 = sA0 + 3 * GTILE;

#pragma unroll
        for (int k16 = 0; k16 < 2; ++k16) {
            uint32_t lA = k16 ? laneA1 : laneA0;
            uint32_t lB = k16 ? laneB1 : laneB0;
            uint32_t ah[2][4], al[2][4];
#pragma unroll
            for (int i = 0; i < 2; ++i) {
                uint32_t aoff = (uint32_t)((wm * 32 + i * 16) * 64);
                LDSM_X4(ah[i], sA0 + aoff + lA);
                LDSM_X4(al[i], sA1 + aoff + lA);
            }
#pragma unroll
            for (int p = 0; p < 4; ++p) {
                uint32_t boff = (uint32_t)((wn * 64 + p * 16) * 64);
                uint32_t bh4[4], bl4[4];
                LDSM_X4(bh4, sB0 + boff + lB);
                LDSM_X4(bl4, sB1 + boff + lB);
#pragma unroll
                for (int half = 0; half < 2; ++half) {
                    int j = 2 * p + half;
                    uint32_t bh0 = bh4[half * 2], bh1 = bh4[half * 2 + 1];
                    uint32_t bl0 = bl4[half * 2], bl1 = bl4[half * 2 + 1];
#pragma unroll
                    for (int i = 0; i < 2; ++i) {
                        mma_bf16(acc[i][j], ah[i][0], ah[i][1], ah[i][2], ah[i][3], bh0, bh1);
                        mma_bf16(acc[i][j], ah[i][0], ah[i][1], ah[i][2], ah[i][3], bl0, bl1);
                        mma_bf16(acc[i][j], al[i][0], al[i][1], al[i][2], al[i][3], bh0, bh1);
                    }
                }
            }
        }

        if (ch + 2 < NC) {
            GISSUE(ch + 2, sput);
        }
        sget = (sget == 2) ? 0 : sget + 1;
        sput = (sput == 2) ? 0 : sput + 1;
    }

    // epilogue
#pragma unroll
    for (int i = 0; i < 2; ++i) {
#pragma unroll
        for (int j = 0; j < 8; ++j) {
            int n = bn + wn * 64 + j * 8 + qc * 2;
            float b0v = bias[n], b1v = bias[n + 1];
#pragma unroll
            for (int half = 0; half < 2; ++half) {
                int m = bm + wm * 32 + i * 16 + qr + half * 8;
                float v0 = acc[i][j][half * 2 + 0] + b0v;
                float v1 = acc[i][j][half * 2 + 1] + b1v;
                if (mode == 0) {
                    int bq = m >> 11;
                    int t = m & (T_ - 1);
                    int sel = n >> 10;
                    int dd = n & (D_ - 1);
                    int h = dd >> 6;
                    int hd = dd & (HD_ - 1);
                    __nv_bfloat16 h0 = __float2bfloat16(v0);
                    __nv_bfloat16 h1 = __float2bfloat16(v1);
                    __nv_bfloat16 l0 = __float2bfloat16(v0 - __bfloat162float(h0));
                    __nv_bfloat16 l1 = __float2bfloat16(v1 - __bfloat162float(h1));
                    if (sel == 2) {
                        size_t vb = ((size_t)(bq * H_ + h) * HD_);
                        g_v_hi[(vb + hd) * T_ + t] = h0;
                        g_v_hi[(vb + hd + 1) * T_ + t] = h1;
                        g_v_lo[(vb + hd) * T_ + t] = l0;
                        g_v_lo[(vb + hd + 1) * T_ + t] = l1;
                    } else {
                        size_t o = ((size_t)(bq * H_ + h) * T_ + t) * HD_ + hd;
                        __nv_bfloat16* dh = (sel == 0) ? g_q_hi : g_k_hi;
                        __nv_bfloat16* dl = (sel == 0) ? g_q_lo : g_k_lo;
                        *(__nv_bfloat162*)(dh + o) = __nv_bfloat162(h0, h1);
                        *(__nv_bfloat162*)(dl + o) = __nv_bfloat162(l0, l1);
                    }
                } else {
                    *(float2*)(out + (size_t)m * N + n) = make_float2(v0, v1);
                }
            }
        }
    }
}

// ---------------------------------------------------------------------------
// Attention: bf16x3 S and PV, all-MUFU exp.
// NEW: 3-stage cp.async KV pipeline, SW128-swizzled tiles (no padding),
// ONE __syncthreads per KV iteration (GEMM-proven structure).
// smem: Q 32KB + 3 x 64KB stages = 224KB.
// ---------------------------------------------------------------------------
#define A_QHI 0
#define A_QLO 16384
#define KV_ST(s) (32768 + (s) * 65536)
#define KO_KHI 0
#define KO_KLO 16384
#define KO_VHI 32768
#define KO_VLO 49152
// post-loop reduction areas reuse the stage region
#define A_OA  32768
#define A_OB  66560
#define A_LP  100352
#define A_LI  101376
#define A_SMEM 229376         // 32768 + 3*65536

__global__ __launch_bounds__(256) void attn_mma_kernel()
{
    extern __shared__ char as_[];
    uint32_t asb = smem_u32(as_);

    int tid = threadIdx.x;
    int wid = tid >> 5;
    int lane = tid & 31;
    int qr = lane >> 2;
    int qc = lane & 3;
    int wm = wid & 3;
    int wn = wid >> 2;
    int q0 = blockIdx.x * 128;
    int h = blockIdx.y;
    int b = blockIdx.z;

    int row_in = lane & 7;
    int tsel = lane >> 3;
    uint32_t swx = (uint32_t)(row_in << 4);   // thread-constant swizzle XOR
    // logical (unswizzled) lane offsets
    uint32_t laneQ = (uint32_t)(((tsel & 1) * 8 + row_in) * 128 + (tsel >> 1) * 16);
    uint32_t laneK = (uint32_t)(((tsel >> 1) * 8 + row_in) * 128 + (tsel & 1) * 16);
    uint32_t laneV = (uint32_t)(((tsel >> 1) * 8 + row_in) * 256 + wn * 128 + (tsel & 1) * 16);

    const size_t bh = (size_t)(b * H_ + h);
    const __nv_bfloat16* gqh = g_q_hi + (bh * T_ + q0) * HD_;
    const __nv_bfloat16* gql = g_q_lo + (bh * T_ + q0) * HD_;
    const __nv_bfloat16* gkh = g_k_hi + bh * T_ * HD_;
    const __nv_bfloat16* gkl = g_k_lo + bh * T_ * HD_;
    const __nv_bfloat16* gvh = g_v_hi + bh * HD_ * T_;
    const __nv_bfloat16* gvl = g_v_lo + bh * HD_ * T_;

#define KV_ISSUE(KT, STG) do {                                                        \
    const __nv_bfloat16* _khp = gkh + (size_t)(KT) * 128 * HD_;                       \
    const __nv_bfloat16* _klp = gkl + (size_t)(KT) * 128 * HD_;                       \
    const __nv_bfloat16* _vhp = gvh + (KT) * 128;                                     \
    const __nv_bfloat16* _vlp = gvl + (KT) * 128;                                     \
    uint32_t _sb = asb + KV_ST(STG);                                                  \
    _Pragma("unroll")                                                                 \
    for (int r = 0; r < 4; ++r) {                                                     \
        int id = tid + r * 256;                                                       \
        int row = id >> 3; int c = id & 7;                                            \
        uint32_t _sw = (uint32_t)(row * 128) + ((uint32_t)(c * 16) ^ (uint32_t)((row & 7) << 4)); \
        CP_ASYNC16(_sb + KO_KHI + _sw, _khp + (size_t)row * HD_ + c * 8);             \
        CP_ASYNC16(_sb + KO_KLO + _sw, _klp + (size_t)row * HD_ + c * 8);             \
    }                                                                                 \
    _Pragma("unroll")                                                                 \
    for (int r = 0; r < 4; ++r) {                                                     \
        int id = tid + r * 256;                                                       \
        int row = id >> 4; int c = id & 15;                                           \
        uint32_t _sw = (uint32_t)(row * 256) + ((uint32_t)(c * 16) ^ (uint32_t)((row & 7) << 4)); \
        CP_ASYNC16(_sb + KO_VHI + _sw, _vhp + (size_t)row * T_ + c * 8);              \
        CP_ASYNC16(_sb + KO_VLO + _sw, _vlp + (size_t)row * T_ + c * 8);              \
    }                                                                                 \
    asm volatile("cp.async.commit_group;"); } while (0)

    // prefetch KV tiles 0,1 (async, overlap Q load below)
    KV_ISSUE(0, 0);
    KV_ISSUE(1, 1);

    // load Q tiles (hi/lo): 128 rows x 128B, SW128 swizzled
#pragma unroll
    for (int r = 0; r < 4; ++r) {
        int id = tid + r * 256;
        int row = id >> 3;
        int c = id & 7;
        uint32_t sw = (uint32_t)(row * 128) + ((uint32_t)(c * 16) ^ (uint32_t)((row & 7) << 4));
        *(uint4*)(as_ + A_QHI + sw) = *(const uint4*)(gqh + (size_t)row * HD_ + c * 8);
        *(uint4*)(as_ + A_QLO + sw) = *(const uint4*)(gql + (size_t)row * HD_ + c * 8);
    }
    __syncthreads();

    // Q hi fragments in registers
    uint32_t qh[2][4][4];
#pragma unroll
    for (int i = 0; i < 2; ++i) {
#pragma unroll
        for (int t = 0; t < 4; ++t) {
            uint32_t qlog = (uint32_t)((wm * 32 + i * 16) * 128 + t * 32) + laneQ;
            LDSM_X4(qh[i][t], asb + A_QHI + (qlog ^ swx));
        }
    }

    float oacc[2][8][4];
#pragma unroll
    for (int i = 0; i < 2; i++)
#pragma unroll
        for (int j = 0; j < 8; j++)
#pragma unroll
            for (int c = 0; c < 4; c++) oacc[i][j][c] = 0.0f;
    float lsum[2][2] = {{0.f, 0.f}, {0.f, 0.f}};

    const int NT = T_ / 128;
    int sget = 0;
    int sput = 2;
    for (int kt = 0; kt < NT; ++kt) {
        if (kt + 1 < NT) {
            asm volatile("cp.async.wait_group 1;");
        } else {
            asm volatile("cp.async.wait_group 0;");
        }
        __syncthreads();

        uint32_t stg = asb + KV_ST(sget);

        // ---- S = Q K^T (bf16x3) ----
        float sacc[2][8][4];
#pragma unroll
        for (int i = 0; i < 2; i++)
#pragma unroll
            for (int j = 0; j < 8; j++)
#pragma unroll
                for (int c = 0; c < 4; c++) sacc[i][j][c] = 0.0f;

#pragma unroll
        for (int t = 0; t < 4; ++t) {
            uint32_t ql[2][4];
#pragma unroll
            for (int i = 0; i < 2; ++i) {
                uint32_t qlog = (uint32_t)((wm * 32 + i * 16) * 128 + t * 32) + laneQ;
                LDSM_X4(ql[i], asb + A_QLO + (qlog ^ swx));
            }
#pragma unroll
            for (int p = 0; p < 4; ++p) {
                uint32_t klog = (uint32_t)((wn * 64 + p * 16) * 128 + t * 32) + laneK;
                uint32_t kaddr = klog ^ swx;
                uint32_t kh4[4], kl4[4];
                LDSM_X4(kh4, stg + KO_KHI + kaddr);
                LDSM_X4(kl4, stg + KO_KLO + kaddr);
#pragma unroll
                for (int half = 0; half < 2; ++half) {
                    int j = 2 * p + half;
                    uint32_t bh0 = kh4[half * 2], bh1 = kh4[half * 2 + 1];
                    uint32_t bl0 = kl4[half * 2], bl1 = kl4[half * 2 + 1];
#pragma unroll
                    for (int i = 0; i < 2; ++i) {
                        mma_bf16(sacc[i][j], qh[i][t][0], qh[i][t][1], qh[i][t][2], qh[i][t][3], bh0, bh1);
                        mma_bf16(sacc[i][j], qh[i][t][0], qh[i][t][1], qh[i][t][2], qh[i][t][3], bl0, bl1);
                        mma_bf16(sacc[i][j], ql[i][0], ql[i][1], ql[i][2], ql[i][3], bh0, bh1);
                    }
                }
            }
        }

        // ---- exp (no max subtraction, all-MUFU) + pack P hi/lo ----
        uint32_t ph[2][8][2], pl[2][8][2];
#pragma unroll
        for (int i = 0; i < 2; ++i) {
#pragma unroll
            for (int j = 0; j < 8; ++j) {
                float p0 = exp_scaled_mufu(sacc[i][j][0]);
                float p1 = exp_scaled_mufu(sacc[i][j][1]);
                float p2 = exp_scaled_mufu(sacc[i][j][2]);
                float p3 = exp_scaled_mufu(sacc[i][j][3]);
                lsum[i][0] += p0 + p1;
                lsum[i][1] += p2 + p3;
                uint32_t h01 = pack_bf16(p0, p1);
                uint32_t h23 = pack_bf16(p2, p3);
                float r0 = p0 - __int_as_float(h01 << 16);
                float r1 = p1 - __int_as_float(h01 & 0xFFFF0000u);
                float r2 = p2 - __int_as_float(h23 << 16);
                float r3 = p3 - __int_as_float(h23 & 0xFFFF0000u);
                ph[i][j][0] = h01;
                ph[i][j][1] = h23;
                pl[i][j][0] = pack_bf16(r0, r1);
                pl[i][j][1] = pack_bf16(r2, r3);
            }
        }

        // ---- O += P V (bf16x3); warp covers kv slice wn*64..+64 ----
#pragma unroll
        for (int t = 0; t < 4; ++t) {
#pragma unroll
            for (int p = 0; p < 4; ++p) {
                uint32_t vlog = (uint32_t)(p * 16 * 256 + t * 32) + laneV;
                uint32_t vaddr = vlog ^ swx;
                uint32_t vh4[4], vl4[4];
                LDSM_X4(vh4, stg + KO_VHI + vaddr);
                LDSM_X4(vl4, stg + KO_VLO + vaddr);
#pragma unroll
                for (int half = 0; half < 2; ++half) {
                    int j = 2 * p + half;
                    uint32_t vh0 = vh4[half * 2], vh1 = vh4[half * 2 + 1];
                    uint32_t vl0 = vl4[half * 2], vl1 = vl4[half * 2 + 1];
#pragma unroll
                    for (int i = 0; i < 2; ++i) {
                        uint32_t a0 = ph[i][2 * t][0], a1 = ph[i][2 * t][1];
                        uint32_t a2 = ph[i][2 * t + 1][0], a3 = ph[i][2 * t + 1][1];
                        mma_bf16(oacc[i][j], a0, a1, a2, a3, vh0, vh1);
                        mma_bf16(oacc[i][j], a0, a1, a2, a3, vl0, vl1);
                        mma_bf16(oacc[i][j], pl[i][2 * t][0], pl[i][2 * t][1],
                                 pl[i][2 * t + 1][0], pl[i][2 * t + 1][1], vh0, vh1);
                    }
                }
            }
        }

        // issue tile kt+2 into the stage freed by compute(kt-1) (fenced by bar above)
        if (kt + 2 < NT) {
            KV_ISSUE(kt + 2, sput);
        }
        sget = (sget == 2) ? 0 : sget + 1;
        sput = (sput == 2) ? 0 : sput + 1;
    }

    __syncthreads();   // all warps done with stages; reuse region for O reduction

    // store partial O (per wn) to smem
    {
        float* obuf = (float*)(as_ + (wn == 0 ? A_OA : A_OB));
#pragma unroll
        for (int i = 0; i < 2; ++i) {
#pragma unroll
            for (int j = 0; j < 8; ++j) {
                int row = wm * 32 + i * 16 + qr;
                int col = j * 8 + qc * 2;
                *(float2*)&obuf[row * 66 + col] = make_float2(oacc[i][j][0], oacc[i][j][1]);
                *(float2*)&obuf[(row + 8) * 66 + col] = make_float2(oacc[i][j][2], oacc[i][j][3]);
            }
        }
    }
    // reduce l over qc lanes, write partials
    {
        float* lp = (float*)(as_ + A_LP);
#pragma unroll
        for (int i = 0; i < 2; ++i) {
#pragma unroll
            for (int hf = 0; hf < 2; ++hf) {
                float v = lsum[i][hf];
                v += __shfl_xor_sync(0xffffffffu, v, 1);
                v += __shfl_xor_sync(0xffffffffu, v, 2);
                lsum[i][hf] = v;
            }
            if (qc == 0) {
                lp[wn * 128 + wm * 32 + i * 16 + qr] = lsum[i][0];
                lp[wn * 128 + wm * 32 + i * 16 + qr + 8] = lsum[i][1];
            }
        }
    }
    __syncthreads();
    {
        float* lp = (float*)(as_ + A_LP);
        float* li = (float*)(as_ + A_LI);
        if (tid < 128) li[tid] = 1.0f / (lp[tid] + lp[128 + tid]);
    }
    __syncthreads();

    // final: sum partials, normalize, split, write g_ao
    {
        const float* oA = (const float*)(as_ + A_OA);
        const float* oB = (const float*)(as_ + A_OB);
        const float* li = (const float*)(as_ + A_LI);
        int colp = (tid & 31) * 2;
        int rbase = tid >> 5;
#pragma unroll
        for (int pass = 0; pass < 16; ++pass) {
            int row = pass * 8 + rbase;
            float iv = li[row];
            float o0 = (oA[row * 66 + colp] + oB[row * 66 + colp]) * iv;
            float o1 = (oA[row * 66 + colp + 1] + oB[row * 66 + colp + 1]) * iv;
            uint32_t hp = pack_bf16(o0, o1);
            float r0 = o0 - __int_as_float(hp << 16);
            float r1 = o1 - __int_as_float(hp & 0xFFFF0000u);
            uint32_t lpk = pack_bf16(r0, r1);
            size_t go = ((size_t)(b * T_ + q0 + row)) * D_ + h * HD_ + colp;
            *(uint32_t*)(g_ao_hi + go) = hp;
            *(uint32_t*)(g_ao_lo + go) = lpk;
        }
    }
}

// ---------------------------------------------------------------------------
extern "C" void kernel_launch(void* const* d_in, const int* in_sizes, int n_in,
                              void* d_out, int out_size)
{
    const float* x = (const float*)d_in[0];
    const float* w_qkv = (const float*)d_in[1];
    const float* b_qkv = (const float*)d_in[2];
    const float* w_proj = (const float*)d_in[3];
    const float* b_proj = (const float*)d_in[4];
    float* out = (float*)d_out;

    __nv_bfloat16 *xhi, *xlo, *wqh, *wql, *wph, *wpl;
    cudaGetSymbolAddress((void**)&xhi, g_x_hi);
    cudaGetSymbolAddress((void**)&xlo, g_x_lo);
    cudaGetSymbolAddress((void**)&wqh, g_wqkvT_hi);
    cudaGetSymbolAddress((void**)&wql, g_wqkvT_lo);
    cudaGetSymbolAddress((void**)&wph, g_wprojT_hi);
    cudaGetSymbolAddress((void**)&wpl, g_wprojT_lo);

    cudaFuncSetAttribute(gemm_bf16x3_kernel, cudaFuncAttributeMaxDynamicSharedMemorySize, 3 * GSTAGE);
    cudaFuncSetAttribute(attn_mma_kernel, cudaFuncAttributeMaxDynamicSharedMemorySize, A_SMEM);

    // split x -> bf16 hi/lo
    {
        int n = M_ * K_;
        split_kernel<<<(n / 4 + 255) / 256, 256>>>(x, xhi, xlo, n);
    }
    transpose_split_kernel<<<dim3(NQKV / 32, K_ / 32), dim3(32, 8)>>>(w_qkv, wqh, wql, K_, NQKV);
    transpose_split_kernel<<<dim3(D_ / 32, K_ / 32), dim3(32, 8)>>>(w_proj, wph, wpl, K_, D_);

    // QKV GEMM -> split q/k/v
    gemm_bf16x3_kernel<<<dim3(NQKV / 128, M_ / 128), 256, 3 * GSTAGE>>>(b_qkv, nullptr, NQKV, 0);

    // Attention (tensor cores + MUFU exp, 3-stage cp.async KV) -> g_ao hi/lo
    attn_mma_kernel<<<dim3(T_ / 128, H_, B_), 256, A_SMEM>>>();

    // Output projection -> out
    gemm_bf16x3_kernel<<<dim3(D_ / 128, M_ / 128), 256, 3 * GSTAGE>>>(b_proj, out, D_, 1);
}

// round 13
// speedup vs baseline: 1.6286x; 1.1956x over previous
#include <cuda_runtime.h>
#include <cuda_bf16.h>
#include <cuda_fp16.h>
#include <cstdint>

#define B_ 4
#define T_ 2048
#define D_ 1024
#define H_ 16
#define HD_ 64
#define K_ 1024
#define M_ (B_*T_)        // 8192
#define NQKV (3*D_)       // 3072

// ---------------------------------------------------------------------------
// Scratch (device globals — allocation-free rule)
// ---------------------------------------------------------------------------
__device__ __nv_bfloat16 g_q_hi[(size_t)B_ * H_ * T_ * HD_];
__device__ __nv_bfloat16 g_q_lo[(size_t)B_ * H_ * T_ * HD_];
__device__ __nv_bfloat16 g_k_hi[(size_t)B_ * H_ * T_ * HD_];
__device__ __nv_bfloat16 g_k_lo[(size_t)B_ * H_ * T_ * HD_];
__device__ __half        g_v16[(size_t)B_ * H_ * HD_ * T_];    // transposed [b,h,hd,t], single fp16
__device__ __nv_bfloat16 g_x_hi[(size_t)M_ * K_];
__device__ __nv_bfloat16 g_x_lo[(size_t)M_ * K_];
__device__ __nv_bfloat16 g_wqkvT_hi[(size_t)NQKV * K_];
__device__ __nv_bfloat16 g_wqkvT_lo[(size_t)NQKV * K_];
__device__ __nv_bfloat16 g_wprojT_hi[(size_t)D_ * K_];
__device__ __nv_bfloat16 g_wprojT_lo[(size_t)D_ * K_];
__device__ __nv_bfloat16 g_ao_hi[(size_t)M_ * D_];
__device__ __nv_bfloat16 g_ao_lo[(size_t)M_ * D_];

// ---------------------------------------------------------------------------
// Helpers
// ---------------------------------------------------------------------------
__device__ __forceinline__ uint32_t smem_u32(const void* p) {
    uint32_t a;
    asm("{ .reg .u64 t; cvta.to.shared.u64 t, %1; cvt.u32.u64 %0, t; }" : "=r"(a) : "l"(p));
    return a;
}
__device__ __forceinline__ void mma_bf16(float c[4], uint32_t a0, uint32_t a1,
                                         uint32_t a2, uint32_t a3,
                                         uint32_t b0, uint32_t b1) {
    asm volatile(
        "mma.sync.aligned.m16n8k16.row.col.f32.bf16.bf16.f32 "
        "{%0,%1,%2,%3},{%4,%5,%6,%7},{%8,%9},{%0,%1,%2,%3};"
        : "+f"(c[0]), "+f"(c[1]), "+f"(c[2]), "+f"(c[3])
        : "r"(a0), "r"(a1), "r"(a2), "r"(a3), "r"(b0), "r"(b1));
}
__device__ __forceinline__ void mma_fp16(float c[4], uint32_t a0, uint32_t a1,
                                         uint32_t a2, uint32_t a3,
                                         uint32_t b0, uint32_t b1) {
    asm volatile(
        "mma.sync.aligned.m16n8k16.row.col.f32.f16.f16.f32 "
        "{%0,%1,%2,%3},{%4,%5,%6,%7},{%8,%9},{%0,%1,%2,%3};"
        : "+f"(c[0]), "+f"(c[1]), "+f"(c[2]), "+f"(c[3])
        : "r"(a0), "r"(a1), "r"(a2), "r"(a3), "r"(b0), "r"(b1));
}
#define LDSM_X4(R, ADDR) \
    asm volatile("ldmatrix.sync.aligned.m8n8.x4.shared.b16 {%0,%1,%2,%3}, [%4];" \
        : "=r"((R)[0]), "=r"((R)[1]), "=r"((R)[2]), "=r"((R)[3]) : "r"(ADDR))

#define CP_ASYNC16(DST, SRC) \
    asm volatile("cp.async.cg.shared.global [%0], [%1], 16;" :: "r"(DST), "l"(SRC))

// d = {hi_elem:f_hi | lo_elem:f_lo}
__device__ __forceinline__ uint32_t pack_bf16(float f_lo, float f_hi) {
    uint32_t d;
    asm("cvt.rn.bf16x2.f32 %0, %1, %2;" : "=r"(d) : "f"(f_hi), "f"(f_lo));
    return d;
}
__device__ __forceinline__ uint32_t pack_f16(float f_lo, float f_hi) {
    uint32_t d;
    asm("cvt.rn.f16x2.f32 %0, %1, %2;" : "=r"(d) : "f"(f_hi), "f"(f_lo));
    return d;
}
// exp(s/8) = 2^(s*C) via MUFU
__device__ __forceinline__ float exp_scaled_mufu(float s) {
    float z = s * 0.18033688011112042f;
    float r;
    asm("ex2.approx.f32 %0, %1;" : "=f"(r) : "f"(z));
    return r;
}

// ---------------------------------------------------------------------------
// Splitters
// ---------------------------------------------------------------------------
__global__ void split_kernel(const float* __restrict__ src,
                             __nv_bfloat16* __restrict__ hi,
                             __nv_bfloat16* __restrict__ lo, int n)
{
    int i = (blockIdx.x * blockDim.x + threadIdx.x) * 4;
    if (i >= n) return;
    float4 v = *(const float4*)(src + i);
    __nv_bfloat16 h0 = __float2bfloat16(v.x);
    __nv_bfloat16 h1 = __float2bfloat16(v.y);
    __nv_bfloat16 h2 = __float2bfloat16(v.z);
    __nv_bfloat16 h3 = __float2bfloat16(v.w);
    __nv_bfloat16 l0 = __float2bfloat16(v.x - __bfloat162float(h0));
    __nv_bfloat16 l1 = __float2bfloat16(v.y - __bfloat162float(h1));
    __nv_bfloat16 l2 = __float2bfloat16(v.z - __bfloat162float(h2));
    __nv_bfloat16 l3 = __float2bfloat16(v.w - __bfloat162float(h3));
    *(__nv_bfloat162*)(hi + i)     = __nv_bfloat162(h0, h1);
    *(__nv_bfloat162*)(hi + i + 2) = __nv_bfloat162(h2, h3);
    *(__nv_bfloat162*)(lo + i)     = __nv_bfloat162(l0, l1);
    *(__nv_bfloat162*)(lo + i + 2) = __nv_bfloat162(l2, l3);
}

__global__ void transpose_split_kernel(const float* __restrict__ src,
                                       __nv_bfloat16* __restrict__ hi,
                                       __nv_bfloat16* __restrict__ lo,
                                       int K, int N)
{
    __shared__ float tile[32][33];
    int nb = blockIdx.x * 32, kb = blockIdx.y * 32;
    int tx = threadIdx.x, ty = threadIdx.y;  // 32 x 8
#pragma unroll
    for (int r = ty; r < 32; r += 8)
        tile[r][tx] = src[(size_t)(kb + r) * N + nb + tx];
    __syncthreads();
#pragma unroll
    for (int r = ty; r < 32; r += 8) {
        float v = tile[tx][r];
        __nv_bfloat16 h = __float2bfloat16(v);
        size_t o = (size_t)(nb + r) * K + kb + tx;
        hi[o] = h;
        lo[o] = __float2bfloat16(v - __bfloat162float(h));
    }
}

// ---------------------------------------------------------------------------
// bf16x3 GEMM, 3-stage cp.async pipeline, SW64-swizzled smem.
// (R11/R12 config; only V epilogue changed: single fp16 store)
// ---------------------------------------------------------------------------
#define GTILE 8192
#define GSTAGE (4*GTILE)

__global__ __launch_bounds__(256, 2) void gemm_bf16x3_kernel(
    const float* __restrict__ bias, float* __restrict__ out, int N, int mode)
{
    extern __shared__ char gs[];
    uint32_t gsb = smem_u32(gs);

    int tid = threadIdx.x;
    int wid = tid >> 5;
    int lane = tid & 31;
    int qr = lane >> 2;
    int qc = lane & 3;
    int wm = wid & 3;
    int wn = wid >> 2;
    int bm = blockIdx.y * 128;
    int bn = blockIdx.x * 128;

    int row_in = lane & 7;
    int tsel = lane >> 3;
    uint32_t maskr = (uint32_t)((row_in & 6) << 3);
    uint32_t rowA = (uint32_t)((tsel & 1) * 8 + row_in);
    uint32_t colA = (uint32_t)((tsel >> 1) * 16);
    uint32_t laneA0 = rowA * 64 + ((colA + 0) ^ maskr);
    uint32_t laneA1 = rowA * 64 + ((colA + 32) ^ maskr);
    uint32_t rowB = (uint32_t)((tsel >> 1) * 8 + row_in);
    uint32_t colB = (uint32_t)((tsel & 1) * 16);
    uint32_t laneB0 = rowB * 64 + ((colB + 0) ^ maskr);
    uint32_t laneB1 = rowB * 64 + ((colB + 32) ^ maskr);

    const __nv_bfloat16* Ahi = (mode == 0) ? g_x_hi : g_ao_hi;
    const __nv_bfloat16* Alo = (mode == 0) ? g_x_lo : g_ao_lo;
    const __nv_bfloat16* Bhi = (mode == 0) ? g_wqkvT_hi : g_wprojT_hi;
    const __nv_bfloat16* Blo = (mode == 0) ? g_wqkvT_lo : g_wprojT_lo;

    const __nv_bfloat16* srcp[4] = {
        Ahi + (size_t)bm * K_, Alo + (size_t)bm * K_,
        Bhi + (size_t)bn * K_, Blo + (size_t)bn * K_ };

    float acc[2][8][4];
#pragma unroll
    for (int i = 0; i < 2; i++)
#pragma unroll
        for (int j = 0; j < 8; j++)
#pragma unroll
            for (int c = 0; c < 4; c++) acc[i][j][c] = 0.0f;

    const int NC = K_ / 32;

#define GISSUE(CH, STG) do { int _k0 = (CH) * 32;                                   \
    _Pragma("unroll")                                                               \
    for (int t8 = 0; t8 < 8; ++t8) {                                                \
        int id = tid + t8 * 256; int tle = id >> 9; int rem = id & 511;             \
        int row = rem >> 2; int c = rem & 3;                                        \
        const __nv_bfloat16* sp = srcp[tle] + (size_t)row * K_ + _k0 + c * 8;       \
        uint32_t sw = (uint32_t)(c * 16) ^ (uint32_t)((row & 6) << 3);              \
        uint32_t dp = gsb + (STG) * GSTAGE + tle * GTILE + row * 64 + sw;           \
        CP_ASYNC16(dp, sp);                                                         \
    }                                                                               \
    asm volatile("cp.async.commit_group;"); } while (0)

    GISSUE(0, 0);
    GISSUE(1, 1);

    int sget = 0;
    int sput = 2;
    for (int ch = 0; ch < NC; ++ch) {
        if (ch + 1 < NC) {
            asm volatile("cp.async.wait_group 1;");
        } else {
            asm volatile("cp.async.wait_group 0;");
        }
        __syncthreads();

        uint32_t sA0 = gsb + sget * GSTAGE;
        uint32_t sA1 = sA0 + GTILE;
        uint32_t sB0 = sA0 + 2 * GTILE;
        uint32_t sB1 = sA0 + 3 * GTILE;

#pragma unroll
        for (int k16 = 0; k16 < 2; ++k16) {
            uint32_t lA = k16 ? laneA1 : laneA0;
            uint32_t lB = k16 ? laneB1 : laneB0;
            uint32_t ah[2][4], al[2][4];
#pragma unroll
            for (int i = 0; i < 2; ++i) {
                uint32_t aoff = (uint32_t)((wm * 32 + i * 16) * 64);
                LDSM_X4(ah[i], sA0 + aoff + lA);
                LDSM_X4(al[i], sA1 + aoff + lA);
            }
#pragma unroll
            for (int p = 0; p < 4; ++p) {
                uint32_t boff = (uint32_t)((wn * 64 + p * 16) * 64);
                uint32_t bh4[4], bl4[4];
                LDSM_X4(bh4, sB0 + boff + lB);
                LDSM_X4(bl4, sB1 + boff + lB);
#pragma unroll
                for (int half = 0; half < 2; ++half) {
                    int j = 2 * p + half;
                    uint32_t bh0 = bh4[half * 2], bh1 = bh4[half * 2 + 1];
                    uint32_t bl0 = bl4[half * 2], bl1 = bl4[half * 2 + 1];
#pragma unroll
                    for (int i = 0; i < 2; ++i) {
                        mma_bf16(acc[i][j], ah[i][0], ah[i][1], ah[i][2], ah[i][3], bh0, bh1);
                        mma_bf16(acc[i][j], ah[i][0], ah[i][1], ah[i][2], ah[i][3], bl0, bl1);
                        mma_bf16(acc[i][j], al[i][0], al[i][1], al[i][2], al[i][3], bh0, bh1);
                    }
                }
            }
        }

        if (ch + 2 < NC) {
            GISSUE(ch + 2, sput);
        }
        sget = (sget == 2) ? 0 : sget + 1;
        sput = (sput == 2) ? 0 : sput + 1;
    }

    // epilogue
#pragma unroll
    for (int i = 0; i < 2; ++i) {
#pragma unroll
        for (int j = 0; j < 8; ++j) {
            int n = bn + wn * 64 + j * 8 + qc * 2;
            float b0v = bias[n], b1v = bias[n + 1];
#pragma unroll
            for (int half = 0; half < 2; ++half) {
                int m = bm + wm * 32 + i * 16 + qr + half * 8;
                float v0 = acc[i][j][half * 2 + 0] + b0v;
                float v1 = acc[i][j][half * 2 + 1] + b1v;
                if (mode == 0) {
                    int bq = m >> 11;
                    int t = m & (T_ - 1);
                    int sel = n >> 10;
                    int dd = n & (D_ - 1);
                    int h = dd >> 6;
                    int hd = dd & (HD_ - 1);
                    if (sel == 2) {
                        size_t vb = ((size_t)(bq * H_ + h) * HD_);
                        g_v16[(vb + hd) * T_ + t] = __float2half(v0);
                        g_v16[(vb + hd + 1) * T_ + t] = __float2half(v1);
                    } else {
                        __nv_bfloat16 h0 = __float2bfloat16(v0);
                        __nv_bfloat16 h1 = __float2bfloat16(v1);
                        __nv_bfloat16 l0 = __float2bfloat16(v0 - __bfloat162float(h0));
                        __nv_bfloat16 l1 = __float2bfloat16(v1 - __bfloat162float(h1));
                        size_t o = ((size_t)(bq * H_ + h) * T_ + t) * HD_ + hd;
                        __nv_bfloat16* dh = (sel == 0) ? g_q_hi : g_k_hi;
                        __nv_bfloat16* dl = (sel == 0) ? g_q_lo : g_k_lo;
                        *(__nv_bfloat162*)(dh + o) = __nv_bfloat162(h0, h1);
                        *(__nv_bfloat162*)(dl + o) = __nv_bfloat162(l0, l1);
                    }
                } else {
                    *(float2*)(out + (size_t)m * N + n) = make_float2(v0, v1);
                }
            }
        }
    }
}

// ---------------------------------------------------------------------------
// Attention: bf16x3 S; fp16 single-term PV (P fp16, V fp16); all-MUFU exp;
// 3-stage cp.async KV pipeline, SW128-swizzled, one bar per iteration.
// smem: Q 32KB + 3 x 48KB stages = 176KB.
// ---------------------------------------------------------------------------
#define A_QHI 0
#define A_QLO 16384
#define KV_ST(s) (32768 + (s) * 49152)
#define KO_KHI 0
#define KO_KLO 16384
#define KO_V   32768
// post-loop reduction areas reuse the stage region
#define A_OA  32768
#define A_OB  66560
#define A_LP  100352
#define A_LI  101376
#define A_SMEM 180224         // 32768 + 3*49152

__global__ __launch_bounds__(256) void attn_mma_kernel()
{
    extern __shared__ char as_[];
    uint32_t asb = smem_u32(as_);

    int tid = threadIdx.x;
    int wid = tid >> 5;
    int lane = tid & 31;
    int qr = lane >> 2;
    int qc = lane & 3;
    int wm = wid & 3;
    int wn = wid >> 2;
    int q0 = blockIdx.x * 128;
    int h = blockIdx.y;
    int b = blockIdx.z;

    int row_in = lane & 7;
    int tsel = lane >> 3;
    uint32_t swx = (uint32_t)(row_in << 4);
    uint32_t laneQ = (uint32_t)(((tsel & 1) * 8 + row_in) * 128 + (tsel >> 1) * 16);
    uint32_t laneK = (uint32_t)(((tsel >> 1) * 8 + row_in) * 128 + (tsel & 1) * 16);
    uint32_t laneV = (uint32_t)(((tsel >> 1) * 8 + row_in) * 256 + wn * 128 + (tsel & 1) * 16);

    const size_t bh = (size_t)(b * H_ + h);
    const __nv_bfloat16* gqh = g_q_hi + (bh * T_ + q0) * HD_;
    const __nv_bfloat16* gql = g_q_lo + (bh * T_ + q0) * HD_;
    const __nv_bfloat16* gkh = g_k_hi + bh * T_ * HD_;
    const __nv_bfloat16* gkl = g_k_lo + bh * T_ * HD_;
    const __half* gv = g_v16 + bh * HD_ * T_;

#define KV_ISSUE(KT, STG) do {                                                        \
    const __nv_bfloat16* _khp = gkh + (size_t)(KT) * 128 * HD_;                       \
    const __nv_bfloat16* _klp = gkl + (size_t)(KT) * 128 * HD_;                       \
    const __half* _vp = gv + (KT) * 128;                                              \
    uint32_t _sb = asb + KV_ST(STG);                                                  \
    _Pragma("unroll")                                                                 \
    for (int r = 0; r < 4; ++r) {                                                     \
        int id = tid + r * 256;                                                       \
        int row = id >> 3; int c = id & 7;                                            \
        uint32_t _sw = (uint32_t)(row * 128) + ((uint32_t)(c * 16) ^ (uint32_t)((row & 7) << 4)); \
        CP_ASYNC16(_sb + KO_KHI + _sw, _khp + (size_t)row * HD_ + c * 8);             \
        CP_ASYNC16(_sb + KO_KLO + _sw, _klp + (size_t)row * HD_ + c * 8);             \
    }                                                                                 \
    _Pragma("unroll")                                                                 \
    for (int r = 0; r < 4; ++r) {                                                     \
        int id = tid + r * 256;                                                       \
        int row = id >> 4; int c = id & 15;                                           \
        uint32_t _sw = (uint32_t)(row * 256) + ((uint32_t)(c * 16) ^ (uint32_t)((row & 7) << 4)); \
        CP_ASYNC16(_sb + KO_V + _sw, _vp + (size_t)row * T_ + c * 8);                 \
    }                                                                                 \
    asm volatile("cp.async.commit_group;"); } while (0)

    KV_ISSUE(0, 0);
    KV_ISSUE(1, 1);

    // load Q tiles (hi/lo): SW128 swizzled
#pragma unroll
    for (int r = 0; r < 4; ++r) {
        int id = tid + r * 256;
        int row = id >> 3;
        int c = id & 7;
        uint32_t sw = (uint32_t)(row * 128) + ((uint32_t)(c * 16) ^ (uint32_t)((row & 7) << 4));
        *(uint4*)(as_ + A_QHI + sw) = *(const uint4*)(gqh + (size_t)row * HD_ + c * 8);
        *(uint4*)(as_ + A_QLO + sw) = *(const uint4*)(gql + (size_t)row * HD_ + c * 8);
    }
    __syncthreads();

    // Q hi fragments in registers
    uint32_t qh[2][4][4];
#pragma unroll
    for (int i = 0; i < 2; ++i) {
#pragma unroll
        for (int t = 0; t < 4; ++t) {
            uint32_t qlog = (uint32_t)((wm * 32 + i * 16) * 128 + t * 32) + laneQ;
            LDSM_X4(qh[i][t], asb + A_QHI + (qlog ^ swx));
        }
    }

    float oacc[2][8][4];
#pragma unroll
    for (int i = 0; i < 2; i++)
#pragma unroll
        for (int j = 0; j < 8; j++)
#pragma unroll
            for (int c = 0; c < 4; c++) oacc[i][j][c] = 0.0f;
    float lsum[2][2] = {{0.f, 0.f}, {0.f, 0.f}};

    const int NT = T_ / 128;
    int sget = 0;
    int sput = 2;
    for (int kt = 0; kt < NT; ++kt) {
        if (kt + 1 < NT) {
            asm volatile("cp.async.wait_group 1;");
        } else {
            asm volatile("cp.async.wait_group 0;");
        }
        __syncthreads();

        uint32_t stg = asb + KV_ST(sget);

        // ---- S = Q K^T (bf16x3) ----
        float sacc[2][8][4];
#pragma unroll
        for (int i = 0; i < 2; i++)
#pragma unroll
            for (int j = 0; j < 8; j++)
#pragma unroll
                for (int c = 0; c < 4; c++) sacc[i][j][c] = 0.0f;

#pragma unroll
        for (int t = 0; t < 4; ++t) {
            uint32_t ql[2][4];
#pragma unroll
            for (int i = 0; i < 2; ++i) {
                uint32_t qlog = (uint32_t)((wm * 32 + i * 16) * 128 + t * 32) + laneQ;
                LDSM_X4(ql[i], asb + A_QLO + (qlog ^ swx));
            }
#pragma unroll
            for (int p = 0; p < 4; ++p) {
                uint32_t klog = (uint32_t)((wn * 64 + p * 16) * 128 + t * 32) + laneK;
                uint32_t kaddr = klog ^ swx;
                uint32_t kh4[4], kl4[4];
                LDSM_X4(kh4, stg + KO_KHI + kaddr);
                LDSM_X4(kl4, stg + KO_KLO + kaddr);
#pragma unroll
                for (int half = 0; half < 2; ++half) {
                    int j = 2 * p + half;
                    uint32_t bh0 = kh4[half * 2], bh1 = kh4[half * 2 + 1];
                    uint32_t bl0 = kl4[half * 2], bl1 = kl4[half * 2 + 1];
#pragma unroll
                    for (int i = 0; i < 2; ++i) {
                        mma_bf16(sacc[i][j], qh[i][t][0], qh[i][t][1], qh[i][t][2], qh[i][t][3], bh0, bh1);
                        mma_bf16(sacc[i][j], qh[i][t][0], qh[i][t][1], qh[i][t][2], qh[i][t][3], bl0, bl1);
                        mma_bf16(sacc[i][j], ql[i][0], ql[i][1], ql[i][2], ql[i][3], bh0, bh1);
                    }
                }
            }
        }

        // ---- exp (no max subtraction, all-MUFU) + pack P to fp16 ----
        uint32_t ph[2][8][2];
#pragma unroll
        for (int i = 0; i < 2; ++i) {
#pragma unroll
            for (int j = 0; j < 8; ++j) {
                float p0 = exp_scaled_mufu(sacc[i][j][0]);
                float p1 = exp_scaled_mufu(sacc[i][j][1]);
                float p2 = exp_scaled_mufu(sacc[i][j][2]);
                float p3 = exp_scaled_mufu(sacc[i][j][3]);
                lsum[i][0] += p0 + p1;
                lsum[i][1] += p2 + p3;
                ph[i][j][0] = pack_f16(p0, p1);
                ph[i][j][1] = pack_f16(p2, p3);
            }
        }

        // ---- O += P V (single fp16 mma); warp covers kv slice wn*64..+64 ----
#pragma unroll
        for (int t = 0; t < 4; ++t) {
#pragma unroll
            for (int p = 0; p < 4; ++p) {
                uint32_t vlog = (uint32_t)(p * 16 * 256 + t * 32) + laneV;
                uint32_t vaddr = vlog ^ swx;
                uint32_t v4[4];
                LDSM_X4(v4, stg + KO_V + vaddr);
#pragma unroll
                for (int half = 0; half < 2; ++half) {
                    int j = 2 * p + half;
                    uint32_t v0 = v4[half * 2], v1 = v4[half * 2 + 1];
#pragma unroll
                    for (int i = 0; i < 2; ++i) {
                        mma_fp16(oacc[i][j], ph[i][2 * t][0], ph[i][2 * t][1],
                                 ph[i][2 * t + 1][0], ph[i][2 * t + 1][1], v0, v1);
                    }
                }
            }
        }

        if (kt + 2 < NT) {
            KV_ISSUE(kt + 2, sput);
        }
        sget = (sget == 2) ? 0 : sget + 1;
        sput = (sput == 2) ? 0 : sput + 1;
    }

    __syncthreads();   // stages done; reuse region for O reduction

    // store partial O (per wn) to smem
    {
        float* obuf = (float*)(as_ + (wn == 0 ? A_OA : A_OB));
#pragma unroll
        for (int i = 0; i < 2; ++i) {
#pragma unroll
            for (int j = 0; j < 8; ++j) {
                int row = wm * 32 + i * 16 + qr;
                int col = j * 8 + qc * 2;
                *(float2*)&obuf[row * 66 + col] = make_float2(oacc[i][j][0], oacc[i][j][1]);
                *(float2*)&obuf[(row + 8) * 66 + col] = make_float2(oacc[i][j][2], oacc[i][j][3]);
            }
        }
    }
    // reduce l over qc lanes, write partials
    {
        float* lp = (float*)(as_ + A_LP);
#pragma unroll
        for (int i = 0; i < 2; ++i) {
#pragma unroll
            for (int hf = 0; hf < 2; ++hf) {
                float v = lsum[i][hf];
                v += __shfl_xor_sync(0xffffffffu, v, 1);
                v += __shfl_xor_sync(0xffffffffu, v, 2);
                lsum[i][hf] = v;
            }
            if (qc == 0) {
                lp[wn * 128 + wm * 32 + i * 16 + qr] = lsum[i][0];
                lp[wn * 128 + wm * 32 + i * 16 + qr + 8] = lsum[i][1];
            }
        }
    }
    __syncthreads();
    {
        float* lp = (float*)(as_ + A_LP);
        float* li = (float*)(as_ + A_LI);
        if (tid < 128) li[tid] = 1.0f / (lp[tid] + lp[128 + tid]);
    }
    __syncthreads();

    // final: sum partials, normalize, split, write g_ao
    {
        const float* oA = (const float*)(as_ + A_OA);
        const float* oB = (const float*)(as_ + A_OB);
        const float* li = (const float*)(as_ + A_LI);
        int colp = (tid & 31) * 2;
        int rbase = tid >> 5;
#pragma unroll
        for (int pass = 0; pass < 16; ++pass) {
            int row = pass * 8 + rbase;
            float iv = li[row];
            float o0 = (oA[row * 66 + colp] + oB[row * 66 + colp]) * iv;
            float o1 = (oA[row * 66 + colp + 1] + oB[row * 66 + colp + 1]) * iv;
            uint32_t hp = pack_bf16(o0, o1);
            float r0 = o0 - __int_as_float(hp << 16);
            float r1 = o1 - __int_as_float(hp & 0xFFFF0000u);
            uint32_t lpk = pack_bf16(r0, r1);
            size_t go = ((size_t)(b * T_ + q0 + row)) * D_ + h * HD_ + colp;
            *(uint32_t*)(g_ao_hi + go) = hp;
            *(uint32_t*)(g_ao_lo + go) = lpk;
        }
    }
}

// ---------------------------------------------------------------------------
extern "C" void kernel_launch(void* const* d_in, const int* in_sizes, int n_in,
                              void* d_out, int out_size)
{
    const float* x = (const float*)d_in[0];
    const float* w_qkv = (const float*)d_in[1];
    const float* b_qkv = (const float*)d_in[2];
    const float* w_proj = (const float*)d_in[3];
    const float* b_proj = (const float*)d_in[4];
    float* out = (float*)d_out;

    __nv_bfloat16 *xhi, *xlo, *wqh, *wql, *wph, *wpl;
    cudaGetSymbolAddress((void**)&xhi, g_x_hi);
    cudaGetSymbolAddress((void**)&xlo, g_x_lo);
    cudaGetSymbolAddress((void**)&wqh, g_wqkvT_hi);
    cudaGetSymbolAddress((void**)&wql, g_wqkvT_lo);
    cudaGetSymbolAddress((void**)&wph, g_wprojT_hi);
    cudaGetSymbolAddress((void**)&wpl, g_wprojT_lo);

    cudaFuncSetAttribute(gemm_bf16x3_kernel, cudaFuncAttributeMaxDynamicSharedMemorySize, 3 * GSTAGE);
    cudaFuncSetAttribute(attn_mma_kernel, cudaFuncAttributeMaxDynamicSharedMemorySize, A_SMEM);

    // split x -> bf16 hi/lo
    {
        int n = M_ * K_;
        split_kernel<<<(n / 4 + 255) / 256, 256>>>(x, xhi, xlo, n);
    }
    transpose_split_kernel<<<dim3(NQKV / 32, K_ / 32), dim3(32, 8)>>>(w_qkv, wqh, wql, K_, NQKV);
    transpose_split_kernel<<<dim3(D_ / 32, K_ / 32), dim3(32, 8)>>>(w_proj, wph, wpl, K_, D_);

    // QKV GEMM -> split q/k (bf16 hi/lo), v (fp16)
    gemm_bf16x3_kernel<<<dim3(NQKV / 128, M_ / 128), 256, 3 * GSTAGE>>>(b_qkv, nullptr, NQKV, 0);

    // Attention (bf16x3 S + fp16 PV, MUFU exp, 3-stage cp.async KV) -> g_ao hi/lo
    attn_mma_kernel<<<dim3(T_ / 128, H_, B_), 256, A_SMEM>>>();

    // Output projection -> out
    gemm_bf16x3_kernel<<<dim3(D_ / 128, M_ / 128), 256, 3 * GSTAGE>>>(b_proj, out, D_, 1);
}